// round 10
// baseline (speedup 1.0000x reference)
#include <cuda_runtime.h>
#include <cuda_bf16.h>
#include <math.h>
#include <stdint.h>

#define BQ   1024
#define NT   50000
#define NTP  50048
#define NL   8
#define KNN  75
#define HD   128
#define NC   10000
#define NTILES 391          // NTP/128

typedef unsigned long long u64;

// ---------------- device scratch ----------------
__device__ float g_h1[BQ * HD];
__device__ float g_h2[BQ * HD];
__device__ float g_h3[BQ * HD];
__device__ float g_q4[BQ * NL];
__device__ float g_t3[(size_t)NT * HD];
__device__ float g_t4[(size_t)NT * NL];
__device__ float g_d2[(size_t)BQ * NT];
__device__ float g_min[(size_t)BQ * NTILES];
__device__ float g_qn[BQ];
__device__ float g_tn[NT];
__device__ float g_tot[BQ * NL];
__device__ __nv_bfloat16 g_qhi[(size_t)BQ * 128];
__device__ __nv_bfloat16 g_qlo[(size_t)BQ * 128];
__device__ __nv_bfloat16 g_thi[(size_t)NTP * 128];    // bank A
__device__ __nv_bfloat16 g_tlo[(size_t)NTP * 128];
__device__ __nv_bfloat16 g_thi2[(size_t)NTP * 128];   // bank B
__device__ __nv_bfloat16 g_tlo2[(size_t)NTP * 128];
__device__ __nv_bfloat16 g_w1th[128 * 128], g_w1tl[128 * 128];
__device__ __nv_bfloat16 g_w2th[128 * 128], g_w2tl[128 * 128];
__device__ __nv_bfloat16 g_w3th[128 * 128], g_w3tl[128 * 128];

// ---------------------------------------------------------------------------
__device__ __forceinline__ void mma_bf16(float* d, const uint32_t* a, const uint32_t* b)
{
    asm volatile(
        "mma.sync.aligned.m16n8k16.row.col.f32.bf16.bf16.f32 "
        "{%0,%1,%2,%3}, {%4,%5,%6,%7}, {%8,%9}, {%0,%1,%2,%3};"
        : "+f"(d[0]), "+f"(d[1]), "+f"(d[2]), "+f"(d[3])
        : "r"(a[0]), "r"(a[1]), "r"(a[2]), "r"(a[3]), "r"(b[0]), "r"(b[1]));
}

#define SLICE_ELEMS (128 * 24)

__device__ __forceinline__ void slice_load_async(
    const __nv_bfloat16* __restrict__ Gp, __nv_bfloat16* Ss,
    int row0, int k0, int lr, int lh)
{
    uint32_t sa = (uint32_t)__cvta_generic_to_shared(Ss + lr * 24 + lh * 8);
    const void* ga = Gp + (size_t)(row0 + lr) * 128 + k0 + lh * 8;
    asm volatile("cp.async.cg.shared.global [%0], [%1], 16;\n" :: "r"(sa), "l"(ga));
}

// ---------------------------------------------------------------------------
__global__ void __launch_bounds__(256)
conv_norm_kernel(const float* __restrict__ A, __nv_bfloat16* __restrict__ hi,
                 __nv_bfloat16* __restrict__ lo, float* __restrict__ nrm,
                 int Mreal, int D)
{
    int warp = threadIdx.x >> 5, lane = threadIdx.x & 31;
    int row = blockIdx.x * 8 + warp;
    int base = lane * 4;

    float ss = 0.f;
    __nv_bfloat16 hb[4], lb[4];
#pragma unroll
    for (int j = 0; j < 4; j++) {
        int col = base + j;
        float v = (row < Mreal && col < D) ? A[(size_t)row * D + col] : 0.f;
        ss += v * v;
        hb[j] = __float2bfloat16_rn(v);
        lb[j] = __float2bfloat16_rn(v - __bfloat162float(hb[j]));
    }
    __nv_bfloat162 h01, h23, l01, l23;
    h01.x = hb[0]; h01.y = hb[1]; h23.x = hb[2]; h23.y = hb[3];
    l01.x = lb[0]; l01.y = lb[1]; l23.x = lb[2]; l23.y = lb[3];
    *(__nv_bfloat162*)&hi[(size_t)row * 128 + base]     = h01;
    *(__nv_bfloat162*)&hi[(size_t)row * 128 + base + 2] = h23;
    *(__nv_bfloat162*)&lo[(size_t)row * 128 + base]     = l01;
    *(__nv_bfloat162*)&lo[(size_t)row * 128 + base + 2] = l23;

#pragma unroll
    for (int off = 16; off > 0; off >>= 1) ss += __shfl_down_sync(0xFFFFFFFFu, ss, off);
    if (lane == 0 && row < Mreal) nrm[row] = ss;
}

// ---------------------------------------------------------------------------
__global__ void __launch_bounds__(256)
wt_convert_kernel(const float* __restrict__ W1, const float* __restrict__ W2,
                  const float* __restrict__ W3)
{
    int idx = blockIdx.x * 256 + threadIdx.x;
    if (idx >= 3 * 128 * 128) return;
    int which = idx >> 14;
    int e = idx & 16383;
    int n = e & 127, k = e >> 7;
    const float* W = (which == 0) ? W1 : (which == 1) ? W2 : W3;
    int K = (which == 0) ? 83 : 128;
    float v = (k < K) ? W[(size_t)k * 128 + n] : 0.f;
    __nv_bfloat16 h = __float2bfloat16_rn(v);
    __nv_bfloat16 l = __float2bfloat16_rn(v - __bfloat162float(h));
    __nv_bfloat16* dh = (which == 0) ? g_w1th : (which == 1) ? g_w2th : g_w3th;
    __nv_bfloat16* dl = (which == 0) ? g_w1tl : (which == 1) ? g_w2tl : g_w3tl;
    dh[e] = h;
    dl[e] = l;
}

// ---------------------------------------------------------------------------
// bf16x3 GEMM mainloop, 3-pass MMA schedule (hh-all, lh-all, hl-all).
// Per-accumulator order unchanged (hh, lh, hl) -> bit-identical results;
// dependency distance between same-acc MMAs goes 2 -> 16.
// ---------------------------------------------------------------------------
__device__ __forceinline__ void gemm3_mainloop(
    const __nv_bfloat16* Ahi, const __nv_bfloat16* Alo,
    const __nv_bfloat16* Bhi, const __nv_bfloat16* Blo,
    __nv_bfloat16* smem, int m0, int n0, int nCh,
    int wm, int wn, int fr, int fc, int lr, int lh,
    float acc[2][8][4])
{
    __nv_bfloat16* AhiS[2] = {smem,                   smem + 4 * SLICE_ELEMS};
    __nv_bfloat16* AloS[2] = {smem + 1 * SLICE_ELEMS, smem + 5 * SLICE_ELEMS};
    __nv_bfloat16* BhiS[2] = {smem + 2 * SLICE_ELEMS, smem + 6 * SLICE_ELEMS};
    __nv_bfloat16* BloS[2] = {smem + 3 * SLICE_ELEMS, smem + 7 * SLICE_ELEMS};

    slice_load_async(Ahi, AhiS[0], m0, 0, lr, lh);
    slice_load_async(Alo, AloS[0], m0, 0, lr, lh);
    slice_load_async(Bhi, BhiS[0], n0, 0, lr, lh);
    slice_load_async(Blo, BloS[0], n0, 0, lr, lh);
    asm volatile("cp.async.commit_group;\n" ::: "memory");

    for (int c = 0; c < nCh; c++) {
        int buf = c & 1;
        if (c + 1 < nCh) {
            int k0 = (c + 1) * 16;
            slice_load_async(Ahi, AhiS[buf ^ 1], m0, k0, lr, lh);
            slice_load_async(Alo, AloS[buf ^ 1], m0, k0, lr, lh);
            slice_load_async(Bhi, BhiS[buf ^ 1], n0, k0, lr, lh);
            slice_load_async(Blo, BloS[buf ^ 1], n0, k0, lr, lh);
            asm volatile("cp.async.commit_group;\n" ::: "memory");
            asm volatile("cp.async.wait_group 1;" ::: "memory");
        } else {
            asm volatile("cp.async.wait_group 0;" ::: "memory");
        }
        __syncthreads();

        const __nv_bfloat16* Ah = AhiS[buf];
        const __nv_bfloat16* Al = AloS[buf];
        const __nv_bfloat16* Bh = BhiS[buf];
        const __nv_bfloat16* Bl = BloS[buf];

        uint32_t ah[2][4];
#pragma unroll
        for (int mt = 0; mt < 2; mt++) {
            int bm = wm + mt * 16;
            ah[mt][0] = *(const uint32_t*)&Ah[(bm + fr) * 24 + fc];
            ah[mt][1] = *(const uint32_t*)&Ah[(bm + fr + 8) * 24 + fc];
            ah[mt][2] = *(const uint32_t*)&Ah[(bm + fr) * 24 + fc + 8];
            ah[mt][3] = *(const uint32_t*)&Ah[(bm + fr + 8) * 24 + fc + 8];
        }
        uint32_t bh8[8][2];
#pragma unroll
        for (int nt = 0; nt < 8; nt++) {
            int nb = wn + nt * 8;
            bh8[nt][0] = *(const uint32_t*)&Bh[(nb + fr) * 24 + fc];
            bh8[nt][1] = *(const uint32_t*)&Bh[(nb + fr) * 24 + fc + 8];
        }
        // pass A: hi*hi (16 independent MMAs)
#pragma unroll
        for (int nt = 0; nt < 8; nt++) {
            mma_bf16(acc[0][nt], ah[0], bh8[nt]);
            mma_bf16(acc[1][nt], ah[1], bh8[nt]);
        }
        // pass B: lo*hi
        uint32_t al[2][4];
#pragma unroll
        for (int mt = 0; mt < 2; mt++) {
            int bm = wm + mt * 16;
            al[mt][0] = *(const uint32_t*)&Al[(bm + fr) * 24 + fc];
            al[mt][1] = *(const uint32_t*)&Al[(bm + fr + 8) * 24 + fc];
            al[mt][2] = *(const uint32_t*)&Al[(bm + fr) * 24 + fc + 8];
            al[mt][3] = *(const uint32_t*)&Al[(bm + fr + 8) * 24 + fc + 8];
        }
#pragma unroll
        for (int nt = 0; nt < 8; nt++) {
            mma_bf16(acc[0][nt], al[0], bh8[nt]);
            mma_bf16(acc[1][nt], al[1], bh8[nt]);
        }
        // pass C: hi*lo
#pragma unroll
        for (int nt = 0; nt < 8; nt++) {
            int nb = wn + nt * 8;
            uint32_t bl[2];
            bl[0] = *(const uint32_t*)&Bl[(nb + fr) * 24 + fc];
            bl[1] = *(const uint32_t*)&Bl[(nb + fr) * 24 + fc + 8];
            mma_bf16(acc[0][nt], ah[0], bl);
            mma_bf16(acc[1][nt], ah[1], bl);
        }
        __syncthreads();
    }
}

// ---------------------------------------------------------------------------
__global__ void __launch_bounds__(256, 2)
mma_dist_kernel(const __nv_bfloat16* __restrict__ Qhi, const __nv_bfloat16* __restrict__ Qlo,
                const __nv_bfloat16* __restrict__ Thi, const __nv_bfloat16* __restrict__ Tlo,
                const float* __restrict__ qn, const float* __restrict__ tn,
                float* __restrict__ out, float* __restrict__ gmin, int nCh)
{
    __shared__ __align__(16) __nv_bfloat16 smem[8 * SLICE_ELEMS];
    __shared__ float sMin[128][2];
    const int tid = threadIdx.x;
    const int wid = tid >> 5, lane = tid & 31;
    const int n0 = blockIdx.x * 128;
    const int m0 = blockIdx.y * 128;
    const int wm = (wid & 3) * 32;
    const int wn = (wid >> 2) * 64;
    const int lr = tid >> 1, lh = tid & 1;
    const int fr = lane >> 2, fc = (lane & 3) * 2;

    float acc[2][8][4];
#pragma unroll
    for (int mt = 0; mt < 2; mt++)
#pragma unroll
        for (int nt = 0; nt < 8; nt++)
#pragma unroll
            for (int j = 0; j < 4; j++) acc[mt][nt][j] = 0.f;

    gemm3_mainloop(Qhi, Qlo, Thi, Tlo, smem, m0, n0, nCh,
                   wm, wn, fr, fc, lr, lh, acc);

    const float FINF = __int_as_float(0x7F800000);
    float rmin[2][2] = {{FINF, FINF}, {FINF, FINF}};
#pragma unroll
    for (int mt = 0; mt < 2; mt++) {
        int mrow = m0 + wm + mt * 16 + fr;
        float q0 = qn[mrow], q1 = qn[mrow + 8];
#pragma unroll
        for (int nt = 0; nt < 8; nt++) {
            int n = n0 + wn + nt * 8 + fc;
            if (n < NT) {
                float t0 = tn[n], t1 = tn[n + 1];
                float2 o;
                o.x = fmaxf(q0 + t0 - 2.f * acc[mt][nt][0], 0.f);
                o.y = fmaxf(q0 + t1 - 2.f * acc[mt][nt][1], 0.f);
                *(float2*)&out[(size_t)mrow * NT + n] = o;
                rmin[mt][0] = fminf(rmin[mt][0], fminf(o.x, o.y));
                o.x = fmaxf(q1 + t0 - 2.f * acc[mt][nt][2], 0.f);
                o.y = fmaxf(q1 + t1 - 2.f * acc[mt][nt][3], 0.f);
                *(float2*)&out[(size_t)(mrow + 8) * NT + n] = o;
                rmin[mt][1] = fminf(rmin[mt][1], fminf(o.x, o.y));
            }
        }
    }
#pragma unroll
    for (int mt = 0; mt < 2; mt++)
#pragma unroll
        for (int rr = 0; rr < 2; rr++) {
            float m = rmin[mt][rr];
            m = fminf(m, __shfl_xor_sync(0xFFFFFFFFu, m, 1));
            m = fminf(m, __shfl_xor_sync(0xFFFFFFFFu, m, 2));
            if ((lane & 3) == 0)
                sMin[wm + mt * 16 + rr * 8 + fr][wn >> 6] = m;
        }
    __syncthreads();
    if (tid < 128)
        gmin[(size_t)(m0 + tid) * NTILES + blockIdx.x] =
            fminf(sMin[tid][0], sMin[tid][1]);
}

// ---------------------------------------------------------------------------
__global__ void __launch_bounds__(256, 2)
mma_linear_kernel(const __nv_bfloat16* __restrict__ Ahi, const __nv_bfloat16* __restrict__ Alo,
                  const __nv_bfloat16* __restrict__ Wth, const __nv_bfloat16* __restrict__ Wtl,
                  const float* __restrict__ bias,
                  __nv_bfloat16* __restrict__ Ohi, __nv_bfloat16* __restrict__ Olo,
                  float* __restrict__ nrm, float* __restrict__ Ofp, int nCh)
{
    __shared__ __align__(16) __nv_bfloat16 smem[8 * SLICE_ELEMS];
    __shared__ float snorm[128];
    __shared__ float sbias[128];
    const int tid = threadIdx.x;
    const int wid = tid >> 5, lane = tid & 31;
    const int m0 = blockIdx.x * 128;
    const int wm = (wid & 3) * 32;
    const int wn = (wid >> 2) * 64;
    const int lr = tid >> 1, lh = tid & 1;
    const int fr = lane >> 2, fc = (lane & 3) * 2;

    if (tid < 128) { sbias[tid] = bias[tid]; snorm[tid] = 0.f; }

    float acc[2][8][4];
#pragma unroll
    for (int mt = 0; mt < 2; mt++)
#pragma unroll
        for (int nt = 0; nt < 8; nt++)
#pragma unroll
            for (int j = 0; j < 4; j++) acc[mt][nt][j] = 0.f;

    gemm3_mainloop(Ahi, Alo, Wth, Wtl, smem, m0, 0, nCh,
                   wm, wn, fr, fc, lr, lh, acc);

#pragma unroll
    for (int mt = 0; mt < 2; mt++) {
        int r0 = wm + mt * 16 + fr;
        int r1 = r0 + 8;
        size_t g0 = (size_t)(m0 + r0) * 128;
        size_t g1 = (size_t)(m0 + r1) * 128;
        float ns0 = 0.f, ns1 = 0.f;
#pragma unroll
        for (int nt = 0; nt < 8; nt++) {
            int n = wn + nt * 8 + fc;
            float b0 = sbias[n], b1 = sbias[n + 1];
            float v00 = fmaxf(acc[mt][nt][0] + b0, 0.f);
            float v01 = fmaxf(acc[mt][nt][1] + b1, 0.f);
            float v10 = fmaxf(acc[mt][nt][2] + b0, 0.f);
            float v11 = fmaxf(acc[mt][nt][3] + b1, 0.f);
            ns0 += v00 * v00 + v01 * v01;
            ns1 += v10 * v10 + v11 * v11;
            __nv_bfloat162 h, l;
            h.x = __float2bfloat16_rn(v00);
            h.y = __float2bfloat16_rn(v01);
            l.x = __float2bfloat16_rn(v00 - __bfloat162float(h.x));
            l.y = __float2bfloat16_rn(v01 - __bfloat162float(h.y));
            *(__nv_bfloat162*)&Ohi[g0 + n] = h;
            *(__nv_bfloat162*)&Olo[g0 + n] = l;
            h.x = __float2bfloat16_rn(v10);
            h.y = __float2bfloat16_rn(v11);
            l.x = __float2bfloat16_rn(v10 - __bfloat162float(h.x));
            l.y = __float2bfloat16_rn(v11 - __bfloat162float(h.y));
            *(__nv_bfloat162*)&Ohi[g1 + n] = h;
            *(__nv_bfloat162*)&Olo[g1 + n] = l;
            if (Ofp) {
                *(float2*)&Ofp[g0 + n] = make_float2(v00, v01);
                *(float2*)&Ofp[g1 + n] = make_float2(v10, v11);
            }
        }
        atomicAdd(&snorm[r0], ns0);
        atomicAdd(&snorm[r1], ns1);
    }
    __syncthreads();
    if (tid < 128 && m0 + tid < NT) nrm[m0 + tid] = snorm[tid];
}

// ---------------------------------------------------------------------------
__global__ void __launch_bounds__(256)
linear_relu_kernel(const float* __restrict__ A, const float* __restrict__ W,
                   const float* __restrict__ bias, float* __restrict__ out,
                   int M, int K)
{
    __shared__ __align__(16) float As[16 * 68];
    __shared__ __align__(16) float Bs[16 * 136];
    const int tx = threadIdx.x, ty = threadIdx.y;
    const int tid = ty * 16 + tx;
    const int m0 = blockIdx.x * 64;

    float acc[4][8];
#pragma unroll
    for (int r = 0; r < 4; r++)
#pragma unroll
        for (int c = 0; c < 8; c++) acc[r][c] = 0.f;

    const int nChunks = (K + 15) / 16;
    for (int ch = 0; ch < nChunks; ch++) {
        const int k0 = ch * 16;
#pragma unroll
        for (int i = 0; i < 4; i++) {
            int e = tid + i * 256;
            int k = e & 15, m = e >> 4;
            float v = 0.f;
            if (k0 + k < K && m0 + m < M) v = A[(size_t)(m0 + m) * K + k0 + k];
            As[k * 68 + m] = v;
        }
#pragma unroll
        for (int i = 0; i < 8; i++) {
            int e = tid + i * 256;
            int h = e & 127, k = e >> 7;
            float v = 0.f;
            if (k0 + k < K) v = W[(size_t)(k0 + k) * HD + h];
            Bs[k * 136 + h] = v;
        }
        __syncthreads();
#pragma unroll
        for (int k = 0; k < 16; k++) {
            float4 a  = *(const float4*)&As[k * 68 + ty * 4];
            float4 b0 = *(const float4*)&Bs[k * 136 + tx * 4];
            float4 b1 = *(const float4*)&Bs[k * 136 + 64 + tx * 4];
            float av[4] = {a.x, a.y, a.z, a.w};
            float bv[8] = {b0.x, b0.y, b0.z, b0.w, b1.x, b1.y, b1.z, b1.w};
#pragma unroll
            for (int r = 0; r < 4; r++)
#pragma unroll
                for (int c = 0; c < 8; c++) acc[r][c] += av[r] * bv[c];
        }
        __syncthreads();
    }
#pragma unroll
    for (int r = 0; r < 4; r++) {
        int m = m0 + ty * 4 + r;
        if (m >= M) continue;
#pragma unroll
        for (int half = 0; half < 2; half++) {
#pragma unroll
            for (int c = 0; c < 4; c++) {
                int h = half * 64 + tx * 4 + c;
                float v = acc[r][half * 4 + c] + bias[h];
                out[(size_t)m * HD + h] = fmaxf(v, 0.f);
            }
        }
    }
}

// ---------------------------------------------------------------------------
__global__ void __launch_bounds__(256)
linear_softmax_kernel(const float* __restrict__ A, const float* __restrict__ W,
                      const float* __restrict__ bias, float* __restrict__ out, int M)
{
    __shared__ float Ws[HD * NL];
    __shared__ float bs[NL];
    int tid = threadIdx.x;
    for (int i = tid; i < HD * NL; i += 256) Ws[i] = W[i];
    if (tid < NL) bs[tid] = bias[tid];
    __syncthreads();

    int warp = tid >> 5, lane = tid & 31;
    int m = blockIdx.x * 8 + warp;
    if (m >= M) return;

    float acc[NL];
#pragma unroll
    for (int h = 0; h < NL; h++) acc[h] = 0.f;
    for (int k = lane; k < HD; k += 32) {
        float x = A[(size_t)m * HD + k];
#pragma unroll
        for (int h = 0; h < NL; h++) acc[h] += x * Ws[k * NL + h];
    }
#pragma unroll
    for (int h = 0; h < NL; h++)
#pragma unroll
        for (int off = 16; off > 0; off >>= 1)
            acc[h] += __shfl_down_sync(0xFFFFFFFFu, acc[h], off);

    if (lane == 0) {
        float v[NL], mx = -1e30f;
#pragma unroll
        for (int h = 0; h < NL; h++) { v[h] = acc[h] + bs[h]; mx = fmaxf(mx, v[h]); }
        float s = 0.f;
#pragma unroll
        for (int h = 0; h < NL; h++) { v[h] = expf(v[h] - mx); s += v[h]; }
        float inv = 1.0f / s;
#pragma unroll
        for (int h = 0; h < NL; h++) out[(size_t)m * NL + h] = v[h] * inv;
    }
}

// ---------------------------------------------------------------------------
// find_kth: shared by select and fused-l4.
// ---------------------------------------------------------------------------
__device__ __forceinline__ void find_kth(const unsigned* hist, int NB, unsigned kth,
                                         int tid, unsigned* s_bin, unsigned* s_kthr)
{
    if (tid < 32) {
        unsigned running = 0;
        for (int base = 0; base < NB; base += 32) {
            unsigned v = hist[base + tid];
            unsigned sc = v;
#pragma unroll
            for (int off = 1; off < 32; off <<= 1) {
                unsigned t = __shfl_up_sync(0xFFFFFFFFu, sc, off);
                if (tid >= off) sc += t;
            }
            unsigned tot = __shfl_sync(0xFFFFFFFFu, sc, 31);
            if (running + tot >= kth) {
                unsigned mask = __ballot_sync(0xFFFFFFFFu, running + sc >= kth);
                int l = __ffs(mask) - 1;
                if (tid == l) { *s_bin = (unsigned)(base + l); *s_kthr = kth - running - (sc - v); }
                break;
            }
            running += tot;
        }
    }
}

// ---------------------------------------------------------------------------
// Exact top-K select (layers 0-3): tile-min threshold + tile-subset scan.
// ---------------------------------------------------------------------------
#define SEL_THREADS 512
#define SEL_CAP 2048
#define OFF_CAND  16384
#define OFF_SEL   (OFF_CAND + SEL_CAP * 8)
#define OFF_TIES  (OFF_SEL + 1024)
#define OFF_TLAB  (OFF_TIES + 1024)
#define OFF_MINS  (OFF_TLAB + 512)
#define OFF_TLIST (OFF_MINS + 392 * 4)
#define SEL_SMEM  (OFF_TLIST + 392 * 4)

__global__ void __launch_bounds__(SEL_THREADS)
select_kernel(const float* __restrict__ d2mat, const float* __restrict__ gmin,
              const int* __restrict__ labels, float* __restrict__ total, int init)
{
    extern __shared__ __align__(16) char sms[];
    unsigned* hist = (unsigned*)sms;
    u64* cand  = (u64*)(sms + OFF_CAND);
    u64* sel   = (u64*)(sms + OFF_SEL);
    u64* ties  = (u64*)(sms + OFF_TIES);
    int* tlab  = (int*)(sms + OFF_TLAB);
    float* mins = (float*)(sms + OFF_MINS);
    int* tlist = (int*)(sms + OFF_TLIST);

    __shared__ unsigned s_M75, s_bin, s_kthr, s_candcnt, s_selcnt, s_tiecnt, s_ntiles;
    __shared__ float s_w[80];
    __shared__ int s_lab[80];

    const int b = blockIdx.x, tid = threadIdx.x, lane = tid & 31;
    const uint4* usrc = (const uint4*)(d2mat + (size_t)b * NT);
    const int NH = NT / 4;

    for (int i = tid; i < NTILES; i += SEL_THREADS)
        mins[i] = gmin[(size_t)b * NTILES + i];
    if (tid == 0) { s_candcnt = 0; s_selcnt = 0; s_tiecnt = 0; s_ntiles = 0; }
    __syncthreads();

    if (tid < NTILES) {
        unsigned key = __float_as_uint(mins[tid]);
        int c = 0;
        for (int j = 0; j < NTILES; j++) {
            unsigned kj = __float_as_uint(mins[j]);
            c += (kj < key) || (kj == key && j < tid);
        }
        if (c == KNN - 1) s_M75 = key;
    }
    __syncthreads();
    const unsigned Mkey = s_M75;

    if (tid < NTILES) {
        if (__float_as_uint(mins[tid]) <= Mkey) {
            unsigned s = atomicAdd(&s_ntiles, 1u);
            tlist[s] = tid;
        }
    }
    __syncthreads();
    const int ntl = (int)s_ntiles;

    for (int w = tid; w < ntl * 32; w += SEL_THREADS) {
        int t = tlist[w >> 5];
        int i4 = t * 32 + (w & 31);
        if (i4 < NH) {
            uint4 a = usrc[i4];
            unsigned k[4] = {a.x, a.y, a.z, a.w};
#pragma unroll
            for (int j = 0; j < 4; j++) {
                if (k[j] <= Mkey) {
                    unsigned s = atomicAdd(&s_candcnt, 1u);
                    if (s < SEL_CAP) cand[s] = ((u64)k[j] << 32) | (unsigned)(i4 * 4 + j);
                }
            }
        }
    }
    __syncthreads();

    unsigned Tkey;
    const unsigned candTotal = s_candcnt;

    if (candTotal <= SEL_CAP) {
        const int cc = (int)candTotal;
        for (int i = tid; i < 4096; i += SEL_THREADS) hist[i] = 0;
        __syncthreads();
        for (int i = tid; i < cc; i += SEL_THREADS)
            atomicAdd(&hist[(unsigned)(cand[i] >> 52)], 1u);
        __syncthreads();
        find_kth(hist, 4096, KNN, tid, &s_bin, &s_kthr);
        __syncthreads();
        const unsigned pfx = s_bin;
        const unsigned k1v = s_kthr;
        for (int i = tid; i < 4096; i += SEL_THREADS) hist[i] = 0;
        __syncthreads();
        for (int i = tid; i < cc; i += SEL_THREADS) {
            unsigned key = (unsigned)(cand[i] >> 32);
            if ((key >> 20) == pfx) atomicAdd(&hist[(key >> 8) & 0xFFFu], 1u);
        }
        __syncthreads();
        find_kth(hist, 4096, k1v, tid, &s_bin, &s_kthr);
        __syncthreads();
        const unsigned pfx20 = (pfx << 12) | s_bin;
        const unsigned k2v = s_kthr;
        for (int i = tid; i < 256; i += SEL_THREADS) hist[i] = 0;
        __syncthreads();
        for (int i = tid; i < cc; i += SEL_THREADS) {
            unsigned key = (unsigned)(cand[i] >> 32);
            if ((key >> 8) == pfx20) atomicAdd(&hist[key & 0xFFu], 1u);
        }
        __syncthreads();
        find_kth(hist, 256, k2v, tid, &s_bin, &s_kthr);
        __syncthreads();
        Tkey = (pfx20 << 8) | s_bin;
        for (int i = tid; i < cc; i += SEL_THREADS) {
            u64 cv = cand[i];
            unsigned key = (unsigned)(cv >> 32);
            if (key < Tkey) {
                unsigned s = atomicAdd(&s_selcnt, 1u);
                if (s < 128) sel[s] = cv;
            } else if (key == Tkey) {
                unsigned s = atomicAdd(&s_tiecnt, 1u);
                if (s < 128) ties[s] = cv;
            }
        }
        __syncthreads();
    } else {
        // fallback (degenerate ties): radix over the tile subset.
        for (int i = tid; i < 4096; i += SEL_THREADS) hist[i] = 0;
        __syncthreads();
        for (int w = tid; w < ntl * 32; w += SEL_THREADS) {
            int t = tlist[w >> 5];
            int i4 = t * 32 + (w & 31);
            uint4 a = (i4 < NH) ? usrc[i4] : make_uint4(~0u, ~0u, ~0u, ~0u);
            unsigned k[4] = {a.x, a.y, a.z, a.w};
#pragma unroll
            for (int j = 0; j < 4; j++) {
                unsigned bin = (k[j] <= Mkey) ? (k[j] >> 20) : 0xFFFFFFFFu;
                unsigned grp = __match_any_sync(0xFFFFFFFFu, bin);
                if (bin != 0xFFFFFFFFu && lane == __ffs(grp) - 1)
                    atomicAdd(&hist[bin], (unsigned)__popc(grp));
            }
        }
        __syncthreads();
        find_kth(hist, 4096, KNN, tid, &s_bin, &s_kthr);
        __syncthreads();
        const unsigned pfx = s_bin;
        const unsigned k1v = s_kthr;

        for (int i = tid; i < 4096; i += SEL_THREADS) hist[i] = 0;
        __syncthreads();
        for (int w = tid; w < ntl * 32; w += SEL_THREADS) {
            int t = tlist[w >> 5];
            int i4 = t * 32 + (w & 31);
            uint4 a = (i4 < NH) ? usrc[i4] : make_uint4(~0u, ~0u, ~0u, ~0u);
            unsigned k[4] = {a.x, a.y, a.z, a.w};
#pragma unroll
            for (int j = 0; j < 4; j++) {
                unsigned bin = (k[j] <= Mkey && (k[j] >> 20) == pfx)
                               ? ((k[j] >> 8) & 0xFFFu) : 0xFFFFFFFFu;
                unsigned grp = __match_any_sync(0xFFFFFFFFu, bin);
                if (bin != 0xFFFFFFFFu && lane == __ffs(grp) - 1)
                    atomicAdd(&hist[bin], (unsigned)__popc(grp));
            }
        }
        __syncthreads();
        find_kth(hist, 4096, k1v, tid, &s_bin, &s_kthr);
        __syncthreads();
        const unsigned pfx20 = (pfx << 12) | s_bin;
        const unsigned k2v = s_kthr;

        for (int i = tid; i < 256; i += SEL_THREADS) hist[i] = 0;
        __syncthreads();
        for (int w = tid; w < ntl * 32; w += SEL_THREADS) {
            int t = tlist[w >> 5];
            int i4 = t * 32 + (w & 31);
            uint4 a = (i4 < NH) ? usrc[i4] : make_uint4(~0u, ~0u, ~0u, ~0u);
            unsigned k[4] = {a.x, a.y, a.z, a.w};
#pragma unroll
            for (int j = 0; j < 4; j++) {
                unsigned bin = (k[j] <= Mkey && (k[j] >> 8) == pfx20)
                               ? (k[j] & 0xFFu) : 0xFFFFFFFFu;
                unsigned grp = __match_any_sync(0xFFFFFFFFu, bin);
                if (bin != 0xFFFFFFFFu && lane == __ffs(grp) - 1)
                    atomicAdd(&hist[bin], (unsigned)__popc(grp));
            }
        }
        __syncthreads();
        find_kth(hist, 256, k2v, tid, &s_bin, &s_kthr);
        __syncthreads();
        Tkey = (pfx20 << 8) | s_bin;

        for (int w = tid; w < ntl * 32; w += SEL_THREADS) {
            int t = tlist[w >> 5];
            int i4 = t * 32 + (w & 31);
            if (i4 < NH) {
                uint4 a = usrc[i4];
                unsigned k[4] = {a.x, a.y, a.z, a.w};
#pragma unroll
                for (int j = 0; j < 4; j++) {
                    if (k[j] < Tkey) {
                        unsigned s = atomicAdd(&s_selcnt, 1u);
                        if (s < 128) sel[s] = ((u64)k[j] << 32) | (unsigned)(i4 * 4 + j);
                    } else if (k[j] == Tkey) {
                        unsigned s = atomicAdd(&s_tiecnt, 1u);
                        if (s < 128) ties[s] = ((u64)k[j] << 32) | (unsigned)(i4 * 4 + j);
                    }
                }
            }
        }
        __syncthreads();
    }

    const int ns = min((int)s_selcnt, 128);
    const int ne = min((int)s_tiecnt, 128);

    if (tid < ns) {
        u64 mine = sel[tid];
        unsigned my_idx = (unsigned)(mine & 0xFFFFFFFFu);
        int rank = 0;
        for (int j = 0; j < ns; j++) rank += ((unsigned)(sel[j] & 0xFFFFFFFFu) < my_idx);
        float d2 = __uint_as_float((unsigned)(mine >> 32));
        s_w[rank] = (d2 > 0.f) ? __fdiv_rn(1.0f, __fsqrt_rn(d2)) : 0.f;
        s_lab[rank] = labels[my_idx];
    }
    if (tid >= 128 && tid - 128 < ne) {
        int t = tid - 128;
        unsigned my_idx = (unsigned)(ties[t] & 0xFFFFFFFFu);
        int rank = 0;
        for (int j = 0; j < ne; j++) rank += ((unsigned)(ties[j] & 0xFFFFFFFFu) < my_idx);
        tlab[rank] = labels[my_idx];
    }
    __syncthreads();

    if (tid == 0) {
        float cls[NL];
#pragma unroll
        for (int l = 0; l < NL; l++) cls[l] = 0.f;
        float stot = 0.f;
        for (int j = 0; j < ns; j++) { stot += s_w[j]; cls[s_lab[j]] += s_w[j]; }
        int need = KNN - ns;
        float d2T = __uint_as_float(Tkey);
        float wT = (d2T > 0.f) ? __fdiv_rn(1.0f, __fsqrt_rn(d2T)) : 0.f;
        int m = (need < ne) ? need : ne;
        for (int j = 0; j < m; j++) { stot += wT; cls[tlab[j]] += wT; }
#pragma unroll
        for (int l = 0; l < NL; l++) {
            float val = stot - cls[l];
            size_t o = (size_t)b * NL + l;
            if (init) total[o] = val; else total[o] += val;
        }
    }
}

// ---------------------------------------------------------------------------
// Fused layer-4 + p-value kernel. 8 queries per block; t4 (1.6 MB, L2-res)
// streamed once per block for tile minima, listed tiles recomputed per query.
// No d2 matrix traffic at all.
// ---------------------------------------------------------------------------
#define L4_THREADS 512
#define L4_CAP 2048
#define F4_HIST  0
#define F4_CAND  16384
#define F4_SEL   (F4_CAND + L4_CAP * 8)
#define F4_TIES  (F4_SEL + 1024)
#define F4_TLAB  (F4_TIES + 1024)
#define F4_MINS  (F4_TLAB + 512)
#define F4_TLIST (F4_MINS + 8 * 392 * 4)
#define F4_SQ    (F4_TLIST + 392 * 4)
#define F4_SMEM  (F4_SQ + 64 * 4)

__device__ __forceinline__ float l4_d2(const float* __restrict__ t4,
                                       const float* __restrict__ qv,
                                       float qq, int row)
{
    const float4* p = (const float4*)(t4 + (size_t)row * 8);
    float4 a = p[0], c = p[1];
    float tt = a.x * a.x + a.y * a.y + a.z * a.z + a.w * a.w
             + c.x * c.x + c.y * c.y + c.z * c.z + c.w * c.w;
    float dot = qv[0] * a.x + qv[1] * a.y + qv[2] * a.z + qv[3] * a.w
              + qv[4] * c.x + qv[5] * c.y + qv[6] * c.z + qv[7] * c.w;
    return fmaxf(qq + tt - 2.f * dot, 0.f);
}

__global__ void __launch_bounds__(L4_THREADS)
fused_l4_kernel(const float* __restrict__ q4, const float* __restrict__ t4,
                const int* __restrict__ labels, const float* __restrict__ total,
                const float* __restrict__ cali, float* __restrict__ out)
{
    extern __shared__ __align__(16) char sms[];
    unsigned* hist = (unsigned*)(sms + F4_HIST);
    u64* cand  = (u64*)(sms + F4_CAND);
    u64* sel   = (u64*)(sms + F4_SEL);
    u64* ties  = (u64*)(sms + F4_TIES);
    int* tlab  = (int*)(sms + F4_TLAB);
    float* mins = (float*)(sms + F4_MINS);   // [8][392]
    int* tlist = (int*)(sms + F4_TLIST);
    float* sq  = (float*)(sms + F4_SQ);      // [8][8]

    __shared__ unsigned s_M, s_bin, s_kthr, s_candcnt, s_selcnt, s_tiecnt, s_ntiles;
    __shared__ float s_w[80];
    __shared__ int s_lab[80];
    __shared__ float s_val[NL];
    __shared__ int s_cnt[NL];

    const int tid = threadIdx.x, warp = tid >> 5, lane = tid & 31;
    const int b0 = blockIdx.x * 8;
    const float FINF = __int_as_float(0x7F800000);

    if (tid < 64) sq[tid] = q4[(size_t)b0 * 8 + tid];
    __syncthreads();

    float qq[8];
#pragma unroll
    for (int qi = 0; qi < 8; qi++) {
        float s = 0.f;
#pragma unroll
        for (int j = 0; j < 8; j++) { float v = sq[qi * 8 + j]; s += v * v; }
        qq[qi] = s;
    }

    // ---- phase 1: per-(query, tile) minima; one t4 stream per block ----
    for (int t = warp; t < NTILES; t += 16) {
        float lmin[8];
#pragma unroll
        for (int qi = 0; qi < 8; qi++) lmin[qi] = FINF;
        for (int s = 0; s < 4; s++) {
            int row = t * 128 + s * 32 + lane;
            if (row < NT) {
#pragma unroll
                for (int qi = 0; qi < 8; qi++) {
                    float d2 = l4_d2(t4, &sq[qi * 8], qq[qi], row);
                    lmin[qi] = fminf(lmin[qi], d2);
                }
            }
        }
#pragma unroll
        for (int qi = 0; qi < 8; qi++) {
            float m = lmin[qi];
#pragma unroll
            for (int off = 16; off > 0; off >>= 1)
                m = fminf(m, __shfl_xor_sync(0xFFFFFFFFu, m, off));
            if (lane == 0) mins[qi * 392 + t] = m;
        }
    }
    __syncthreads();

    // ---- per-query select + p-value ----
    for (int qi = 0; qi < 8; qi++) {
        const int b = b0 + qi;
        const float* qv = &sq[qi * 8];
        const float qqv = qq[qi];
        const float* qmins = &mins[qi * 392];

        if (tid == 0) { s_candcnt = 0; s_selcnt = 0; s_tiecnt = 0; s_ntiles = 0; }
        __syncthreads();

        if (tid < NTILES) {
            unsigned key = __float_as_uint(qmins[tid]);
            int c = 0;
            for (int j = 0; j < NTILES; j++) {
                unsigned kj = __float_as_uint(qmins[j]);
                c += (kj < key) || (kj == key && j < tid);
            }
            if (c == KNN - 1) s_M = key;
        }
        __syncthreads();
        const unsigned Mkey = s_M;
        if (tid < NTILES && __float_as_uint(qmins[tid]) <= Mkey) {
            unsigned s = atomicAdd(&s_ntiles, 1u);
            tlist[s] = tid;
        }
        __syncthreads();
        const int ntl = (int)s_ntiles;

        // phase 2: recompute d2 over listed tiles, compact
        for (int idx = tid; idx < ntl * 128; idx += L4_THREADS) {
            int row = tlist[idx >> 7] * 128 + (idx & 127);
            if (row < NT) {
                unsigned key = __float_as_uint(l4_d2(t4, qv, qqv, row));
                if (key <= Mkey) {
                    unsigned s = atomicAdd(&s_candcnt, 1u);
                    if (s < L4_CAP) cand[s] = ((u64)key << 32) | (unsigned)row;
                }
            }
        }
        __syncthreads();

        unsigned Tkey;
        if (s_candcnt <= L4_CAP) {
            const int cc = (int)s_candcnt;
            for (int i = tid; i < 4096; i += L4_THREADS) hist[i] = 0;
            __syncthreads();
            for (int i = tid; i < cc; i += L4_THREADS)
                atomicAdd(&hist[(unsigned)(cand[i] >> 52)], 1u);
            __syncthreads();
            find_kth(hist, 4096, KNN, tid, &s_bin, &s_kthr);
            __syncthreads();
            const unsigned pfx = s_bin;
            const unsigned k1v = s_kthr;
            for (int i = tid; i < 4096; i += L4_THREADS) hist[i] = 0;
            __syncthreads();
            for (int i = tid; i < cc; i += L4_THREADS) {
                unsigned key = (unsigned)(cand[i] >> 32);
                if ((key >> 20) == pfx) atomicAdd(&hist[(key >> 8) & 0xFFFu], 1u);
            }
            __syncthreads();
            find_kth(hist, 4096, k1v, tid, &s_bin, &s_kthr);
            __syncthreads();
            const unsigned pfx20 = (pfx << 12) | s_bin;
            const unsigned k2v = s_kthr;
            for (int i = tid; i < 256; i += L4_THREADS) hist[i] = 0;
            __syncthreads();
            for (int i = tid; i < cc; i += L4_THREADS) {
                unsigned key = (unsigned)(cand[i] >> 32);
                if ((key >> 8) == pfx20) atomicAdd(&hist[key & 0xFFu], 1u);
            }
            __syncthreads();
            find_kth(hist, 256, k2v, tid, &s_bin, &s_kthr);
            __syncthreads();
            Tkey = (pfx20 << 8) | s_bin;
            for (int i = tid; i < cc; i += L4_THREADS) {
                u64 cv = cand[i];
                unsigned key = (unsigned)(cv >> 32);
                if (key < Tkey) {
                    unsigned s = atomicAdd(&s_selcnt, 1u);
                    if (s < 128) sel[s] = cv;
                } else if (key == Tkey) {
                    unsigned s = atomicAdd(&s_tiecnt, 1u);
                    if (s < 128) ties[s] = cv;
                }
            }
            __syncthreads();
        } else {
            // fallback: radix over listed tiles with inline d2 (degenerate ties)
            for (int i = tid; i < 4096; i += L4_THREADS) hist[i] = 0;
            __syncthreads();
            for (int idx = tid; idx < ntl * 128; idx += L4_THREADS) {
                int row = tlist[idx >> 7] * 128 + (idx & 127);
                unsigned bin = 0xFFFFFFFFu;
                if (row < NT) {
                    unsigned key = __float_as_uint(l4_d2(t4, qv, qqv, row));
                    if (key <= Mkey) bin = key >> 20;
                }
                unsigned grp = __match_any_sync(0xFFFFFFFFu, bin);
                if (bin != 0xFFFFFFFFu && lane == __ffs(grp) - 1)
                    atomicAdd(&hist[bin], (unsigned)__popc(grp));
            }
            __syncthreads();
            find_kth(hist, 4096, KNN, tid, &s_bin, &s_kthr);
            __syncthreads();
            const unsigned pfx = s_bin;
            const unsigned k1v = s_kthr;

            for (int i = tid; i < 4096; i += L4_THREADS) hist[i] = 0;
            __syncthreads();
            for (int idx = tid; idx < ntl * 128; idx += L4_THREADS) {
                int row = tlist[idx >> 7] * 128 + (idx & 127);
                unsigned bin = 0xFFFFFFFFu;
                if (row < NT) {
                    unsigned key = __float_as_uint(l4_d2(t4, qv, qqv, row));
                    if (key <= Mkey && (key >> 20) == pfx) bin = (key >> 8) & 0xFFFu;
                }
                unsigned grp = __match_any_sync(0xFFFFFFFFu, bin);
                if (bin != 0xFFFFFFFFu && lane == __ffs(grp) - 1)
                    atomicAdd(&hist[bin], (unsigned)__popc(grp));
            }
            __syncthreads();
            find_kth(hist, 4096, k1v, tid, &s_bin, &s_kthr);
            __syncthreads();
            const unsigned pfx20 = (pfx << 12) | s_bin;
            const unsigned k2v = s_kthr;

            for (int i = tid; i < 256; i += L4_THREADS) hist[i] = 0;
            __syncthreads();
            for (int idx = tid; idx < ntl * 128; idx += L4_THREADS) {
                int row = tlist[idx >> 7] * 128 + (idx & 127);
                unsigned bin = 0xFFFFFFFFu;
                if (row < NT) {
                    unsigned key = __float_as_uint(l4_d2(t4, qv, qqv, row));
                    if (key <= Mkey && (key >> 8) == pfx20) bin = key & 0xFFu;
                }
                unsigned grp = __match_any_sync(0xFFFFFFFFu, bin);
                if (bin != 0xFFFFFFFFu && lane == __ffs(grp) - 1)
                    atomicAdd(&hist[bin], (unsigned)__popc(grp));
            }
            __syncthreads();
            find_kth(hist, 256, k2v, tid, &s_bin, &s_kthr);
            __syncthreads();
            Tkey = (pfx20 << 8) | s_bin;

            for (int idx = tid; idx < ntl * 128; idx += L4_THREADS) {
                int row = tlist[idx >> 7] * 128 + (idx & 127);
                if (row < NT) {
                    unsigned key = __float_as_uint(l4_d2(t4, qv, qqv, row));
                    if (key < Tkey) {
                        unsigned s = atomicAdd(&s_selcnt, 1u);
                        if (s < 128) sel[s] = ((u64)key << 32) | (unsigned)row;
                    } else if (key == Tkey) {
                        unsigned s = atomicAdd(&s_tiecnt, 1u);
                        if (s < 128) ties[s] = ((u64)key << 32) | (unsigned)row;
                    }
                }
            }
            __syncthreads();
        }

        const int ns = min((int)s_selcnt, 128);
        const int ne = min((int)s_tiecnt, 128);

        if (tid < ns) {
            u64 mine = sel[tid];
            unsigned my_idx = (unsigned)(mine & 0xFFFFFFFFu);
            int rank = 0;
            for (int j = 0; j < ns; j++) rank += ((unsigned)(sel[j] & 0xFFFFFFFFu) < my_idx);
            float d2 = __uint_as_float((unsigned)(mine >> 32));
            s_w[rank] = (d2 > 0.f) ? __fdiv_rn(1.0f, __fsqrt_rn(d2)) : 0.f;
            s_lab[rank] = labels[my_idx];
        }
        if (tid >= 128 && tid - 128 < ne) {
            int t = tid - 128;
            unsigned my_idx = (unsigned)(ties[t] & 0xFFFFFFFFu);
            int rank = 0;
            for (int j = 0; j < ne; j++) rank += ((unsigned)(ties[j] & 0xFFFFFFFFu) < my_idx);
            tlab[rank] = labels[my_idx];
        }
        __syncthreads();

        if (tid == 0) {
            float cls[NL];
#pragma unroll
            for (int l = 0; l < NL; l++) cls[l] = 0.f;
            float stot = 0.f;
            for (int j = 0; j < ns; j++) { stot += s_w[j]; cls[s_lab[j]] += s_w[j]; }
            int need = KNN - ns;
            float d2T = __uint_as_float(Tkey);
            float wT = (d2T > 0.f) ? __fdiv_rn(1.0f, __fsqrt_rn(d2T)) : 0.f;
            int m = (need < ne) ? need : ne;
            for (int j = 0; j < m; j++) { stot += wT; cls[tlab[j]] += wT; }
#pragma unroll
            for (int l = 0; l < NL; l++)
                s_val[l] = total[(size_t)b * NL + l] + (stot - cls[l]);
        }
        if (tid < NL) s_cnt[tid] = 0;
        __syncthreads();

        // fused p-value for this query
        int cnt[NL];
#pragma unroll
        for (int l = 0; l < NL; l++) cnt[l] = 0;
        for (int i = tid; i < NC; i += L4_THREADS) {
            float cl = cali[i];
#pragma unroll
            for (int l = 0; l < NL; l++) cnt[l] += (cl >= s_val[l]) ? 1 : 0;
        }
#pragma unroll
        for (int l = 0; l < NL; l++) atomicAdd(&s_cnt[l], cnt[l]);
        __syncthreads();
        if (tid < NL) out[(size_t)b * NL + tid] = (float)s_cnt[tid] * (1.0f / NC);
        __syncthreads();
    }
}

// ---------------------------------------------------------------------------
extern "C" void kernel_launch(void* const* d_in, const int* in_sizes, int n_in,
                              void* d_out, int out_size)
{
    const float* x        = (const float*)d_in[0];
    const float* train_x  = (const float*)d_in[1];
    const int*   lab      = (const int*)  d_in[2];
    const float* cali     = (const float*)d_in[3];
    const float* W1 = (const float*)d_in[4];  const float* b1 = (const float*)d_in[5];
    const float* W2 = (const float*)d_in[6];  const float* b2 = (const float*)d_in[7];
    const float* W3 = (const float*)d_in[8];  const float* b3 = (const float*)d_in[9];
    const float* W4 = (const float*)d_in[10]; const float* b4 = (const float*)d_in[11];
    float* out = (float*)d_out;

    float *h1p, *h2p, *h3p, *q4p, *t3p, *t4p, *d2p, *qnp, *tnp, *totp, *minp;
    __nv_bfloat16 *qhip, *qlop, *thip, *tlop, *thi2p, *tlo2p;
    __nv_bfloat16 *w1th, *w1tl, *w2th, *w2tl, *w3th, *w3tl;
    cudaGetSymbolAddress((void**)&h1p, g_h1);
    cudaGetSymbolAddress((void**)&h2p, g_h2);
    cudaGetSymbolAddress((void**)&h3p, g_h3);
    cudaGetSymbolAddress((void**)&q4p, g_q4);
    cudaGetSymbolAddress((void**)&t3p, g_t3);
    cudaGetSymbolAddress((void**)&t4p, g_t4);
    cudaGetSymbolAddress((void**)&d2p, g_d2);
    cudaGetSymbolAddress((void**)&minp, g_min);
    cudaGetSymbolAddress((void**)&qnp, g_qn);
    cudaGetSymbolAddress((void**)&tnp, g_tn);
    cudaGetSymbolAddress((void**)&totp, g_tot);
    cudaGetSymbolAddress((void**)&qhip, g_qhi);
    cudaGetSymbolAddress((void**)&qlop, g_qlo);
    cudaGetSymbolAddress((void**)&thip, g_thi);
    cudaGetSymbolAddress((void**)&tlop, g_tlo);
    cudaGetSymbolAddress((void**)&thi2p, g_thi2);
    cudaGetSymbolAddress((void**)&tlo2p, g_tlo2);
    cudaGetSymbolAddress((void**)&w1th, g_w1th);
    cudaGetSymbolAddress((void**)&w1tl, g_w1tl);
    cudaGetSymbolAddress((void**)&w2th, g_w2th);
    cudaGetSymbolAddress((void**)&w2tl, g_w2tl);
    cudaGetSymbolAddress((void**)&w3th, g_w3th);
    cudaGetSymbolAddress((void**)&w3tl, g_w3tl);

    cudaFuncSetAttribute(select_kernel,
                         cudaFuncAttributeMaxDynamicSharedMemorySize, SEL_SMEM);
    cudaFuncSetAttribute(fused_l4_kernel,
                         cudaFuncAttributeMaxDynamicSharedMemorySize, F4_SMEM);

    dim3 tb(16, 16);
    const int D0 = 83;
    const dim3 mgrid(NTILES, BQ / 128);

    conv_norm_kernel<<<BQ / 8, 256>>>(x, qhip, qlop, qnp, BQ, D0);
    conv_norm_kernel<<<NTP / 8, 256>>>(train_x, thip, tlop, tnp, NT, D0);
    wt_convert_kernel<<<(3 * 128 * 128 + 255) / 256, 256>>>(W1, W2, W3);

    // layer 0 (mma_dist = launch #4 -> profiled)
    mma_dist_kernel<<<mgrid, 256>>>(qhip, qlop, thip, tlop, qnp, tnp, d2p, minp, 6);
    select_kernel<<<BQ, SEL_THREADS, SEL_SMEM>>>(d2p, minp, lab, totp, 1);

    // query-side MLP (tiny SIMT)
    linear_relu_kernel<<<BQ / 64, tb>>>(x,   W1, b1, h1p, BQ, D0);
    linear_relu_kernel<<<BQ / 64, tb>>>(h1p, W2, b2, h2p, BQ, HD);
    linear_relu_kernel<<<BQ / 64, tb>>>(h2p, W3, b3, h3p, BQ, HD);
    linear_softmax_kernel<<<(BQ + 7) / 8, 256>>>(h3p, W4, b4, q4p, BQ);

    // layer 1
    mma_linear_kernel<<<NTILES, 256>>>(thip, tlop, w1th, w1tl, b1,
                                       thi2p, tlo2p, tnp, (float*)0, 6);
    conv_norm_kernel<<<BQ / 8, 256>>>(h1p, qhip, qlop, qnp, BQ, HD);
    mma_dist_kernel<<<mgrid, 256>>>(qhip, qlop, thi2p, tlo2p, qnp, tnp, d2p, minp, 8);
    select_kernel<<<BQ, SEL_THREADS, SEL_SMEM>>>(d2p, minp, lab, totp, 0);

    // layer 2
    mma_linear_kernel<<<NTILES, 256>>>(thi2p, tlo2p, w2th, w2tl, b2,
                                       thip, tlop, tnp, (float*)0, 8);
    conv_norm_kernel<<<BQ / 8, 256>>>(h2p, qhip, qlop, qnp, BQ, HD);
    mma_dist_kernel<<<mgrid, 256>>>(qhip, qlop, thip, tlop, qnp, tnp, d2p, minp, 8);
    select_kernel<<<BQ, SEL_THREADS, SEL_SMEM>>>(d2p, minp, lab, totp, 0);

    // layer 3 (+ fp32 t3 for softmax)
    mma_linear_kernel<<<NTILES, 256>>>(thip, tlop, w3th, w3tl, b3,
                                       thi2p, tlo2p, tnp, t3p, 8);
    conv_norm_kernel<<<BQ / 8, 256>>>(h3p, qhip, qlop, qnp, BQ, HD);
    mma_dist_kernel<<<mgrid, 256>>>(qhip, qlop, thi2p, tlo2p, qnp, tnp, d2p, minp, 8);
    select_kernel<<<BQ, SEL_THREADS, SEL_SMEM>>>(d2p, minp, lab, totp, 0);

    // layer 4: fused softmax-features distance + select + p-value
    linear_softmax_kernel<<<(NT + 7) / 8, 256>>>(t3p, W4, b4, t4p, NT);
    fused_l4_kernel<<<BQ / 8, L4_THREADS, F4_SMEM>>>(q4p, t4p, lab, totp, cali, out);
}

// round 11
// speedup vs baseline: 1.0856x; 1.0856x over previous
#include <cuda_runtime.h>
#include <cuda_bf16.h>
#include <math.h>
#include <stdint.h>

#define BQ   1024
#define NT   50000
#define NTP  50048
#define NL   8
#define KNN  75
#define HD   128
#define NC   10000
#define NTILES 391          // NTP/128

typedef unsigned long long u64;

// ---------------- device scratch ----------------
__device__ float g_h1[BQ * HD];
__device__ float g_h2[BQ * HD];
__device__ float g_h3[BQ * HD];
__device__ float g_q4[BQ * NL];
__device__ float g_t3[(size_t)NT * HD];
__device__ float g_t4[(size_t)NT * NL];
__device__ float g_d2[(size_t)BQ * NT];
__device__ float g_min[(size_t)BQ * NTILES];
__device__ float g_qn[BQ];
__device__ float g_tn[NT];
__device__ float g_tot[BQ * NL];
__device__ __nv_bfloat16 g_qhi[(size_t)BQ * 128];
__device__ __nv_bfloat16 g_qlo[(size_t)BQ * 128];
__device__ __nv_bfloat16 g_thi[(size_t)NTP * 128];    // bank A
__device__ __nv_bfloat16 g_tlo[(size_t)NTP * 128];
__device__ __nv_bfloat16 g_thi2[(size_t)NTP * 128];   // bank B
__device__ __nv_bfloat16 g_tlo2[(size_t)NTP * 128];
__device__ __nv_bfloat16 g_w1th[128 * 128], g_w1tl[128 * 128];
__device__ __nv_bfloat16 g_w2th[128 * 128], g_w2tl[128 * 128];
__device__ __nv_bfloat16 g_w3th[128 * 128], g_w3tl[128 * 128];

// ---------------------------------------------------------------------------
__device__ __forceinline__ void mma_bf16(float* d, const uint32_t* a, const uint32_t* b)
{
    asm volatile(
        "mma.sync.aligned.m16n8k16.row.col.f32.bf16.bf16.f32 "
        "{%0,%1,%2,%3}, {%4,%5,%6,%7}, {%8,%9}, {%0,%1,%2,%3};"
        : "+f"(d[0]), "+f"(d[1]), "+f"(d[2]), "+f"(d[3])
        : "r"(a[0]), "r"(a[1]), "r"(a[2]), "r"(a[3]), "r"(b[0]), "r"(b[1]));
}

#define SLICE_ELEMS (128 * 24)

__device__ __forceinline__ void slice_load_async(
    const __nv_bfloat16* __restrict__ Gp, __nv_bfloat16* Ss,
    int row0, int k0, int lr, int lh)
{
    uint32_t sa = (uint32_t)__cvta_generic_to_shared(Ss + lr * 24 + lh * 8);
    const void* ga = Gp + (size_t)(row0 + lr) * 128 + k0 + lh * 8;
    asm volatile("cp.async.cg.shared.global [%0], [%1], 16;\n" :: "r"(sa), "l"(ga));
}

// ---------------------------------------------------------------------------
__global__ void __launch_bounds__(256)
conv_norm_kernel(const float* __restrict__ A, __nv_bfloat16* __restrict__ hi,
                 __nv_bfloat16* __restrict__ lo, float* __restrict__ nrm,
                 int Mreal, int D)
{
    int warp = threadIdx.x >> 5, lane = threadIdx.x & 31;
    int row = blockIdx.x * 8 + warp;
    int base = lane * 4;

    float ss = 0.f;
    __nv_bfloat16 hb[4], lb[4];
#pragma unroll
    for (int j = 0; j < 4; j++) {
        int col = base + j;
        float v = (row < Mreal && col < D) ? A[(size_t)row * D + col] : 0.f;
        ss += v * v;
        hb[j] = __float2bfloat16_rn(v);
        lb[j] = __float2bfloat16_rn(v - __bfloat162float(hb[j]));
    }
    __nv_bfloat162 h01, h23, l01, l23;
    h01.x = hb[0]; h01.y = hb[1]; h23.x = hb[2]; h23.y = hb[3];
    l01.x = lb[0]; l01.y = lb[1]; l23.x = lb[2]; l23.y = lb[3];
    *(__nv_bfloat162*)&hi[(size_t)row * 128 + base]     = h01;
    *(__nv_bfloat162*)&hi[(size_t)row * 128 + base + 2] = h23;
    *(__nv_bfloat162*)&lo[(size_t)row * 128 + base]     = l01;
    *(__nv_bfloat162*)&lo[(size_t)row * 128 + base + 2] = l23;

#pragma unroll
    for (int off = 16; off > 0; off >>= 1) ss += __shfl_down_sync(0xFFFFFFFFu, ss, off);
    if (lane == 0 && row < Mreal) nrm[row] = ss;
}

// ---------------------------------------------------------------------------
__global__ void __launch_bounds__(256)
wt_convert_kernel(const float* __restrict__ W1, const float* __restrict__ W2,
                  const float* __restrict__ W3)
{
    int idx = blockIdx.x * 256 + threadIdx.x;
    if (idx >= 3 * 128 * 128) return;
    int which = idx >> 14;
    int e = idx & 16383;
    int n = e & 127, k = e >> 7;
    const float* W = (which == 0) ? W1 : (which == 1) ? W2 : W3;
    int K = (which == 0) ? 83 : 128;
    float v = (k < K) ? W[(size_t)k * 128 + n] : 0.f;
    __nv_bfloat16 h = __float2bfloat16_rn(v);
    __nv_bfloat16 l = __float2bfloat16_rn(v - __bfloat162float(h));
    __nv_bfloat16* dh = (which == 0) ? g_w1th : (which == 1) ? g_w2th : g_w3th;
    __nv_bfloat16* dl = (which == 0) ? g_w1tl : (which == 1) ? g_w2tl : g_w3tl;
    dh[e] = h;
    dl[e] = l;
}

// ---------------------------------------------------------------------------
// bf16x3 GEMM mainloop, 3-pass MMA schedule (hh-all, lh-all, hl-all).
// Per-accumulator order unchanged (hh, lh, hl) -> bit-identical results;
// dependency distance between same-acc MMAs goes 2 -> 16.
// ---------------------------------------------------------------------------
__device__ __forceinline__ void gemm3_mainloop(
    const __nv_bfloat16* Ahi, const __nv_bfloat16* Alo,
    const __nv_bfloat16* Bhi, const __nv_bfloat16* Blo,
    __nv_bfloat16* smem, int m0, int n0, int nCh,
    int wm, int wn, int fr, int fc, int lr, int lh,
    float acc[2][8][4])
{
    __nv_bfloat16* AhiS[2] = {smem,                   smem + 4 * SLICE_ELEMS};
    __nv_bfloat16* AloS[2] = {smem + 1 * SLICE_ELEMS, smem + 5 * SLICE_ELEMS};
    __nv_bfloat16* BhiS[2] = {smem + 2 * SLICE_ELEMS, smem + 6 * SLICE_ELEMS};
    __nv_bfloat16* BloS[2] = {smem + 3 * SLICE_ELEMS, smem + 7 * SLICE_ELEMS};

    slice_load_async(Ahi, AhiS[0], m0, 0, lr, lh);
    slice_load_async(Alo, AloS[0], m0, 0, lr, lh);
    slice_load_async(Bhi, BhiS[0], n0, 0, lr, lh);
    slice_load_async(Blo, BloS[0], n0, 0, lr, lh);
    asm volatile("cp.async.commit_group;\n" ::: "memory");

    for (int c = 0; c < nCh; c++) {
        int buf = c & 1;
        if (c + 1 < nCh) {
            int k0 = (c + 1) * 16;
            slice_load_async(Ahi, AhiS[buf ^ 1], m0, k0, lr, lh);
            slice_load_async(Alo, AloS[buf ^ 1], m0, k0, lr, lh);
            slice_load_async(Bhi, BhiS[buf ^ 1], n0, k0, lr, lh);
            slice_load_async(Blo, BloS[buf ^ 1], n0, k0, lr, lh);
            asm volatile("cp.async.commit_group;\n" ::: "memory");
            asm volatile("cp.async.wait_group 1;" ::: "memory");
        } else {
            asm volatile("cp.async.wait_group 0;" ::: "memory");
        }
        __syncthreads();

        const __nv_bfloat16* Ah = AhiS[buf];
        const __nv_bfloat16* Al = AloS[buf];
        const __nv_bfloat16* Bh = BhiS[buf];
        const __nv_bfloat16* Bl = BloS[buf];

        uint32_t ah[2][4];
#pragma unroll
        for (int mt = 0; mt < 2; mt++) {
            int bm = wm + mt * 16;
            ah[mt][0] = *(const uint32_t*)&Ah[(bm + fr) * 24 + fc];
            ah[mt][1] = *(const uint32_t*)&Ah[(bm + fr + 8) * 24 + fc];
            ah[mt][2] = *(const uint32_t*)&Ah[(bm + fr) * 24 + fc + 8];
            ah[mt][3] = *(const uint32_t*)&Ah[(bm + fr + 8) * 24 + fc + 8];
        }
        uint32_t bh8[8][2];
#pragma unroll
        for (int nt = 0; nt < 8; nt++) {
            int nb = wn + nt * 8;
            bh8[nt][0] = *(const uint32_t*)&Bh[(nb + fr) * 24 + fc];
            bh8[nt][1] = *(const uint32_t*)&Bh[(nb + fr) * 24 + fc + 8];
        }
        // pass A: hi*hi (16 independent MMAs)
#pragma unroll
        for (int nt = 0; nt < 8; nt++) {
            mma_bf16(acc[0][nt], ah[0], bh8[nt]);
            mma_bf16(acc[1][nt], ah[1], bh8[nt]);
        }
        // pass B: lo*hi
        uint32_t al[2][4];
#pragma unroll
        for (int mt = 0; mt < 2; mt++) {
            int bm = wm + mt * 16;
            al[mt][0] = *(const uint32_t*)&Al[(bm + fr) * 24 + fc];
            al[mt][1] = *(const uint32_t*)&Al[(bm + fr + 8) * 24 + fc];
            al[mt][2] = *(const uint32_t*)&Al[(bm + fr) * 24 + fc + 8];
            al[mt][3] = *(const uint32_t*)&Al[(bm + fr + 8) * 24 + fc + 8];
        }
#pragma unroll
        for (int nt = 0; nt < 8; nt++) {
            mma_bf16(acc[0][nt], al[0], bh8[nt]);
            mma_bf16(acc[1][nt], al[1], bh8[nt]);
        }
        // pass C: hi*lo
#pragma unroll
        for (int nt = 0; nt < 8; nt++) {
            int nb = wn + nt * 8;
            uint32_t bl[2];
            bl[0] = *(const uint32_t*)&Bl[(nb + fr) * 24 + fc];
            bl[1] = *(const uint32_t*)&Bl[(nb + fr) * 24 + fc + 8];
            mma_bf16(acc[0][nt], ah[0], bl);
            mma_bf16(acc[1][nt], ah[1], bl);
        }
        __syncthreads();
    }
}

// ---------------------------------------------------------------------------
__global__ void __launch_bounds__(256, 2)
mma_dist_kernel(const __nv_bfloat16* __restrict__ Qhi, const __nv_bfloat16* __restrict__ Qlo,
                const __nv_bfloat16* __restrict__ Thi, const __nv_bfloat16* __restrict__ Tlo,
                const float* __restrict__ qn, const float* __restrict__ tn,
                float* __restrict__ out, float* __restrict__ gmin, int nCh)
{
    __shared__ __align__(16) __nv_bfloat16 smem[8 * SLICE_ELEMS];
    __shared__ float sMin[128][2];
    const int tid = threadIdx.x;
    const int wid = tid >> 5, lane = tid & 31;
    const int n0 = blockIdx.x * 128;
    const int m0 = blockIdx.y * 128;
    const int wm = (wid & 3) * 32;
    const int wn = (wid >> 2) * 64;
    const int lr = tid >> 1, lh = tid & 1;
    const int fr = lane >> 2, fc = (lane & 3) * 2;

    float acc[2][8][4];
#pragma unroll
    for (int mt = 0; mt < 2; mt++)
#pragma unroll
        for (int nt = 0; nt < 8; nt++)
#pragma unroll
            for (int j = 0; j < 4; j++) acc[mt][nt][j] = 0.f;

    gemm3_mainloop(Qhi, Qlo, Thi, Tlo, smem, m0, n0, nCh,
                   wm, wn, fr, fc, lr, lh, acc);

    const float FINF = __int_as_float(0x7F800000);
    float rmin[2][2] = {{FINF, FINF}, {FINF, FINF}};
#pragma unroll
    for (int mt = 0; mt < 2; mt++) {
        int mrow = m0 + wm + mt * 16 + fr;
        float q0 = qn[mrow], q1 = qn[mrow + 8];
#pragma unroll
        for (int nt = 0; nt < 8; nt++) {
            int n = n0 + wn + nt * 8 + fc;
            if (n < NT) {
                float t0 = tn[n], t1 = tn[n + 1];
                float2 o;
                o.x = fmaxf(q0 + t0 - 2.f * acc[mt][nt][0], 0.f);
                o.y = fmaxf(q0 + t1 - 2.f * acc[mt][nt][1], 0.f);
                *(float2*)&out[(size_t)mrow * NT + n] = o;
                rmin[mt][0] = fminf(rmin[mt][0], fminf(o.x, o.y));
                o.x = fmaxf(q1 + t0 - 2.f * acc[mt][nt][2], 0.f);
                o.y = fmaxf(q1 + t1 - 2.f * acc[mt][nt][3], 0.f);
                *(float2*)&out[(size_t)(mrow + 8) * NT + n] = o;
                rmin[mt][1] = fminf(rmin[mt][1], fminf(o.x, o.y));
            }
        }
    }
#pragma unroll
    for (int mt = 0; mt < 2; mt++)
#pragma unroll
        for (int rr = 0; rr < 2; rr++) {
            float m = rmin[mt][rr];
            m = fminf(m, __shfl_xor_sync(0xFFFFFFFFu, m, 1));
            m = fminf(m, __shfl_xor_sync(0xFFFFFFFFu, m, 2));
            if ((lane & 3) == 0)
                sMin[wm + mt * 16 + rr * 8 + fr][wn >> 6] = m;
        }
    __syncthreads();
    if (tid < 128)
        gmin[(size_t)(m0 + tid) * NTILES + blockIdx.x] =
            fminf(sMin[tid][0], sMin[tid][1]);
}

// ---------------------------------------------------------------------------
__global__ void __launch_bounds__(256, 2)
mma_linear_kernel(const __nv_bfloat16* __restrict__ Ahi, const __nv_bfloat16* __restrict__ Alo,
                  const __nv_bfloat16* __restrict__ Wth, const __nv_bfloat16* __restrict__ Wtl,
                  const float* __restrict__ bias,
                  __nv_bfloat16* __restrict__ Ohi, __nv_bfloat16* __restrict__ Olo,
                  float* __restrict__ nrm, float* __restrict__ Ofp, int nCh)
{
    __shared__ __align__(16) __nv_bfloat16 smem[8 * SLICE_ELEMS];
    __shared__ float snorm[128];
    __shared__ float sbias[128];
    const int tid = threadIdx.x;
    const int wid = tid >> 5, lane = tid & 31;
    const int m0 = blockIdx.x * 128;
    const int wm = (wid & 3) * 32;
    const int wn = (wid >> 2) * 64;
    const int lr = tid >> 1, lh = tid & 1;
    const int fr = lane >> 2, fc = (lane & 3) * 2;

    if (tid < 128) { sbias[tid] = bias[tid]; snorm[tid] = 0.f; }

    float acc[2][8][4];
#pragma unroll
    for (int mt = 0; mt < 2; mt++)
#pragma unroll
        for (int nt = 0; nt < 8; nt++)
#pragma unroll
            for (int j = 0; j < 4; j++) acc[mt][nt][j] = 0.f;

    gemm3_mainloop(Ahi, Alo, Wth, Wtl, smem, m0, 0, nCh,
                   wm, wn, fr, fc, lr, lh, acc);

#pragma unroll
    for (int mt = 0; mt < 2; mt++) {
        int r0 = wm + mt * 16 + fr;
        int r1 = r0 + 8;
        size_t g0 = (size_t)(m0 + r0) * 128;
        size_t g1 = (size_t)(m0 + r1) * 128;
        float ns0 = 0.f, ns1 = 0.f;
#pragma unroll
        for (int nt = 0; nt < 8; nt++) {
            int n = wn + nt * 8 + fc;
            float b0 = sbias[n], b1 = sbias[n + 1];
            float v00 = fmaxf(acc[mt][nt][0] + b0, 0.f);
            float v01 = fmaxf(acc[mt][nt][1] + b1, 0.f);
            float v10 = fmaxf(acc[mt][nt][2] + b0, 0.f);
            float v11 = fmaxf(acc[mt][nt][3] + b1, 0.f);
            ns0 += v00 * v00 + v01 * v01;
            ns1 += v10 * v10 + v11 * v11;
            __nv_bfloat162 h, l;
            h.x = __float2bfloat16_rn(v00);
            h.y = __float2bfloat16_rn(v01);
            l.x = __float2bfloat16_rn(v00 - __bfloat162float(h.x));
            l.y = __float2bfloat16_rn(v01 - __bfloat162float(h.y));
            *(__nv_bfloat162*)&Ohi[g0 + n] = h;
            *(__nv_bfloat162*)&Olo[g0 + n] = l;
            h.x = __float2bfloat16_rn(v10);
            h.y = __float2bfloat16_rn(v11);
            l.x = __float2bfloat16_rn(v10 - __bfloat162float(h.x));
            l.y = __float2bfloat16_rn(v11 - __bfloat162float(h.y));
            *(__nv_bfloat162*)&Ohi[g1 + n] = h;
            *(__nv_bfloat162*)&Olo[g1 + n] = l;
            if (Ofp) {
                *(float2*)&Ofp[g0 + n] = make_float2(v00, v01);
                *(float2*)&Ofp[g1 + n] = make_float2(v10, v11);
            }
        }
        atomicAdd(&snorm[r0], ns0);
        atomicAdd(&snorm[r1], ns1);
    }
    __syncthreads();
    if (tid < 128 && m0 + tid < NT) nrm[m0 + tid] = snorm[tid];
}

// ---------------------------------------------------------------------------
__global__ void __launch_bounds__(256)
linear_relu_kernel(const float* __restrict__ A, const float* __restrict__ W,
                   const float* __restrict__ bias, float* __restrict__ out,
                   int M, int K)
{
    __shared__ __align__(16) float As[16 * 68];
    __shared__ __align__(16) float Bs[16 * 136];
    const int tx = threadIdx.x, ty = threadIdx.y;
    const int tid = ty * 16 + tx;
    const int m0 = blockIdx.x * 64;

    float acc[4][8];
#pragma unroll
    for (int r = 0; r < 4; r++)
#pragma unroll
        for (int c = 0; c < 8; c++) acc[r][c] = 0.f;

    const int nChunks = (K + 15) / 16;
    for (int ch = 0; ch < nChunks; ch++) {
        const int k0 = ch * 16;
#pragma unroll
        for (int i = 0; i < 4; i++) {
            int e = tid + i * 256;
            int k = e & 15, m = e >> 4;
            float v = 0.f;
            if (k0 + k < K && m0 + m < M) v = A[(size_t)(m0 + m) * K + k0 + k];
            As[k * 68 + m] = v;
        }
#pragma unroll
        for (int i = 0; i < 8; i++) {
            int e = tid + i * 256;
            int h = e & 127, k = e >> 7;
            float v = 0.f;
            if (k0 + k < K) v = W[(size_t)(k0 + k) * HD + h];
            Bs[k * 136 + h] = v;
        }
        __syncthreads();
#pragma unroll
        for (int k = 0; k < 16; k++) {
            float4 a  = *(const float4*)&As[k * 68 + ty * 4];
            float4 b0 = *(const float4*)&Bs[k * 136 + tx * 4];
            float4 b1 = *(const float4*)&Bs[k * 136 + 64 + tx * 4];
            float av[4] = {a.x, a.y, a.z, a.w};
            float bv[8] = {b0.x, b0.y, b0.z, b0.w, b1.x, b1.y, b1.z, b1.w};
#pragma unroll
            for (int r = 0; r < 4; r++)
#pragma unroll
                for (int c = 0; c < 8; c++) acc[r][c] += av[r] * bv[c];
        }
        __syncthreads();
    }
#pragma unroll
    for (int r = 0; r < 4; r++) {
        int m = m0 + ty * 4 + r;
        if (m >= M) continue;
#pragma unroll
        for (int half = 0; half < 2; half++) {
#pragma unroll
            for (int c = 0; c < 4; c++) {
                int h = half * 64 + tx * 4 + c;
                float v = acc[r][half * 4 + c] + bias[h];
                out[(size_t)m * HD + h] = fmaxf(v, 0.f);
            }
        }
    }
}

// ---------------------------------------------------------------------------
__global__ void __launch_bounds__(256)
linear_softmax_kernel(const float* __restrict__ A, const float* __restrict__ W,
                      const float* __restrict__ bias, float* __restrict__ out, int M)
{
    __shared__ float Ws[HD * NL];
    __shared__ float bs[NL];
    int tid = threadIdx.x;
    for (int i = tid; i < HD * NL; i += 256) Ws[i] = W[i];
    if (tid < NL) bs[tid] = bias[tid];
    __syncthreads();

    int warp = tid >> 5, lane = tid & 31;
    int m = blockIdx.x * 8 + warp;
    if (m >= M) return;

    float acc[NL];
#pragma unroll
    for (int h = 0; h < NL; h++) acc[h] = 0.f;
    for (int k = lane; k < HD; k += 32) {
        float x = A[(size_t)m * HD + k];
#pragma unroll
        for (int h = 0; h < NL; h++) acc[h] += x * Ws[k * NL + h];
    }
#pragma unroll
    for (int h = 0; h < NL; h++)
#pragma unroll
        for (int off = 16; off > 0; off >>= 1)
            acc[h] += __shfl_down_sync(0xFFFFFFFFu, acc[h], off);

    if (lane == 0) {
        float v[NL], mx = -1e30f;
#pragma unroll
        for (int h = 0; h < NL; h++) { v[h] = acc[h] + bs[h]; mx = fmaxf(mx, v[h]); }
        float s = 0.f;
#pragma unroll
        for (int h = 0; h < NL; h++) { v[h] = expf(v[h] - mx); s += v[h]; }
        float inv = 1.0f / s;
#pragma unroll
        for (int h = 0; h < NL; h++) out[(size_t)m * NL + h] = v[h] * inv;
    }
}

// ---------------------------------------------------------------------------
__global__ void __launch_bounds__(256)
rownorm_kernel(const float* __restrict__ A, float* __restrict__ out, int M, int D)
{
    int warp = threadIdx.x >> 5, lane = threadIdx.x & 31;
    int m = blockIdx.x * 8 + warp;
    if (m >= M) return;
    float s = 0.f;
    for (int k = lane; k < D; k += 32) { float v = A[(size_t)m * D + k]; s += v * v; }
#pragma unroll
    for (int off = 16; off > 0; off >>= 1) s += __shfl_down_sync(0xFFFFFFFFu, s, off);
    if (lane == 0) out[m] = s;
}

// ---------------------------------------------------------------------------
// SIMT fp32 distance GEMM (layer 4, D=8) + tile min.
// ---------------------------------------------------------------------------
__global__ void __launch_bounds__(256)
dist_kernel(const float* __restrict__ Q, const float* __restrict__ T,
            const float* __restrict__ qn, const float* __restrict__ tn,
            float* __restrict__ out, float* __restrict__ gmin, int D, int Ncols)
{
    __shared__ __align__(16) float As[16 * 68];
    __shared__ __align__(16) float Bs[16 * 136];
    __shared__ unsigned sMinU[64];
    const int tx = threadIdx.x, ty = threadIdx.y;
    const int tid = ty * 16 + tx;
    const int n0 = blockIdx.x * 128;
    const int m0 = blockIdx.y * 64;

    if (tid < 64) sMinU[tid] = 0x7F800000u;

    float acc[4][8];
#pragma unroll
    for (int r = 0; r < 4; r++)
#pragma unroll
        for (int c = 0; c < 8; c++) acc[r][c] = 0.f;

    const int nChunks = (D + 15) / 16;
    for (int ch = 0; ch < nChunks; ch++) {
        const int k0 = ch * 16;
#pragma unroll
        for (int i = 0; i < 4; i++) {
            int e = tid + i * 256;
            int k = e & 15, m = e >> 4;
            float v = (k0 + k < D) ? Q[(size_t)(m0 + m) * D + k0 + k] : 0.f;
            As[k * 68 + m] = v;
        }
#pragma unroll
        for (int i = 0; i < 8; i++) {
            int e = tid + i * 256;
            int k = e & 15, n = e >> 4;
            int gn = n0 + n;
            float v = 0.f;
            if (k0 + k < D && gn < Ncols) v = T[(size_t)gn * D + k0 + k];
            Bs[k * 136 + n] = v;
        }
        __syncthreads();
#pragma unroll
        for (int k = 0; k < 16; k++) {
            float4 a  = *(const float4*)&As[k * 68 + ty * 4];
            float4 b0 = *(const float4*)&Bs[k * 136 + tx * 4];
            float4 b1 = *(const float4*)&Bs[k * 136 + 64 + tx * 4];
            float av[4] = {a.x, a.y, a.z, a.w};
            float bv[8] = {b0.x, b0.y, b0.z, b0.w, b1.x, b1.y, b1.z, b1.w};
#pragma unroll
            for (int r = 0; r < 4; r++)
#pragma unroll
                for (int c = 0; c < 8; c++) acc[r][c] += av[r] * bv[c];
        }
        __syncthreads();
    }
    const float FINF = __int_as_float(0x7F800000);
#pragma unroll
    for (int r = 0; r < 4; r++) {
        int m = m0 + ty * 4 + r;
        float qv = qn[m];
        float lm = FINF;
#pragma unroll
        for (int half = 0; half < 2; half++) {
#pragma unroll
            for (int c = 0; c < 4; c++) {
                int n = n0 + half * 64 + tx * 4 + c;
                if (n < Ncols) {
                    float d = fmaxf(qv + tn[n] - 2.f * acc[r][half * 4 + c], 0.f);
                    out[(size_t)m * Ncols + n] = d;
                    lm = fminf(lm, d);
                }
            }
        }
        if (lm < FINF) atomicMin(&sMinU[ty * 4 + r], __float_as_uint(lm));
    }
    __syncthreads();
    if (tid < 64)
        gmin[(size_t)(m0 + tid) * NTILES + blockIdx.x] = __uint_as_float(sMinU[tid]);
}

// ---------------------------------------------------------------------------
__device__ __forceinline__ void find_kth(const unsigned* hist, int NB, unsigned kth,
                                         int tid, unsigned* s_bin, unsigned* s_kthr)
{
    if (tid < 32) {
        unsigned running = 0;
        for (int base = 0; base < NB; base += 32) {
            unsigned v = hist[base + tid];
            unsigned sc = v;
#pragma unroll
            for (int off = 1; off < 32; off <<= 1) {
                unsigned t = __shfl_up_sync(0xFFFFFFFFu, sc, off);
                if (tid >= off) sc += t;
            }
            unsigned tot = __shfl_sync(0xFFFFFFFFu, sc, 31);
            if (running + tot >= kth) {
                unsigned mask = __ballot_sync(0xFFFFFFFFu, running + sc >= kth);
                int l = __ffs(mask) - 1;
                if (tid == l) { *s_bin = (unsigned)(base + l); *s_kthr = kth - running - (sc - v); }
                break;
            }
            running += tot;
        }
    }
}

// ---------------------------------------------------------------------------
// Exact top-K select: tile-min threshold + tile-subset scan.
// ---------------------------------------------------------------------------
#define SEL_THREADS 512
#define SEL_CAP 2048
#define OFF_CAND  16384
#define OFF_SEL   (OFF_CAND + SEL_CAP * 8)
#define OFF_TIES  (OFF_SEL + 1024)
#define OFF_TLAB  (OFF_TIES + 1024)
#define OFF_MINS  (OFF_TLAB + 512)
#define OFF_TLIST (OFF_MINS + 392 * 4)
#define SEL_SMEM  (OFF_TLIST + 392 * 4)

__global__ void __launch_bounds__(SEL_THREADS)
select_kernel(const float* __restrict__ d2mat, const float* __restrict__ gmin,
              const int* __restrict__ labels, float* __restrict__ total, int init)
{
    extern __shared__ __align__(16) char sms[];
    unsigned* hist = (unsigned*)sms;
    u64* cand  = (u64*)(sms + OFF_CAND);
    u64* sel   = (u64*)(sms + OFF_SEL);
    u64* ties  = (u64*)(sms + OFF_TIES);
    int* tlab  = (int*)(sms + OFF_TLAB);
    float* mins = (float*)(sms + OFF_MINS);
    int* tlist = (int*)(sms + OFF_TLIST);

    __shared__ unsigned s_M75, s_bin, s_kthr, s_candcnt, s_selcnt, s_tiecnt, s_ntiles;
    __shared__ float s_w[80];
    __shared__ int s_lab[80];

    const int b = blockIdx.x, tid = threadIdx.x, lane = tid & 31;
    const uint4* usrc = (const uint4*)(d2mat + (size_t)b * NT);
    const int NH = NT / 4;

    for (int i = tid; i < NTILES; i += SEL_THREADS)
        mins[i] = gmin[(size_t)b * NTILES + i];
    if (tid == 0) { s_candcnt = 0; s_selcnt = 0; s_tiecnt = 0; s_ntiles = 0; }
    __syncthreads();

    if (tid < NTILES) {
        unsigned key = __float_as_uint(mins[tid]);
        int c = 0;
        for (int j = 0; j < NTILES; j++) {
            unsigned kj = __float_as_uint(mins[j]);
            c += (kj < key) || (kj == key && j < tid);
        }
        if (c == KNN - 1) s_M75 = key;
    }
    __syncthreads();
    const unsigned Mkey = s_M75;

    if (tid < NTILES) {
        if (__float_as_uint(mins[tid]) <= Mkey) {
            unsigned s = atomicAdd(&s_ntiles, 1u);
            tlist[s] = tid;
        }
    }
    __syncthreads();
    const int ntl = (int)s_ntiles;

    for (int w = tid; w < ntl * 32; w += SEL_THREADS) {
        int t = tlist[w >> 5];
        int i4 = t * 32 + (w & 31);
        if (i4 < NH) {
            uint4 a = usrc[i4];
            unsigned k[4] = {a.x, a.y, a.z, a.w};
#pragma unroll
            for (int j = 0; j < 4; j++) {
                if (k[j] <= Mkey) {
                    unsigned s = atomicAdd(&s_candcnt, 1u);
                    if (s < SEL_CAP) cand[s] = ((u64)k[j] << 32) | (unsigned)(i4 * 4 + j);
                }
            }
        }
    }
    __syncthreads();

    unsigned Tkey;
    const unsigned candTotal = s_candcnt;

    if (candTotal <= SEL_CAP) {
        const int cc = (int)candTotal;
        for (int i = tid; i < 4096; i += SEL_THREADS) hist[i] = 0;
        __syncthreads();
        for (int i = tid; i < cc; i += SEL_THREADS)
            atomicAdd(&hist[(unsigned)(cand[i] >> 52)], 1u);
        __syncthreads();
        find_kth(hist, 4096, KNN, tid, &s_bin, &s_kthr);
        __syncthreads();
        const unsigned pfx = s_bin;
        const unsigned k1v = s_kthr;
        for (int i = tid; i < 4096; i += SEL_THREADS) hist[i] = 0;
        __syncthreads();
        for (int i = tid; i < cc; i += SEL_THREADS) {
            unsigned key = (unsigned)(cand[i] >> 32);
            if ((key >> 20) == pfx) atomicAdd(&hist[(key >> 8) & 0xFFFu], 1u);
        }
        __syncthreads();
        find_kth(hist, 4096, k1v, tid, &s_bin, &s_kthr);
        __syncthreads();
        const unsigned pfx20 = (pfx << 12) | s_bin;
        const unsigned k2v = s_kthr;
        for (int i = tid; i < 256; i += SEL_THREADS) hist[i] = 0;
        __syncthreads();
        for (int i = tid; i < cc; i += SEL_THREADS) {
            unsigned key = (unsigned)(cand[i] >> 32);
            if ((key >> 8) == pfx20) atomicAdd(&hist[key & 0xFFu], 1u);
        }
        __syncthreads();
        find_kth(hist, 256, k2v, tid, &s_bin, &s_kthr);
        __syncthreads();
        Tkey = (pfx20 << 8) | s_bin;
        for (int i = tid; i < cc; i += SEL_THREADS) {
            u64 cv = cand[i];
            unsigned key = (unsigned)(cv >> 32);
            if (key < Tkey) {
                unsigned s = atomicAdd(&s_selcnt, 1u);
                if (s < 128) sel[s] = cv;
            } else if (key == Tkey) {
                unsigned s = atomicAdd(&s_tiecnt, 1u);
                if (s < 128) ties[s] = cv;
            }
        }
        __syncthreads();
    } else {
        // fallback (degenerate ties): radix over the tile subset.
        for (int i = tid; i < 4096; i += SEL_THREADS) hist[i] = 0;
        __syncthreads();
        for (int w = tid; w < ntl * 32; w += SEL_THREADS) {
            int t = tlist[w >> 5];
            int i4 = t * 32 + (w & 31);
            uint4 a = (i4 < NH) ? usrc[i4] : make_uint4(~0u, ~0u, ~0u, ~0u);
            unsigned k[4] = {a.x, a.y, a.z, a.w};
#pragma unroll
            for (int j = 0; j < 4; j++) {
                unsigned bin = (k[j] <= Mkey) ? (k[j] >> 20) : 0xFFFFFFFFu;
                unsigned grp = __match_any_sync(0xFFFFFFFFu, bin);
                if (bin != 0xFFFFFFFFu && lane == __ffs(grp) - 1)
                    atomicAdd(&hist[bin], (unsigned)__popc(grp));
            }
        }
        __syncthreads();
        find_kth(hist, 4096, KNN, tid, &s_bin, &s_kthr);
        __syncthreads();
        const unsigned pfx = s_bin;
        const unsigned k1v = s_kthr;

        for (int i = tid; i < 4096; i += SEL_THREADS) hist[i] = 0;
        __syncthreads();
        for (int w = tid; w < ntl * 32; w += SEL_THREADS) {
            int t = tlist[w >> 5];
            int i4 = t * 32 + (w & 31);
            uint4 a = (i4 < NH) ? usrc[i4] : make_uint4(~0u, ~0u, ~0u, ~0u);
            unsigned k[4] = {a.x, a.y, a.z, a.w};
#pragma unroll
            for (int j = 0; j < 4; j++) {
                unsigned bin = (k[j] <= Mkey && (k[j] >> 20) == pfx)
                               ? ((k[j] >> 8) & 0xFFFu) : 0xFFFFFFFFu;
                unsigned grp = __match_any_sync(0xFFFFFFFFu, bin);
                if (bin != 0xFFFFFFFFu && lane == __ffs(grp) - 1)
                    atomicAdd(&hist[bin], (unsigned)__popc(grp));
            }
        }
        __syncthreads();
        find_kth(hist, 4096, k1v, tid, &s_bin, &s_kthr);
        __syncthreads();
        const unsigned pfx20 = (pfx << 12) | s_bin;
        const unsigned k2v = s_kthr;

        for (int i = tid; i < 256; i += SEL_THREADS) hist[i] = 0;
        __syncthreads();
        for (int w = tid; w < ntl * 32; w += SEL_THREADS) {
            int t = tlist[w >> 5];
            int i4 = t * 32 + (w & 31);
            uint4 a = (i4 < NH) ? usrc[i4] : make_uint4(~0u, ~0u, ~0u, ~0u);
            unsigned k[4] = {a.x, a.y, a.z, a.w};
#pragma unroll
            for (int j = 0; j < 4; j++) {
                unsigned bin = (k[j] <= Mkey && (k[j] >> 8) == pfx20)
                               ? (k[j] & 0xFFu) : 0xFFFFFFFFu;
                unsigned grp = __match_any_sync(0xFFFFFFFFu, bin);
                if (bin != 0xFFFFFFFFu && lane == __ffs(grp) - 1)
                    atomicAdd(&hist[bin], (unsigned)__popc(grp));
            }
        }
        __syncthreads();
        find_kth(hist, 256, k2v, tid, &s_bin, &s_kthr);
        __syncthreads();
        Tkey = (pfx20 << 8) | s_bin;

        for (int w = tid; w < ntl * 32; w += SEL_THREADS) {
            int t = tlist[w >> 5];
            int i4 = t * 32 + (w & 31);
            if (i4 < NH) {
                uint4 a = usrc[i4];
                unsigned k[4] = {a.x, a.y, a.z, a.w};
#pragma unroll
                for (int j = 0; j < 4; j++) {
                    if (k[j] < Tkey) {
                        unsigned s = atomicAdd(&s_selcnt, 1u);
                        if (s < 128) sel[s] = ((u64)k[j] << 32) | (unsigned)(i4 * 4 + j);
                    } else if (k[j] == Tkey) {
                        unsigned s = atomicAdd(&s_tiecnt, 1u);
                        if (s < 128) ties[s] = ((u64)k[j] << 32) | (unsigned)(i4 * 4 + j);
                    }
                }
            }
        }
        __syncthreads();
    }

    const int ns = min((int)s_selcnt, 128);
    const int ne = min((int)s_tiecnt, 128);

    if (tid < ns) {
        u64 mine = sel[tid];
        unsigned my_idx = (unsigned)(mine & 0xFFFFFFFFu);
        int rank = 0;
        for (int j = 0; j < ns; j++) rank += ((unsigned)(sel[j] & 0xFFFFFFFFu) < my_idx);
        float d2 = __uint_as_float((unsigned)(mine >> 32));
        s_w[rank] = (d2 > 0.f) ? __fdiv_rn(1.0f, __fsqrt_rn(d2)) : 0.f;
        s_lab[rank] = labels[my_idx];
    }
    if (tid >= 128 && tid - 128 < ne) {
        int t = tid - 128;
        unsigned my_idx = (unsigned)(ties[t] & 0xFFFFFFFFu);
        int rank = 0;
        for (int j = 0; j < ne; j++) rank += ((unsigned)(ties[j] & 0xFFFFFFFFu) < my_idx);
        tlab[rank] = labels[my_idx];
    }
    __syncthreads();

    if (tid == 0) {
        float cls[NL];
#pragma unroll
        for (int l = 0; l < NL; l++) cls[l] = 0.f;
        float stot = 0.f;
        for (int j = 0; j < ns; j++) { stot += s_w[j]; cls[s_lab[j]] += s_w[j]; }
        int need = KNN - ns;
        float d2T = __uint_as_float(Tkey);
        float wT = (d2T > 0.f) ? __fdiv_rn(1.0f, __fsqrt_rn(d2T)) : 0.f;
        int m = (need < ne) ? need : ne;
        for (int j = 0; j < m; j++) { stot += wT; cls[tlab[j]] += wT; }
#pragma unroll
        for (int l = 0; l < NL; l++) {
            float val = stot - cls[l];
            size_t o = (size_t)b * NL + l;
            if (init) total[o] = val; else total[o] += val;
        }
    }
}

// ---------------------------------------------------------------------------
__global__ void __launch_bounds__(256)
pvalue_kernel(const float* __restrict__ total, const float* __restrict__ cali,
              float* __restrict__ out)
{
    const int b = blockIdx.x, tid = threadIdx.x;
    float t[NL];
#pragma unroll
    for (int l = 0; l < NL; l++) t[l] = total[(size_t)b * NL + l];
    int cnt[NL];
#pragma unroll
    for (int l = 0; l < NL; l++) cnt[l] = 0;
    for (int i = tid; i < NC; i += 256) {
        float c = cali[i];
#pragma unroll
        for (int l = 0; l < NL; l++) cnt[l] += (c >= t[l]) ? 1 : 0;
    }
    __shared__ int sc[NL];
    if (tid < NL) sc[tid] = 0;
    __syncthreads();
#pragma unroll
    for (int l = 0; l < NL; l++) atomicAdd(&sc[l], cnt[l]);
    __syncthreads();
    if (tid < NL) out[(size_t)b * NL + tid] = (float)sc[tid] * (1.0f / NC);
}

// ---------------------------------------------------------------------------
extern "C" void kernel_launch(void* const* d_in, const int* in_sizes, int n_in,
                              void* d_out, int out_size)
{
    const float* x        = (const float*)d_in[0];
    const float* train_x  = (const float*)d_in[1];
    const int*   lab      = (const int*)  d_in[2];
    const float* cali     = (const float*)d_in[3];
    const float* W1 = (const float*)d_in[4];  const float* b1 = (const float*)d_in[5];
    const float* W2 = (const float*)d_in[6];  const float* b2 = (const float*)d_in[7];
    const float* W3 = (const float*)d_in[8];  const float* b3 = (const float*)d_in[9];
    const float* W4 = (const float*)d_in[10]; const float* b4 = (const float*)d_in[11];
    float* out = (float*)d_out;

    float *h1p, *h2p, *h3p, *q4p, *t3p, *t4p, *d2p, *qnp, *tnp, *totp, *minp;
    __nv_bfloat16 *qhip, *qlop, *thip, *tlop, *thi2p, *tlo2p;
    __nv_bfloat16 *w1th, *w1tl, *w2th, *w2tl, *w3th, *w3tl;
    cudaGetSymbolAddress((void**)&h1p, g_h1);
    cudaGetSymbolAddress((void**)&h2p, g_h2);
    cudaGetSymbolAddress((void**)&h3p, g_h3);
    cudaGetSymbolAddress((void**)&q4p, g_q4);
    cudaGetSymbolAddress((void**)&t3p, g_t3);
    cudaGetSymbolAddress((void**)&t4p, g_t4);
    cudaGetSymbolAddress((void**)&d2p, g_d2);
    cudaGetSymbolAddress((void**)&minp, g_min);
    cudaGetSymbolAddress((void**)&qnp, g_qn);
    cudaGetSymbolAddress((void**)&tnp, g_tn);
    cudaGetSymbolAddress((void**)&totp, g_tot);
    cudaGetSymbolAddress((void**)&qhip, g_qhi);
    cudaGetSymbolAddress((void**)&qlop, g_qlo);
    cudaGetSymbolAddress((void**)&thip, g_thi);
    cudaGetSymbolAddress((void**)&tlop, g_tlo);
    cudaGetSymbolAddress((void**)&thi2p, g_thi2);
    cudaGetSymbolAddress((void**)&tlo2p, g_tlo2);
    cudaGetSymbolAddress((void**)&w1th, g_w1th);
    cudaGetSymbolAddress((void**)&w1tl, g_w1tl);
    cudaGetSymbolAddress((void**)&w2th, g_w2th);
    cudaGetSymbolAddress((void**)&w2tl, g_w2tl);
    cudaGetSymbolAddress((void**)&w3th, g_w3th);
    cudaGetSymbolAddress((void**)&w3tl, g_w3tl);

    cudaFuncSetAttribute(select_kernel,
                         cudaFuncAttributeMaxDynamicSharedMemorySize, SEL_SMEM);

    dim3 tb(16, 16);
    const int D0 = 83;
    const dim3 mgrid(NTILES, BQ / 128);

    conv_norm_kernel<<<BQ / 8, 256>>>(x, qhip, qlop, qnp, BQ, D0);
    conv_norm_kernel<<<NTP / 8, 256>>>(train_x, thip, tlop, tnp, NT, D0);
    wt_convert_kernel<<<(3 * 128 * 128 + 255) / 256, 256>>>(W1, W2, W3);

    // layer 0 (mma_dist = launch #4 -> profiled)
    mma_dist_kernel<<<mgrid, 256>>>(qhip, qlop, thip, tlop, qnp, tnp, d2p, minp, 6);
    select_kernel<<<BQ, SEL_THREADS, SEL_SMEM>>>(d2p, minp, lab, totp, 1);

    // query-side MLP (tiny SIMT)
    linear_relu_kernel<<<BQ / 64, tb>>>(x,   W1, b1, h1p, BQ, D0);
    linear_relu_kernel<<<BQ / 64, tb>>>(h1p, W2, b2, h2p, BQ, HD);
    linear_relu_kernel<<<BQ / 64, tb>>>(h2p, W3, b3, h3p, BQ, HD);
    linear_softmax_kernel<<<(BQ + 7) / 8, 256>>>(h3p, W4, b4, q4p, BQ);

    // layer 1
    mma_linear_kernel<<<NTILES, 256>>>(thip, tlop, w1th, w1tl, b1,
                                       thi2p, tlo2p, tnp, (float*)0, 6);
    conv_norm_kernel<<<BQ / 8, 256>>>(h1p, qhip, qlop, qnp, BQ, HD);
    mma_dist_kernel<<<mgrid, 256>>>(qhip, qlop, thi2p, tlo2p, qnp, tnp, d2p, minp, 8);
    select_kernel<<<BQ, SEL_THREADS, SEL_SMEM>>>(d2p, minp, lab, totp, 0);

    // layer 2
    mma_linear_kernel<<<NTILES, 256>>>(thi2p, tlo2p, w2th, w2tl, b2,
                                       thip, tlop, tnp, (float*)0, 8);
    conv_norm_kernel<<<BQ / 8, 256>>>(h2p, qhip, qlop, qnp, BQ, HD);
    mma_dist_kernel<<<mgrid, 256>>>(qhip, qlop, thip, tlop, qnp, tnp, d2p, minp, 8);
    select_kernel<<<BQ, SEL_THREADS, SEL_SMEM>>>(d2p, minp, lab, totp, 0);

    // layer 3 (+ fp32 t3 for softmax)
    mma_linear_kernel<<<NTILES, 256>>>(thip, tlop, w3th, w3tl, b3,
                                       thi2p, tlo2p, tnp, t3p, 8);
    conv_norm_kernel<<<BQ / 8, 256>>>(h3p, qhip, qlop, qnp, BQ, HD);
    mma_dist_kernel<<<mgrid, 256>>>(qhip, qlop, thi2p, tlo2p, qnp, tnp, d2p, minp, 8);
    select_kernel<<<BQ, SEL_THREADS, SEL_SMEM>>>(d2p, minp, lab, totp, 0);

    // layer 4 (softmax features, D=8): exact fp32 path
    linear_softmax_kernel<<<(NT + 7) / 8, 256>>>(t3p, W4, b4, t4p, NT);
    rownorm_kernel<<<(BQ + 7) / 8, 256>>>(q4p, qnp, BQ, NL);
    rownorm_kernel<<<(NT + 7) / 8, 256>>>(t4p, tnp, NT, NL);
    dist_kernel<<<dim3(NTILES, BQ / 64), tb>>>(q4p, t4p, qnp, tnp, d2p, minp, NL, NT);
    select_kernel<<<BQ, SEL_THREADS, SEL_SMEM>>>(d2p, minp, lab, totp, 0);

    pvalue_kernel<<<BQ, 256>>>(totp, cali, out);
}

// round 12
// speedup vs baseline: 1.0895x; 1.0036x over previous
#include <cuda_runtime.h>
#include <cuda_bf16.h>
#include <math.h>
#include <stdint.h>

#define BQ   1024
#define NT   50000
#define NTP  50048
#define NL   8
#define KNN  75
#define HD   128
#define NC   10000
#define NTILES 391          // NTP/128

typedef unsigned long long u64;

// ---------------- device scratch ----------------
__device__ float g_h1[BQ * HD];
__device__ float g_h2[BQ * HD];
__device__ float g_h3[BQ * HD];
__device__ float g_q4[BQ * NL];
__device__ float g_t3[(size_t)NT * HD];
__device__ float g_t4[(size_t)NT * NL];
__device__ float g_d2[(size_t)BQ * NT];
__device__ float g_min[(size_t)BQ * NTILES];
__device__ float g_qn[BQ];
__device__ float g_tn[NT];
__device__ float g_tot[BQ * NL];
__device__ __nv_bfloat16 g_qhi[(size_t)BQ * 128];
__device__ __nv_bfloat16 g_qlo[(size_t)BQ * 128];
__device__ __nv_bfloat16 g_thi[(size_t)NTP * 128];    // bank A
__device__ __nv_bfloat16 g_tlo[(size_t)NTP * 128];
__device__ __nv_bfloat16 g_thi2[(size_t)NTP * 128];   // bank B
__device__ __nv_bfloat16 g_tlo2[(size_t)NTP * 128];
__device__ __nv_bfloat16 g_w1th[128 * 128], g_w1tl[128 * 128];
__device__ __nv_bfloat16 g_w2th[128 * 128], g_w2tl[128 * 128];
__device__ __nv_bfloat16 g_w3th[128 * 128], g_w3tl[128 * 128];

// ---------------------------------------------------------------------------
__device__ __forceinline__ void mma_bf16(float* d, const uint32_t* a, const uint32_t* b)
{
    asm volatile(
        "mma.sync.aligned.m16n8k16.row.col.f32.bf16.bf16.f32 "
        "{%0,%1,%2,%3}, {%4,%5,%6,%7}, {%8,%9}, {%0,%1,%2,%3};"
        : "+f"(d[0]), "+f"(d[1]), "+f"(d[2]), "+f"(d[3])
        : "r"(a[0]), "r"(a[1]), "r"(a[2]), "r"(a[3]), "r"(b[0]), "r"(b[1]));
}

#define SLICE_ELEMS (128 * 24)

__device__ __forceinline__ void slice_load_async(
    const __nv_bfloat16* __restrict__ Gp, __nv_bfloat16* Ss,
    int row0, int k0, int lr, int lh)
{
    uint32_t sa = (uint32_t)__cvta_generic_to_shared(Ss + lr * 24 + lh * 8);
    const void* ga = Gp + (size_t)(row0 + lr) * 128 + k0 + lh * 8;
    asm volatile("cp.async.cg.shared.global [%0], [%1], 16;\n" :: "r"(sa), "l"(ga));
}

// ---------------------------------------------------------------------------
__global__ void __launch_bounds__(256)
conv_norm_kernel(const float* __restrict__ A, __nv_bfloat16* __restrict__ hi,
                 __nv_bfloat16* __restrict__ lo, float* __restrict__ nrm,
                 int Mreal, int D)
{
    int warp = threadIdx.x >> 5, lane = threadIdx.x & 31;
    int row = blockIdx.x * 8 + warp;
    int base = lane * 4;

    float ss = 0.f;
    __nv_bfloat16 hb[4], lb[4];
#pragma unroll
    for (int j = 0; j < 4; j++) {
        int col = base + j;
        float v = (row < Mreal && col < D) ? A[(size_t)row * D + col] : 0.f;
        ss += v * v;
        hb[j] = __float2bfloat16_rn(v);
        lb[j] = __float2bfloat16_rn(v - __bfloat162float(hb[j]));
    }
    __nv_bfloat162 h01, h23, l01, l23;
    h01.x = hb[0]; h01.y = hb[1]; h23.x = hb[2]; h23.y = hb[3];
    l01.x = lb[0]; l01.y = lb[1]; l23.x = lb[2]; l23.y = lb[3];
    *(__nv_bfloat162*)&hi[(size_t)row * 128 + base]     = h01;
    *(__nv_bfloat162*)&hi[(size_t)row * 128 + base + 2] = h23;
    *(__nv_bfloat162*)&lo[(size_t)row * 128 + base]     = l01;
    *(__nv_bfloat162*)&lo[(size_t)row * 128 + base + 2] = l23;

#pragma unroll
    for (int off = 16; off > 0; off >>= 1) ss += __shfl_down_sync(0xFFFFFFFFu, ss, off);
    if (lane == 0 && row < Mreal) nrm[row] = ss;
}

// ---------------------------------------------------------------------------
__global__ void __launch_bounds__(256)
wt_convert_kernel(const float* __restrict__ W1, const float* __restrict__ W2,
                  const float* __restrict__ W3)
{
    int idx = blockIdx.x * 256 + threadIdx.x;
    if (idx >= 3 * 128 * 128) return;
    int which = idx >> 14;
    int e = idx & 16383;
    int n = e & 127, k = e >> 7;
    const float* W = (which == 0) ? W1 : (which == 1) ? W2 : W3;
    int K = (which == 0) ? 83 : 128;
    float v = (k < K) ? W[(size_t)k * 128 + n] : 0.f;
    __nv_bfloat16 h = __float2bfloat16_rn(v);
    __nv_bfloat16 l = __float2bfloat16_rn(v - __bfloat162float(h));
    __nv_bfloat16* dh = (which == 0) ? g_w1th : (which == 1) ? g_w2th : g_w3th;
    __nv_bfloat16* dl = (which == 0) ? g_w1tl : (which == 1) ? g_w2tl : g_w3tl;
    dh[e] = h;
    dl[e] = l;
}

// ---------------------------------------------------------------------------
// bf16x3 GEMM mainloop (128-row tiles, 2-buffer) - used by mma_linear_kernel.
// ---------------------------------------------------------------------------
__device__ __forceinline__ void gemm3_mainloop(
    const __nv_bfloat16* Ahi, const __nv_bfloat16* Alo,
    const __nv_bfloat16* Bhi, const __nv_bfloat16* Blo,
    __nv_bfloat16* smem, int m0, int n0, int nCh,
    int wm, int wn, int fr, int fc, int lr, int lh,
    float acc[2][8][4])
{
    __nv_bfloat16* AhiS[2] = {smem,                   smem + 4 * SLICE_ELEMS};
    __nv_bfloat16* AloS[2] = {smem + 1 * SLICE_ELEMS, smem + 5 * SLICE_ELEMS};
    __nv_bfloat16* BhiS[2] = {smem + 2 * SLICE_ELEMS, smem + 6 * SLICE_ELEMS};
    __nv_bfloat16* BloS[2] = {smem + 3 * SLICE_ELEMS, smem + 7 * SLICE_ELEMS};

    slice_load_async(Ahi, AhiS[0], m0, 0, lr, lh);
    slice_load_async(Alo, AloS[0], m0, 0, lr, lh);
    slice_load_async(Bhi, BhiS[0], n0, 0, lr, lh);
    slice_load_async(Blo, BloS[0], n0, 0, lr, lh);
    asm volatile("cp.async.commit_group;\n" ::: "memory");

    for (int c = 0; c < nCh; c++) {
        int buf = c & 1;
        if (c + 1 < nCh) {
            int k0 = (c + 1) * 16;
            slice_load_async(Ahi, AhiS[buf ^ 1], m0, k0, lr, lh);
            slice_load_async(Alo, AloS[buf ^ 1], m0, k0, lr, lh);
            slice_load_async(Bhi, BhiS[buf ^ 1], n0, k0, lr, lh);
            slice_load_async(Blo, BloS[buf ^ 1], n0, k0, lr, lh);
            asm volatile("cp.async.commit_group;\n" ::: "memory");
            asm volatile("cp.async.wait_group 1;" ::: "memory");
        } else {
            asm volatile("cp.async.wait_group 0;" ::: "memory");
        }
        __syncthreads();

        const __nv_bfloat16* Ah = AhiS[buf];
        const __nv_bfloat16* Al = AloS[buf];
        const __nv_bfloat16* Bh = BhiS[buf];
        const __nv_bfloat16* Bl = BloS[buf];

        uint32_t ah[2][4];
#pragma unroll
        for (int mt = 0; mt < 2; mt++) {
            int bm = wm + mt * 16;
            ah[mt][0] = *(const uint32_t*)&Ah[(bm + fr) * 24 + fc];
            ah[mt][1] = *(const uint32_t*)&Ah[(bm + fr + 8) * 24 + fc];
            ah[mt][2] = *(const uint32_t*)&Ah[(bm + fr) * 24 + fc + 8];
            ah[mt][3] = *(const uint32_t*)&Ah[(bm + fr + 8) * 24 + fc + 8];
        }
        uint32_t bh8[8][2];
#pragma unroll
        for (int nt = 0; nt < 8; nt++) {
            int nb = wn + nt * 8;
            bh8[nt][0] = *(const uint32_t*)&Bh[(nb + fr) * 24 + fc];
            bh8[nt][1] = *(const uint32_t*)&Bh[(nb + fr) * 24 + fc + 8];
        }
#pragma unroll
        for (int nt = 0; nt < 8; nt++) {
            mma_bf16(acc[0][nt], ah[0], bh8[nt]);
            mma_bf16(acc[1][nt], ah[1], bh8[nt]);
        }
        uint32_t al[2][4];
#pragma unroll
        for (int mt = 0; mt < 2; mt++) {
            int bm = wm + mt * 16;
            al[mt][0] = *(const uint32_t*)&Al[(bm + fr) * 24 + fc];
            al[mt][1] = *(const uint32_t*)&Al[(bm + fr + 8) * 24 + fc];
            al[mt][2] = *(const uint32_t*)&Al[(bm + fr) * 24 + fc + 8];
            al[mt][3] = *(const uint32_t*)&Al[(bm + fr + 8) * 24 + fc + 8];
        }
#pragma unroll
        for (int nt = 0; nt < 8; nt++) {
            mma_bf16(acc[0][nt], al[0], bh8[nt]);
            mma_bf16(acc[1][nt], al[1], bh8[nt]);
        }
#pragma unroll
        for (int nt = 0; nt < 8; nt++) {
            int nb = wn + nt * 8;
            uint32_t bl[2];
            bl[0] = *(const uint32_t*)&Bl[(nb + fr) * 24 + fc];
            bl[1] = *(const uint32_t*)&Bl[(nb + fr) * 24 + fc + 8];
            mma_bf16(acc[0][nt], ah[0], bl);
            mma_bf16(acc[1][nt], ah[1], bl);
        }
        __syncthreads();
    }
}

// ---------------------------------------------------------------------------
// 256x128 distance GEMM, 512 threads, 3-stage pipeline, 1 sync per chunk.
// A slices: 256x16 (stride 24); B slices: 128x16.
// Accumulation order per element unchanged (hh, lh, hl per chunk).
// ---------------------------------------------------------------------------
#define ASL (256 * 24)          // A slice elems
#define BSL (128 * 24)          // B slice elems
#define STAGE_ELEMS (2 * ASL + 2 * BSL)   // 18432 elems
#define MD_SMEM (3 * STAGE_ELEMS * 2)     // 110592 bytes

__global__ void __launch_bounds__(512, 1)
mma_dist_kernel(const __nv_bfloat16* __restrict__ Qhi, const __nv_bfloat16* __restrict__ Qlo,
                const __nv_bfloat16* __restrict__ Thi, const __nv_bfloat16* __restrict__ Tlo,
                const float* __restrict__ qn, const float* __restrict__ tn,
                float* __restrict__ out, float* __restrict__ gmin, int nCh)
{
    extern __shared__ __align__(16) __nv_bfloat16 dsm[];
    __shared__ float sMin[256][2];
    const int tid = threadIdx.x;
    const int wid = tid >> 5, lane = tid & 31;
    const int n0 = blockIdx.x * 128;
    const int m0 = blockIdx.y * 256;
    const int wm = (wid & 7) * 32;          // 8 m-blocks
    const int wn = (wid >> 3) * 64;         // 2 n-halves
    const int fr = lane >> 2, fc = (lane & 3) * 2;
    const int ar = tid >> 1, ah2 = tid & 1;             // A loader: 256 rows x 2
    const int br = (tid & 255) >> 1, bh2 = tid & 1;     // B loader: 128 rows x 2

    float acc[2][8][4];
#pragma unroll
    for (int mt = 0; mt < 2; mt++)
#pragma unroll
        for (int nt = 0; nt < 8; nt++)
#pragma unroll
            for (int j = 0; j < 4; j++) acc[mt][nt][j] = 0.f;

    // stage s base: dsm + s*STAGE_ELEMS; layout: Ahi | Alo | Bhi | Blo
#define LOAD_STAGE(s, k0) do {                                                  \
        __nv_bfloat16* sb_ = dsm + (s) * STAGE_ELEMS;                           \
        slice_load_async(Qhi, sb_,            m0, (k0), ar, ah2);               \
        slice_load_async(Qlo, sb_ + ASL,      m0, (k0), ar, ah2);               \
        if (tid < 256) slice_load_async(Thi, sb_ + 2 * ASL,      n0, (k0), br, bh2); \
        else           slice_load_async(Tlo, sb_ + 2 * ASL + BSL, n0, (k0), br, bh2); \
        asm volatile("cp.async.commit_group;\n" ::: "memory");                  \
    } while (0)

    LOAD_STAGE(0, 0);
    if (nCh > 1) LOAD_STAGE(1, 16);

    for (int c = 0; c < nCh; c++) {
        if (c + 1 < nCh) asm volatile("cp.async.wait_group 1;" ::: "memory");
        else             asm volatile("cp.async.wait_group 0;" ::: "memory");
        __syncthreads();
        if (c + 2 < nCh) LOAD_STAGE((c + 2) % 3, (c + 2) * 16);

        const __nv_bfloat16* sb = dsm + (c % 3) * STAGE_ELEMS;
        const __nv_bfloat16* Ah = sb;
        const __nv_bfloat16* Al = sb + ASL;
        const __nv_bfloat16* Bh = sb + 2 * ASL;
        const __nv_bfloat16* Bl = sb + 2 * ASL + BSL;

        uint32_t ah[2][4];
#pragma unroll
        for (int mt = 0; mt < 2; mt++) {
            int bm = wm + mt * 16;
            ah[mt][0] = *(const uint32_t*)&Ah[(bm + fr) * 24 + fc];
            ah[mt][1] = *(const uint32_t*)&Ah[(bm + fr + 8) * 24 + fc];
            ah[mt][2] = *(const uint32_t*)&Ah[(bm + fr) * 24 + fc + 8];
            ah[mt][3] = *(const uint32_t*)&Ah[(bm + fr + 8) * 24 + fc + 8];
        }
        uint32_t bh8[8][2];
#pragma unroll
        for (int nt = 0; nt < 8; nt++) {
            int nb = wn + nt * 8;
            bh8[nt][0] = *(const uint32_t*)&Bh[(nb + fr) * 24 + fc];
            bh8[nt][1] = *(const uint32_t*)&Bh[(nb + fr) * 24 + fc + 8];
        }
        // pass A: hi*hi
#pragma unroll
        for (int nt = 0; nt < 8; nt++) {
            mma_bf16(acc[0][nt], ah[0], bh8[nt]);
            mma_bf16(acc[1][nt], ah[1], bh8[nt]);
        }
        // pass B: lo*hi
        uint32_t al[2][4];
#pragma unroll
        for (int mt = 0; mt < 2; mt++) {
            int bm = wm + mt * 16;
            al[mt][0] = *(const uint32_t*)&Al[(bm + fr) * 24 + fc];
            al[mt][1] = *(const uint32_t*)&Al[(bm + fr + 8) * 24 + fc];
            al[mt][2] = *(const uint32_t*)&Al[(bm + fr) * 24 + fc + 8];
            al[mt][3] = *(const uint32_t*)&Al[(bm + fr + 8) * 24 + fc + 8];
        }
#pragma unroll
        for (int nt = 0; nt < 8; nt++) {
            mma_bf16(acc[0][nt], al[0], bh8[nt]);
            mma_bf16(acc[1][nt], al[1], bh8[nt]);
        }
        // pass C: hi*lo
#pragma unroll
        for (int nt = 0; nt < 8; nt++) {
            int nb = wn + nt * 8;
            uint32_t bl[2];
            bl[0] = *(const uint32_t*)&Bl[(nb + fr) * 24 + fc];
            bl[1] = *(const uint32_t*)&Bl[(nb + fr) * 24 + fc + 8];
            mma_bf16(acc[0][nt], ah[0], bl);
            mma_bf16(acc[1][nt], ah[1], bl);
        }
    }
#undef LOAD_STAGE

    const float FINF = __int_as_float(0x7F800000);
    float rmin[2][2] = {{FINF, FINF}, {FINF, FINF}};
#pragma unroll
    for (int mt = 0; mt < 2; mt++) {
        int mrow = m0 + wm + mt * 16 + fr;
        float q0 = qn[mrow], q1 = qn[mrow + 8];
#pragma unroll
        for (int nt = 0; nt < 8; nt++) {
            int n = n0 + wn + nt * 8 + fc;
            if (n < NT) {
                float t0 = tn[n], t1 = tn[n + 1];
                float2 o;
                o.x = fmaxf(q0 + t0 - 2.f * acc[mt][nt][0], 0.f);
                o.y = fmaxf(q0 + t1 - 2.f * acc[mt][nt][1], 0.f);
                *(float2*)&out[(size_t)mrow * NT + n] = o;
                rmin[mt][0] = fminf(rmin[mt][0], fminf(o.x, o.y));
                o.x = fmaxf(q1 + t0 - 2.f * acc[mt][nt][2], 0.f);
                o.y = fmaxf(q1 + t1 - 2.f * acc[mt][nt][3], 0.f);
                *(float2*)&out[(size_t)(mrow + 8) * NT + n] = o;
                rmin[mt][1] = fminf(rmin[mt][1], fminf(o.x, o.y));
            }
        }
    }
    __syncthreads();   // all MMA-phase smem reads done before sMin reuse is irrelevant (separate buffer) - kept for store ordering clarity
#pragma unroll
    for (int mt = 0; mt < 2; mt++)
#pragma unroll
        for (int rr = 0; rr < 2; rr++) {
            float m = rmin[mt][rr];
            m = fminf(m, __shfl_xor_sync(0xFFFFFFFFu, m, 1));
            m = fminf(m, __shfl_xor_sync(0xFFFFFFFFu, m, 2));
            if ((lane & 3) == 0)
                sMin[wm + mt * 16 + rr * 8 + fr][wn >> 6] = m;
        }
    __syncthreads();
    if (tid < 256)
        gmin[(size_t)(m0 + tid) * NTILES + blockIdx.x] =
            fminf(sMin[tid][0], sMin[tid][1]);
}

// ---------------------------------------------------------------------------
__global__ void __launch_bounds__(256, 2)
mma_linear_kernel(const __nv_bfloat16* __restrict__ Ahi, const __nv_bfloat16* __restrict__ Alo,
                  const __nv_bfloat16* __restrict__ Wth, const __nv_bfloat16* __restrict__ Wtl,
                  const float* __restrict__ bias,
                  __nv_bfloat16* __restrict__ Ohi, __nv_bfloat16* __restrict__ Olo,
                  float* __restrict__ nrm, float* __restrict__ Ofp, int nCh)
{
    __shared__ __align__(16) __nv_bfloat16 smem[8 * SLICE_ELEMS];
    __shared__ float snorm[128];
    __shared__ float sbias[128];
    const int tid = threadIdx.x;
    const int wid = tid >> 5, lane = tid & 31;
    const int m0 = blockIdx.x * 128;
    const int wm = (wid & 3) * 32;
    const int wn = (wid >> 2) * 64;
    const int lr = tid >> 1, lh = tid & 1;
    const int fr = lane >> 2, fc = (lane & 3) * 2;

    if (tid < 128) { sbias[tid] = bias[tid]; snorm[tid] = 0.f; }

    float acc[2][8][4];
#pragma unroll
    for (int mt = 0; mt < 2; mt++)
#pragma unroll
        for (int nt = 0; nt < 8; nt++)
#pragma unroll
            for (int j = 0; j < 4; j++) acc[mt][nt][j] = 0.f;

    gemm3_mainloop(Ahi, Alo, Wth, Wtl, smem, m0, 0, nCh,
                   wm, wn, fr, fc, lr, lh, acc);

#pragma unroll
    for (int mt = 0; mt < 2; mt++) {
        int r0 = wm + mt * 16 + fr;
        int r1 = r0 + 8;
        size_t g0 = (size_t)(m0 + r0) * 128;
        size_t g1 = (size_t)(m0 + r1) * 128;
        float ns0 = 0.f, ns1 = 0.f;
#pragma unroll
        for (int nt = 0; nt < 8; nt++) {
            int n = wn + nt * 8 + fc;
            float b0 = sbias[n], b1 = sbias[n + 1];
            float v00 = fmaxf(acc[mt][nt][0] + b0, 0.f);
            float v01 = fmaxf(acc[mt][nt][1] + b1, 0.f);
            float v10 = fmaxf(acc[mt][nt][2] + b0, 0.f);
            float v11 = fmaxf(acc[mt][nt][3] + b1, 0.f);
            ns0 += v00 * v00 + v01 * v01;
            ns1 += v10 * v10 + v11 * v11;
            __nv_bfloat162 h, l;
            h.x = __float2bfloat16_rn(v00);
            h.y = __float2bfloat16_rn(v01);
            l.x = __float2bfloat16_rn(v00 - __bfloat162float(h.x));
            l.y = __float2bfloat16_rn(v01 - __bfloat162float(h.y));
            *(__nv_bfloat162*)&Ohi[g0 + n] = h;
            *(__nv_bfloat162*)&Olo[g0 + n] = l;
            h.x = __float2bfloat16_rn(v10);
            h.y = __float2bfloat16_rn(v11);
            l.x = __float2bfloat16_rn(v10 - __bfloat162float(h.x));
            l.y = __float2bfloat16_rn(v11 - __bfloat162float(h.y));
            *(__nv_bfloat162*)&Ohi[g1 + n] = h;
            *(__nv_bfloat162*)&Olo[g1 + n] = l;
            if (Ofp) {
                *(float2*)&Ofp[g0 + n] = make_float2(v00, v01);
                *(float2*)&Ofp[g1 + n] = make_float2(v10, v11);
            }
        }
        atomicAdd(&snorm[r0], ns0);
        atomicAdd(&snorm[r1], ns1);
    }
    __syncthreads();
    if (tid < 128 && m0 + tid < NT) nrm[m0 + tid] = snorm[tid];
}

// ---------------------------------------------------------------------------
__global__ void __launch_bounds__(256)
linear_relu_kernel(const float* __restrict__ A, const float* __restrict__ W,
                   const float* __restrict__ bias, float* __restrict__ out,
                   int M, int K)
{
    __shared__ __align__(16) float As[16 * 68];
    __shared__ __align__(16) float Bs[16 * 136];
    const int tx = threadIdx.x, ty = threadIdx.y;
    const int tid = ty * 16 + tx;
    const int m0 = blockIdx.x * 64;

    float acc[4][8];
#pragma unroll
    for (int r = 0; r < 4; r++)
#pragma unroll
        for (int c = 0; c < 8; c++) acc[r][c] = 0.f;

    const int nChunks = (K + 15) / 16;
    for (int ch = 0; ch < nChunks; ch++) {
        const int k0 = ch * 16;
#pragma unroll
        for (int i = 0; i < 4; i++) {
            int e = tid + i * 256;
            int k = e & 15, m = e >> 4;
            float v = 0.f;
            if (k0 + k < K && m0 + m < M) v = A[(size_t)(m0 + m) * K + k0 + k];
            As[k * 68 + m] = v;
        }
#pragma unroll
        for (int i = 0; i < 8; i++) {
            int e = tid + i * 256;
            int h = e & 127, k = e >> 7;
            float v = 0.f;
            if (k0 + k < K) v = W[(size_t)(k0 + k) * HD + h];
            Bs[k * 136 + h] = v;
        }
        __syncthreads();
#pragma unroll
        for (int k = 0; k < 16; k++) {
            float4 a  = *(const float4*)&As[k * 68 + ty * 4];
            float4 b0 = *(const float4*)&Bs[k * 136 + tx * 4];
            float4 b1 = *(const float4*)&Bs[k * 136 + 64 + tx * 4];
            float av[4] = {a.x, a.y, a.z, a.w};
            float bv[8] = {b0.x, b0.y, b0.z, b0.w, b1.x, b1.y, b1.z, b1.w};
#pragma unroll
            for (int r = 0; r < 4; r++)
#pragma unroll
                for (int c = 0; c < 8; c++) acc[r][c] += av[r] * bv[c];
        }
        __syncthreads();
    }
#pragma unroll
    for (int r = 0; r < 4; r++) {
        int m = m0 + ty * 4 + r;
        if (m >= M) continue;
#pragma unroll
        for (int half = 0; half < 2; half++) {
#pragma unroll
            for (int c = 0; c < 4; c++) {
                int h = half * 64 + tx * 4 + c;
                float v = acc[r][half * 4 + c] + bias[h];
                out[(size_t)m * HD + h] = fmaxf(v, 0.f);
            }
        }
    }
}

// ---------------------------------------------------------------------------
__global__ void __launch_bounds__(256)
linear_softmax_kernel(const float* __restrict__ A, const float* __restrict__ W,
                      const float* __restrict__ bias, float* __restrict__ out, int M)
{
    __shared__ float Ws[HD * NL];
    __shared__ float bs[NL];
    int tid = threadIdx.x;
    for (int i = tid; i < HD * NL; i += 256) Ws[i] = W[i];
    if (tid < NL) bs[tid] = bias[tid];
    __syncthreads();

    int warp = tid >> 5, lane = tid & 31;
    int m = blockIdx.x * 8 + warp;
    if (m >= M) return;

    float acc[NL];
#pragma unroll
    for (int h = 0; h < NL; h++) acc[h] = 0.f;
    for (int k = lane; k < HD; k += 32) {
        float x = A[(size_t)m * HD + k];
#pragma unroll
        for (int h = 0; h < NL; h++) acc[h] += x * Ws[k * NL + h];
    }
#pragma unroll
    for (int h = 0; h < NL; h++)
#pragma unroll
        for (int off = 16; off > 0; off >>= 1)
            acc[h] += __shfl_down_sync(0xFFFFFFFFu, acc[h], off);

    if (lane == 0) {
        float v[NL], mx = -1e30f;
#pragma unroll
        for (int h = 0; h < NL; h++) { v[h] = acc[h] + bs[h]; mx = fmaxf(mx, v[h]); }
        float s = 0.f;
#pragma unroll
        for (int h = 0; h < NL; h++) { v[h] = expf(v[h] - mx); s += v[h]; }
        float inv = 1.0f / s;
#pragma unroll
        for (int h = 0; h < NL; h++) out[(size_t)m * NL + h] = v[h] * inv;
    }
}

// ---------------------------------------------------------------------------
__global__ void __launch_bounds__(256)
rownorm_kernel(const float* __restrict__ A, float* __restrict__ out, int M, int D)
{
    int warp = threadIdx.x >> 5, lane = threadIdx.x & 31;
    int m = blockIdx.x * 8 + warp;
    if (m >= M) return;
    float s = 0.f;
    for (int k = lane; k < D; k += 32) { float v = A[(size_t)m * D + k]; s += v * v; }
#pragma unroll
    for (int off = 16; off > 0; off >>= 1) s += __shfl_down_sync(0xFFFFFFFFu, s, off);
    if (lane == 0) out[m] = s;
}

// ---------------------------------------------------------------------------
// SIMT fp32 distance GEMM (layer 4, D=8) + tile min.
// ---------------------------------------------------------------------------
__global__ void __launch_bounds__(256)
dist_kernel(const float* __restrict__ Q, const float* __restrict__ T,
            const float* __restrict__ qn, const float* __restrict__ tn,
            float* __restrict__ out, float* __restrict__ gmin, int D, int Ncols)
{
    __shared__ __align__(16) float As[16 * 68];
    __shared__ __align__(16) float Bs[16 * 136];
    __shared__ unsigned sMinU[64];
    const int tx = threadIdx.x, ty = threadIdx.y;
    const int tid = ty * 16 + tx;
    const int n0 = blockIdx.x * 128;
    const int m0 = blockIdx.y * 64;

    if (tid < 64) sMinU[tid] = 0x7F800000u;

    float acc[4][8];
#pragma unroll
    for (int r = 0; r < 4; r++)
#pragma unroll
        for (int c = 0; c < 8; c++) acc[r][c] = 0.f;

    const int nChunks = (D + 15) / 16;
    for (int ch = 0; ch < nChunks; ch++) {
        const int k0 = ch * 16;
#pragma unroll
        for (int i = 0; i < 4; i++) {
            int e = tid + i * 256;
            int k = e & 15, m = e >> 4;
            float v = (k0 + k < D) ? Q[(size_t)(m0 + m) * D + k0 + k] : 0.f;
            As[k * 68 + m] = v;
        }
#pragma unroll
        for (int i = 0; i < 8; i++) {
            int e = tid + i * 256;
            int k = e & 15, n = e >> 4;
            int gn = n0 + n;
            float v = 0.f;
            if (k0 + k < D && gn < Ncols) v = T[(size_t)gn * D + k0 + k];
            Bs[k * 136 + n] = v;
        }
        __syncthreads();
#pragma unroll
        for (int k = 0; k < 16; k++) {
            float4 a  = *(const float4*)&As[k * 68 + ty * 4];
            float4 b0 = *(const float4*)&Bs[k * 136 + tx * 4];
            float4 b1 = *(const float4*)&Bs[k * 136 + 64 + tx * 4];
            float av[4] = {a.x, a.y, a.z, a.w};
            float bv[8] = {b0.x, b0.y, b0.z, b0.w, b1.x, b1.y, b1.z, b1.w};
#pragma unroll
            for (int r = 0; r < 4; r++)
#pragma unroll
                for (int c = 0; c < 8; c++) acc[r][c] += av[r] * bv[c];
        }
        __syncthreads();
    }
    const float FINF = __int_as_float(0x7F800000);
#pragma unroll
    for (int r = 0; r < 4; r++) {
        int m = m0 + ty * 4 + r;
        float qv = qn[m];
        float lm = FINF;
#pragma unroll
        for (int half = 0; half < 2; half++) {
#pragma unroll
            for (int c = 0; c < 4; c++) {
                int n = n0 + half * 64 + tx * 4 + c;
                if (n < Ncols) {
                    float d = fmaxf(qv + tn[n] - 2.f * acc[r][half * 4 + c], 0.f);
                    out[(size_t)m * Ncols + n] = d;
                    lm = fminf(lm, d);
                }
            }
        }
        if (lm < FINF) atomicMin(&sMinU[ty * 4 + r], __float_as_uint(lm));
    }
    __syncthreads();
    if (tid < 64)
        gmin[(size_t)(m0 + tid) * NTILES + blockIdx.x] = __uint_as_float(sMinU[tid]);
}

// ---------------------------------------------------------------------------
__device__ __forceinline__ void find_kth(const unsigned* hist, int NB, unsigned kth,
                                         int tid, unsigned* s_bin, unsigned* s_kthr)
{
    if (tid < 32) {
        unsigned running = 0;
        for (int base = 0; base < NB; base += 32) {
            unsigned v = hist[base + tid];
            unsigned sc = v;
#pragma unroll
            for (int off = 1; off < 32; off <<= 1) {
                unsigned t = __shfl_up_sync(0xFFFFFFFFu, sc, off);
                if (tid >= off) sc += t;
            }
            unsigned tot = __shfl_sync(0xFFFFFFFFu, sc, 31);
            if (running + tot >= kth) {
                unsigned mask = __ballot_sync(0xFFFFFFFFu, running + sc >= kth);
                int l = __ffs(mask) - 1;
                if (tid == l) { *s_bin = (unsigned)(base + l); *s_kthr = kth - running - (sc - v); }
                break;
            }
            running += tot;
        }
    }
}

// ---------------------------------------------------------------------------
// Exact top-K select: tile-min threshold + tile-subset scan.
// ---------------------------------------------------------------------------
#define SEL_THREADS 512
#define SEL_CAP 2048
#define OFF_CAND  16384
#define OFF_SEL   (OFF_CAND + SEL_CAP * 8)
#define OFF_TIES  (OFF_SEL + 1024)
#define OFF_TLAB  (OFF_TIES + 1024)
#define OFF_MINS  (OFF_TLAB + 512)
#define OFF_TLIST (OFF_MINS + 392 * 4)
#define SEL_SMEM  (OFF_TLIST + 392 * 4)

__global__ void __launch_bounds__(SEL_THREADS)
select_kernel(const float* __restrict__ d2mat, const float* __restrict__ gmin,
              const int* __restrict__ labels, float* __restrict__ total, int init)
{
    extern __shared__ __align__(16) char sms[];
    unsigned* hist = (unsigned*)sms;
    u64* cand  = (u64*)(sms + OFF_CAND);
    u64* sel   = (u64*)(sms + OFF_SEL);
    u64* ties  = (u64*)(sms + OFF_TIES);
    int* tlab  = (int*)(sms + OFF_TLAB);
    float* mins = (float*)(sms + OFF_MINS);
    int* tlist = (int*)(sms + OFF_TLIST);

    __shared__ unsigned s_M75, s_bin, s_kthr, s_candcnt, s_selcnt, s_tiecnt, s_ntiles;
    __shared__ float s_w[80];
    __shared__ int s_lab[80];

    const int b = blockIdx.x, tid = threadIdx.x, lane = tid & 31;
    const uint4* usrc = (const uint4*)(d2mat + (size_t)b * NT);
    const int NH = NT / 4;

    for (int i = tid; i < NTILES; i += SEL_THREADS)
        mins[i] = gmin[(size_t)b * NTILES + i];
    if (tid == 0) { s_candcnt = 0; s_selcnt = 0; s_tiecnt = 0; s_ntiles = 0; }
    __syncthreads();

    if (tid < NTILES) {
        unsigned key = __float_as_uint(mins[tid]);
        int c = 0;
        for (int j = 0; j < NTILES; j++) {
            unsigned kj = __float_as_uint(mins[j]);
            c += (kj < key) || (kj == key && j < tid);
        }
        if (c == KNN - 1) s_M75 = key;
    }
    __syncthreads();
    const unsigned Mkey = s_M75;

    if (tid < NTILES) {
        if (__float_as_uint(mins[tid]) <= Mkey) {
            unsigned s = atomicAdd(&s_ntiles, 1u);
            tlist[s] = tid;
        }
    }
    __syncthreads();
    const int ntl = (int)s_ntiles;

    for (int w = tid; w < ntl * 32; w += SEL_THREADS) {
        int t = tlist[w >> 5];
        int i4 = t * 32 + (w & 31);
        if (i4 < NH) {
            uint4 a = usrc[i4];
            unsigned k[4] = {a.x, a.y, a.z, a.w};
#pragma unroll
            for (int j = 0; j < 4; j++) {
                if (k[j] <= Mkey) {
                    unsigned s = atomicAdd(&s_candcnt, 1u);
                    if (s < SEL_CAP) cand[s] = ((u64)k[j] << 32) | (unsigned)(i4 * 4 + j);
                }
            }
        }
    }
    __syncthreads();

    unsigned Tkey;
    const unsigned candTotal = s_candcnt;

    if (candTotal <= SEL_CAP) {
        const int cc = (int)candTotal;
        for (int i = tid; i < 4096; i += SEL_THREADS) hist[i] = 0;
        __syncthreads();
        for (int i = tid; i < cc; i += SEL_THREADS)
            atomicAdd(&hist[(unsigned)(cand[i] >> 52)], 1u);
        __syncthreads();
        find_kth(hist, 4096, KNN, tid, &s_bin, &s_kthr);
        __syncthreads();
        const unsigned pfx = s_bin;
        const unsigned k1v = s_kthr;
        for (int i = tid; i < 4096; i += SEL_THREADS) hist[i] = 0;
        __syncthreads();
        for (int i = tid; i < cc; i += SEL_THREADS) {
            unsigned key = (unsigned)(cand[i] >> 32);
            if ((key >> 20) == pfx) atomicAdd(&hist[(key >> 8) & 0xFFFu], 1u);
        }
        __syncthreads();
        find_kth(hist, 4096, k1v, tid, &s_bin, &s_kthr);
        __syncthreads();
        const unsigned pfx20 = (pfx << 12) | s_bin;
        const unsigned k2v = s_kthr;
        for (int i = tid; i < 256; i += SEL_THREADS) hist[i] = 0;
        __syncthreads();
        for (int i = tid; i < cc; i += SEL_THREADS) {
            unsigned key = (unsigned)(cand[i] >> 32);
            if ((key >> 8) == pfx20) atomicAdd(&hist[key & 0xFFu], 1u);
        }
        __syncthreads();
        find_kth(hist, 256, k2v, tid, &s_bin, &s_kthr);
        __syncthreads();
        Tkey = (pfx20 << 8) | s_bin;
        for (int i = tid; i < cc; i += SEL_THREADS) {
            u64 cv = cand[i];
            unsigned key = (unsigned)(cv >> 32);
            if (key < Tkey) {
                unsigned s = atomicAdd(&s_selcnt, 1u);
                if (s < 128) sel[s] = cv;
            } else if (key == Tkey) {
                unsigned s = atomicAdd(&s_tiecnt, 1u);
                if (s < 128) ties[s] = cv;
            }
        }
        __syncthreads();
    } else {
        // fallback (degenerate ties): radix over the tile subset.
        for (int i = tid; i < 4096; i += SEL_THREADS) hist[i] = 0;
        __syncthreads();
        for (int w = tid; w < ntl * 32; w += SEL_THREADS) {
            int t = tlist[w >> 5];
            int i4 = t * 32 + (w & 31);
            uint4 a = (i4 < NH) ? usrc[i4] : make_uint4(~0u, ~0u, ~0u, ~0u);
            unsigned k[4] = {a.x, a.y, a.z, a.w};
#pragma unroll
            for (int j = 0; j < 4; j++) {
                unsigned bin = (k[j] <= Mkey) ? (k[j] >> 20) : 0xFFFFFFFFu;
                unsigned grp = __match_any_sync(0xFFFFFFFFu, bin);
                if (bin != 0xFFFFFFFFu && lane == __ffs(grp) - 1)
                    atomicAdd(&hist[bin], (unsigned)__popc(grp));
            }
        }
        __syncthreads();
        find_kth(hist, 4096, KNN, tid, &s_bin, &s_kthr);
        __syncthreads();
        const unsigned pfx = s_bin;
        const unsigned k1v = s_kthr;

        for (int i = tid; i < 4096; i += SEL_THREADS) hist[i] = 0;
        __syncthreads();
        for (int w = tid; w < ntl * 32; w += SEL_THREADS) {
            int t = tlist[w >> 5];
            int i4 = t * 32 + (w & 31);
            uint4 a = (i4 < NH) ? usrc[i4] : make_uint4(~0u, ~0u, ~0u, ~0u);
            unsigned k[4] = {a.x, a.y, a.z, a.w};
#pragma unroll
            for (int j = 0; j < 4; j++) {
                unsigned bin = (k[j] <= Mkey && (k[j] >> 20) == pfx)
                               ? ((k[j] >> 8) & 0xFFFu) : 0xFFFFFFFFu;
                unsigned grp = __match_any_sync(0xFFFFFFFFu, bin);
                if (bin != 0xFFFFFFFFu && lane == __ffs(grp) - 1)
                    atomicAdd(&hist[bin], (unsigned)__popc(grp));
            }
        }
        __syncthreads();
        find_kth(hist, 4096, k1v, tid, &s_bin, &s_kthr);
        __syncthreads();
        const unsigned pfx20 = (pfx << 12) | s_bin;
        const unsigned k2v = s_kthr;

        for (int i = tid; i < 256; i += SEL_THREADS) hist[i] = 0;
        __syncthreads();
        for (int w = tid; w < ntl * 32; w += SEL_THREADS) {
            int t = tlist[w >> 5];
            int i4 = t * 32 + (w & 31);
            uint4 a = (i4 < NH) ? usrc[i4] : make_uint4(~0u, ~0u, ~0u, ~0u);
            unsigned k[4] = {a.x, a.y, a.z, a.w};
#pragma unroll
            for (int j = 0; j < 4; j++) {
                unsigned bin = (k[j] <= Mkey && (k[j] >> 8) == pfx20)
                               ? (k[j] & 0xFFu) : 0xFFFFFFFFu;
                unsigned grp = __match_any_sync(0xFFFFFFFFu, bin);
                if (bin != 0xFFFFFFFFu && lane == __ffs(grp) - 1)
                    atomicAdd(&hist[bin], (unsigned)__popc(grp));
            }
        }
        __syncthreads();
        find_kth(hist, 256, k2v, tid, &s_bin, &s_kthr);
        __syncthreads();
        Tkey = (pfx20 << 8) | s_bin;

        for (int w = tid; w < ntl * 32; w += SEL_THREADS) {
            int t = tlist[w >> 5];
            int i4 = t * 32 + (w & 31);
            if (i4 < NH) {
                uint4 a = usrc[i4];
                unsigned k[4] = {a.x, a.y, a.z, a.w};
#pragma unroll
                for (int j = 0; j < 4; j++) {
                    if (k[j] < Tkey) {
                        unsigned s = atomicAdd(&s_selcnt, 1u);
                        if (s < 128) sel[s] = ((u64)k[j] << 32) | (unsigned)(i4 * 4 + j);
                    } else if (k[j] == Tkey) {
                        unsigned s = atomicAdd(&s_tiecnt, 1u);
                        if (s < 128) ties[s] = ((u64)k[j] << 32) | (unsigned)(i4 * 4 + j);
                    }
                }
            }
        }
        __syncthreads();
    }

    const int ns = min((int)s_selcnt, 128);
    const int ne = min((int)s_tiecnt, 128);

    if (tid < ns) {
        u64 mine = sel[tid];
        unsigned my_idx = (unsigned)(mine & 0xFFFFFFFFu);
        int rank = 0;
        for (int j = 0; j < ns; j++) rank += ((unsigned)(sel[j] & 0xFFFFFFFFu) < my_idx);
        float d2 = __uint_as_float((unsigned)(mine >> 32));
        s_w[rank] = (d2 > 0.f) ? __fdiv_rn(1.0f, __fsqrt_rn(d2)) : 0.f;
        s_lab[rank] = labels[my_idx];
    }
    if (tid >= 128 && tid - 128 < ne) {
        int t = tid - 128;
        unsigned my_idx = (unsigned)(ties[t] & 0xFFFFFFFFu);
        int rank = 0;
        for (int j = 0; j < ne; j++) rank += ((unsigned)(ties[j] & 0xFFFFFFFFu) < my_idx);
        tlab[rank] = labels[my_idx];
    }
    __syncthreads();

    if (tid == 0) {
        float cls[NL];
#pragma unroll
        for (int l = 0; l < NL; l++) cls[l] = 0.f;
        float stot = 0.f;
        for (int j = 0; j < ns; j++) { stot += s_w[j]; cls[s_lab[j]] += s_w[j]; }
        int need = KNN - ns;
        float d2T = __uint_as_float(Tkey);
        float wT = (d2T > 0.f) ? __fdiv_rn(1.0f, __fsqrt_rn(d2T)) : 0.f;
        int m = (need < ne) ? need : ne;
        for (int j = 0; j < m; j++) { stot += wT; cls[tlab[j]] += wT; }
#pragma unroll
        for (int l = 0; l < NL; l++) {
            float val = stot - cls[l];
            size_t o = (size_t)b * NL + l;
            if (init) total[o] = val; else total[o] += val;
        }
    }
}

// ---------------------------------------------------------------------------
__global__ void __launch_bounds__(256)
pvalue_kernel(const float* __restrict__ total, const float* __restrict__ cali,
              float* __restrict__ out)
{
    const int b = blockIdx.x, tid = threadIdx.x;
    float t[NL];
#pragma unroll
    for (int l = 0; l < NL; l++) t[l] = total[(size_t)b * NL + l];
    int cnt[NL];
#pragma unroll
    for (int l = 0; l < NL; l++) cnt[l] = 0;
    for (int i = tid; i < NC; i += 256) {
        float c = cali[i];
#pragma unroll
        for (int l = 0; l < NL; l++) cnt[l] += (c >= t[l]) ? 1 : 0;
    }
    __shared__ int sc[NL];
    if (tid < NL) sc[tid] = 0;
    __syncthreads();
#pragma unroll
    for (int l = 0; l < NL; l++) atomicAdd(&sc[l], cnt[l]);
    __syncthreads();
    if (tid < NL) out[(size_t)b * NL + tid] = (float)sc[tid] * (1.0f / NC);
}

// ---------------------------------------------------------------------------
extern "C" void kernel_launch(void* const* d_in, const int* in_sizes, int n_in,
                              void* d_out, int out_size)
{
    const float* x        = (const float*)d_in[0];
    const float* train_x  = (const float*)d_in[1];
    const int*   lab      = (const int*)  d_in[2];
    const float* cali     = (const float*)d_in[3];
    const float* W1 = (const float*)d_in[4];  const float* b1 = (const float*)d_in[5];
    const float* W2 = (const float*)d_in[6];  const float* b2 = (const float*)d_in[7];
    const float* W3 = (const float*)d_in[8];  const float* b3 = (const float*)d_in[9];
    const float* W4 = (const float*)d_in[10]; const float* b4 = (const float*)d_in[11];
    float* out = (float*)d_out;

    float *h1p, *h2p, *h3p, *q4p, *t3p, *t4p, *d2p, *qnp, *tnp, *totp, *minp;
    __nv_bfloat16 *qhip, *qlop, *thip, *tlop, *thi2p, *tlo2p;
    __nv_bfloat16 *w1th, *w1tl, *w2th, *w2tl, *w3th, *w3tl;
    cudaGetSymbolAddress((void**)&h1p, g_h1);
    cudaGetSymbolAddress((void**)&h2p, g_h2);
    cudaGetSymbolAddress((void**)&h3p, g_h3);
    cudaGetSymbolAddress((void**)&q4p, g_q4);
    cudaGetSymbolAddress((void**)&t3p, g_t3);
    cudaGetSymbolAddress((void**)&t4p, g_t4);
    cudaGetSymbolAddress((void**)&d2p, g_d2);
    cudaGetSymbolAddress((void**)&minp, g_min);
    cudaGetSymbolAddress((void**)&qnp, g_qn);
    cudaGetSymbolAddress((void**)&tnp, g_tn);
    cudaGetSymbolAddress((void**)&totp, g_tot);
    cudaGetSymbolAddress((void**)&qhip, g_qhi);
    cudaGetSymbolAddress((void**)&qlop, g_qlo);
    cudaGetSymbolAddress((void**)&thip, g_thi);
    cudaGetSymbolAddress((void**)&tlop, g_tlo);
    cudaGetSymbolAddress((void**)&thi2p, g_thi2);
    cudaGetSymbolAddress((void**)&tlo2p, g_tlo2);
    cudaGetSymbolAddress((void**)&w1th, g_w1th);
    cudaGetSymbolAddress((void**)&w1tl, g_w1tl);
    cudaGetSymbolAddress((void**)&w2th, g_w2th);
    cudaGetSymbolAddress((void**)&w2tl, g_w2tl);
    cudaGetSymbolAddress((void**)&w3th, g_w3th);
    cudaGetSymbolAddress((void**)&w3tl, g_w3tl);

    cudaFuncSetAttribute(select_kernel,
                         cudaFuncAttributeMaxDynamicSharedMemorySize, SEL_SMEM);
    cudaFuncSetAttribute(mma_dist_kernel,
                         cudaFuncAttributeMaxDynamicSharedMemorySize, MD_SMEM);

    dim3 tb(16, 16);
    const int D0 = 83;
    const dim3 mgrid(NTILES, BQ / 256);

    conv_norm_kernel<<<BQ / 8, 256>>>(x, qhip, qlop, qnp, BQ, D0);
    conv_norm_kernel<<<NTP / 8, 256>>>(train_x, thip, tlop, tnp, NT, D0);
    wt_convert_kernel<<<(3 * 128 * 128 + 255) / 256, 256>>>(W1, W2, W3);

    // layer 0 (mma_dist = launch #4 -> profiled)
    mma_dist_kernel<<<mgrid, 512, MD_SMEM>>>(qhip, qlop, thip, tlop, qnp, tnp, d2p, minp, 6);
    select_kernel<<<BQ, SEL_THREADS, SEL_SMEM>>>(d2p, minp, lab, totp, 1);

    // query-side MLP (tiny SIMT)
    linear_relu_kernel<<<BQ / 64, tb>>>(x,   W1, b1, h1p, BQ, D0);
    linear_relu_kernel<<<BQ / 64, tb>>>(h1p, W2, b2, h2p, BQ, HD);
    linear_relu_kernel<<<BQ / 64, tb>>>(h2p, W3, b3, h3p, BQ, HD);
    linear_softmax_kernel<<<(BQ + 7) / 8, 256>>>(h3p, W4, b4, q4p, BQ);

    // layer 1
    mma_linear_kernel<<<NTILES, 256>>>(thip, tlop, w1th, w1tl, b1,
                                       thi2p, tlo2p, tnp, (float*)0, 6);
    conv_norm_kernel<<<BQ / 8, 256>>>(h1p, qhip, qlop, qnp, BQ, HD);
    mma_dist_kernel<<<mgrid, 512, MD_SMEM>>>(qhip, qlop, thi2p, tlo2p, qnp, tnp, d2p, minp, 8);
    select_kernel<<<BQ, SEL_THREADS, SEL_SMEM>>>(d2p, minp, lab, totp, 0);

    // layer 2
    mma_linear_kernel<<<NTILES, 256>>>(thi2p, tlo2p, w2th, w2tl, b2,
                                       thip, tlop, tnp, (float*)0, 8);
    conv_norm_kernel<<<BQ / 8, 256>>>(h2p, qhip, qlop, qnp, BQ, HD);
    mma_dist_kernel<<<mgrid, 512, MD_SMEM>>>(qhip, qlop, thip, tlop, qnp, tnp, d2p, minp, 8);
    select_kernel<<<BQ, SEL_THREADS, SEL_SMEM>>>(d2p, minp, lab, totp, 0);

    // layer 3 (+ fp32 t3 for softmax)
    mma_linear_kernel<<<NTILES, 256>>>(thip, tlop, w3th, w3tl, b3,
                                       thi2p, tlo2p, tnp, t3p, 8);
    conv_norm_kernel<<<BQ / 8, 256>>>(h3p, qhip, qlop, qnp, BQ, HD);
    mma_dist_kernel<<<mgrid, 512, MD_SMEM>>>(qhip, qlop, thi2p, tlo2p, qnp, tnp, d2p, minp, 8);
    select_kernel<<<BQ, SEL_THREADS, SEL_SMEM>>>(d2p, minp, lab, totp, 0);

    // layer 4 (softmax features, D=8): exact fp32 path
    linear_softmax_kernel<<<(NT + 7) / 8, 256>>>(t3p, W4, b4, t4p, NT);
    rownorm_kernel<<<(BQ + 7) / 8, 256>>>(q4p, qnp, BQ, NL);
    rownorm_kernel<<<(NT + 7) / 8, 256>>>(t4p, tnp, NT, NL);
    dist_kernel<<<dim3(NTILES, BQ / 64), tb>>>(q4p, t4p, qnp, tnp, d2p, minp, NL, NT);
    select_kernel<<<BQ, SEL_THREADS, SEL_SMEM>>>(d2p, minp, lab, totp, 0);

    pvalue_kernel<<<BQ, 256>>>(totp, cali, out);
}

// round 13
// speedup vs baseline: 1.0904x; 1.0008x over previous
#include <cuda_runtime.h>
#include <cuda_bf16.h>
#include <math.h>
#include <stdint.h>

#define BQ   1024
#define NT   50000
#define NTP  50048
#define NL   8
#define KNN  75
#define HD   128
#define NC   10000
#define NTILES 391          // NTP/128

typedef unsigned long long u64;

// ---------------- device scratch ----------------
__device__ float g_h1[BQ * HD];
__device__ float g_h2[BQ * HD];
__device__ float g_h3[BQ * HD];
__device__ float g_q4[BQ * NL];
__device__ float g_t3[(size_t)NT * HD];
__device__ float g_t4[(size_t)NT * NL];
__device__ float g_d2[(size_t)BQ * NT];
__device__ float g_min[(size_t)BQ * NTILES];
__device__ float g_qn[BQ];
__device__ float g_tn[NT];
__device__ float g_tot[BQ * NL];
__device__ __nv_bfloat16 g_qhi[(size_t)BQ * 128];
__device__ __nv_bfloat16 g_qlo[(size_t)BQ * 128];
__device__ __nv_bfloat16 g_thi[(size_t)NTP * 128];    // bank A
__device__ __nv_bfloat16 g_tlo[(size_t)NTP * 128];
__device__ __nv_bfloat16 g_thi2[(size_t)NTP * 128];   // bank B
__device__ __nv_bfloat16 g_tlo2[(size_t)NTP * 128];
__device__ __nv_bfloat16 g_w1th[128 * 128], g_w1tl[128 * 128];
__device__ __nv_bfloat16 g_w2th[128 * 128], g_w2tl[128 * 128];
__device__ __nv_bfloat16 g_w3th[128 * 128], g_w3tl[128 * 128];

// ---------------------------------------------------------------------------
__device__ __forceinline__ void mma_bf16(float* d, const uint32_t* a, const uint32_t* b)
{
    asm volatile(
        "mma.sync.aligned.m16n8k16.row.col.f32.bf16.bf16.f32 "
        "{%0,%1,%2,%3}, {%4,%5,%6,%7}, {%8,%9}, {%0,%1,%2,%3};"
        : "+f"(d[0]), "+f"(d[1]), "+f"(d[2]), "+f"(d[3])
        : "r"(a[0]), "r"(a[1]), "r"(a[2]), "r"(a[3]), "r"(b[0]), "r"(b[1]));
}

#define LDSM4(r, a) \
    asm volatile("ldmatrix.sync.aligned.m8n8.x4.shared.b16 {%0,%1,%2,%3}, [%4];" \
        : "=r"((r)[0]), "=r"((r)[1]), "=r"((r)[2]), "=r"((r)[3]) : "r"(a))

#define SLICE_ELEMS (128 * 24)

__device__ __forceinline__ void slice_load_async(
    const __nv_bfloat16* __restrict__ Gp, __nv_bfloat16* Ss,
    int row0, int k0, int lr, int lh)
{
    uint32_t sa = (uint32_t)__cvta_generic_to_shared(Ss + lr * 24 + lh * 8);
    const void* ga = Gp + (size_t)(row0 + lr) * 128 + k0 + lh * 8;
    asm volatile("cp.async.cg.shared.global [%0], [%1], 16;\n" :: "r"(sa), "l"(ga));
}

// Per-chunk MMA body: ldmatrix fragment loads (12 LDSM vs 48 LDS), then the
// 3-pass schedule hh / lh / hl. Same values, same per-acc order -> bit-identical.
// AhA/AlA: A slice base + lane A-offset; BhA/BlA: B slice base + lane B-offset.
// mt step = 16 rows * 48 B = 768 B; nt-pair step = 768 B.
__device__ __forceinline__ void chunk_mma(
    uint32_t AhA, uint32_t AlA, uint32_t BhA, uint32_t BlA, float acc[2][8][4])
{
    uint32_t ah[2][4], bh[8][2];
    LDSM4(ah[0], AhA);
    LDSM4(ah[1], AhA + 768);
#pragma unroll
    for (int p = 0; p < 4; p++) {
        uint32_t bb[4];
        LDSM4(bb, BhA + p * 768);
        bh[2 * p][0] = bb[0]; bh[2 * p][1] = bb[1];
        bh[2 * p + 1][0] = bb[2]; bh[2 * p + 1][1] = bb[3];
    }
    // pass A: hi*hi
#pragma unroll
    for (int nt = 0; nt < 8; nt++) {
        mma_bf16(acc[0][nt], ah[0], bh[nt]);
        mma_bf16(acc[1][nt], ah[1], bh[nt]);
    }
    // pass B: lo*hi
    uint32_t al[2][4];
    LDSM4(al[0], AlA);
    LDSM4(al[1], AlA + 768);
#pragma unroll
    for (int nt = 0; nt < 8; nt++) {
        mma_bf16(acc[0][nt], al[0], bh[nt]);
        mma_bf16(acc[1][nt], al[1], bh[nt]);
    }
    // pass C: hi*lo
    uint32_t bl[8][2];
#pragma unroll
    for (int p = 0; p < 4; p++) {
        uint32_t bb[4];
        LDSM4(bb, BlA + p * 768);
        bl[2 * p][0] = bb[0]; bl[2 * p][1] = bb[1];
        bl[2 * p + 1][0] = bb[2]; bl[2 * p + 1][1] = bb[3];
    }
#pragma unroll
    for (int nt = 0; nt < 8; nt++) {
        mma_bf16(acc[0][nt], ah[0], bl[nt]);
        mma_bf16(acc[1][nt], ah[1], bl[nt]);
    }
}

// lane offsets (bytes) into a slice for ldmatrix addressing
__device__ __forceinline__ uint32_t a_lane_off(int wm, int lane)
{
    return (uint32_t)(((wm + (lane & 15)) * 24 + ((lane >> 4) & 1) * 8) * 2);
}
__device__ __forceinline__ uint32_t b_lane_off(int wn, int lane)
{
    return (uint32_t)(((wn + (lane & 7) + ((lane >> 4) & 1) * 8) * 24
                       + ((lane >> 3) & 1) * 8) * 2);
}

// ---------------------------------------------------------------------------
__global__ void __launch_bounds__(256)
conv_norm_kernel(const float* __restrict__ A, __nv_bfloat16* __restrict__ hi,
                 __nv_bfloat16* __restrict__ lo, float* __restrict__ nrm,
                 int Mreal, int D)
{
    int warp = threadIdx.x >> 5, lane = threadIdx.x & 31;
    int row = blockIdx.x * 8 + warp;
    int base = lane * 4;

    float ss = 0.f;
    __nv_bfloat16 hb[4], lb[4];
#pragma unroll
    for (int j = 0; j < 4; j++) {
        int col = base + j;
        float v = (row < Mreal && col < D) ? A[(size_t)row * D + col] : 0.f;
        ss += v * v;
        hb[j] = __float2bfloat16_rn(v);
        lb[j] = __float2bfloat16_rn(v - __bfloat162float(hb[j]));
    }
    __nv_bfloat162 h01, h23, l01, l23;
    h01.x = hb[0]; h01.y = hb[1]; h23.x = hb[2]; h23.y = hb[3];
    l01.x = lb[0]; l01.y = lb[1]; l23.x = lb[2]; l23.y = lb[3];
    *(__nv_bfloat162*)&hi[(size_t)row * 128 + base]     = h01;
    *(__nv_bfloat162*)&hi[(size_t)row * 128 + base + 2] = h23;
    *(__nv_bfloat162*)&lo[(size_t)row * 128 + base]     = l01;
    *(__nv_bfloat162*)&lo[(size_t)row * 128 + base + 2] = l23;

#pragma unroll
    for (int off = 16; off > 0; off >>= 1) ss += __shfl_down_sync(0xFFFFFFFFu, ss, off);
    if (lane == 0 && row < Mreal) nrm[row] = ss;
}

// ---------------------------------------------------------------------------
__global__ void __launch_bounds__(256)
wt_convert_kernel(const float* __restrict__ W1, const float* __restrict__ W2,
                  const float* __restrict__ W3)
{
    int idx = blockIdx.x * 256 + threadIdx.x;
    if (idx >= 3 * 128 * 128) return;
    int which = idx >> 14;
    int e = idx & 16383;
    int n = e & 127, k = e >> 7;
    const float* W = (which == 0) ? W1 : (which == 1) ? W2 : W3;
    int K = (which == 0) ? 83 : 128;
    float v = (k < K) ? W[(size_t)k * 128 + n] : 0.f;
    __nv_bfloat16 h = __float2bfloat16_rn(v);
    __nv_bfloat16 l = __float2bfloat16_rn(v - __bfloat162float(h));
    __nv_bfloat16* dh = (which == 0) ? g_w1th : (which == 1) ? g_w2th : g_w3th;
    __nv_bfloat16* dl = (which == 0) ? g_w1tl : (which == 1) ? g_w2tl : g_w3tl;
    dh[e] = h;
    dl[e] = l;
}

// ---------------------------------------------------------------------------
// bf16x3 GEMM mainloop (128-row tiles, 2-buffer) - used by mma_linear_kernel.
// ---------------------------------------------------------------------------
__device__ __forceinline__ void gemm3_mainloop(
    const __nv_bfloat16* Ahi, const __nv_bfloat16* Alo,
    const __nv_bfloat16* Bhi, const __nv_bfloat16* Blo,
    __nv_bfloat16* smem, int m0, int n0, int nCh,
    int wm, int wn, int lane, int lr, int lh,
    float acc[2][8][4])
{
    __nv_bfloat16* AhiS[2] = {smem,                   smem + 4 * SLICE_ELEMS};
    __nv_bfloat16* AloS[2] = {smem + 1 * SLICE_ELEMS, smem + 5 * SLICE_ELEMS};
    __nv_bfloat16* BhiS[2] = {smem + 2 * SLICE_ELEMS, smem + 6 * SLICE_ELEMS};
    __nv_bfloat16* BloS[2] = {smem + 3 * SLICE_ELEMS, smem + 7 * SLICE_ELEMS};

    const uint32_t sbase = (uint32_t)__cvta_generic_to_shared(smem);
    const uint32_t aoff = a_lane_off(wm, lane);
    const uint32_t boff = b_lane_off(wn, lane);

    slice_load_async(Ahi, AhiS[0], m0, 0, lr, lh);
    slice_load_async(Alo, AloS[0], m0, 0, lr, lh);
    slice_load_async(Bhi, BhiS[0], n0, 0, lr, lh);
    slice_load_async(Blo, BloS[0], n0, 0, lr, lh);
    asm volatile("cp.async.commit_group;\n" ::: "memory");

    for (int c = 0; c < nCh; c++) {
        int buf = c & 1;
        if (c + 1 < nCh) {
            int k0 = (c + 1) * 16;
            slice_load_async(Ahi, AhiS[buf ^ 1], m0, k0, lr, lh);
            slice_load_async(Alo, AloS[buf ^ 1], m0, k0, lr, lh);
            slice_load_async(Bhi, BhiS[buf ^ 1], n0, k0, lr, lh);
            slice_load_async(Blo, BloS[buf ^ 1], n0, k0, lr, lh);
            asm volatile("cp.async.commit_group;\n" ::: "memory");
            asm volatile("cp.async.wait_group 1;" ::: "memory");
        } else {
            asm volatile("cp.async.wait_group 0;" ::: "memory");
        }
        __syncthreads();

        const uint32_t bufB = sbase + (uint32_t)(buf * 4 * SLICE_ELEMS * 2);
        chunk_mma(bufB + aoff,
                  bufB + (uint32_t)(1 * SLICE_ELEMS * 2) + aoff,
                  bufB + (uint32_t)(2 * SLICE_ELEMS * 2) + boff,
                  bufB + (uint32_t)(3 * SLICE_ELEMS * 2) + boff,
                  acc);
        __syncthreads();
    }
}

// ---------------------------------------------------------------------------
// 256x128 distance GEMM, 512 threads, 3-stage pipeline, 1 sync per chunk.
// ---------------------------------------------------------------------------
#define ASL (256 * 24)          // A slice elems
#define BSL (128 * 24)          // B slice elems
#define STAGE_ELEMS (2 * ASL + 2 * BSL)   // 18432 elems
#define MD_SMEM (3 * STAGE_ELEMS * 2)     // 110592 bytes

__global__ void __launch_bounds__(512, 1)
mma_dist_kernel(const __nv_bfloat16* __restrict__ Qhi, const __nv_bfloat16* __restrict__ Qlo,
                const __nv_bfloat16* __restrict__ Thi, const __nv_bfloat16* __restrict__ Tlo,
                const float* __restrict__ qn, const float* __restrict__ tn,
                float* __restrict__ out, float* __restrict__ gmin, int nCh)
{
    extern __shared__ __align__(16) __nv_bfloat16 dsm[];
    __shared__ float sMin[256][2];
    const int tid = threadIdx.x;
    const int wid = tid >> 5, lane = tid & 31;
    const int n0 = blockIdx.x * 128;
    const int m0 = blockIdx.y * 256;
    const int wm = (wid & 7) * 32;          // 8 m-blocks
    const int wn = (wid >> 3) * 64;         // 2 n-halves
    const int fr = lane >> 2, fc = (lane & 3) * 2;
    const int ar = tid >> 1, ah2 = tid & 1;             // A loader: 256 rows x 2
    const int br = (tid & 255) >> 1, bh2 = tid & 1;     // B loader: 128 rows x 2

    const uint32_t sbase = (uint32_t)__cvta_generic_to_shared(dsm);
    const uint32_t aoff = a_lane_off(wm, lane);
    const uint32_t boff = b_lane_off(wn, lane);

    float acc[2][8][4];
#pragma unroll
    for (int mt = 0; mt < 2; mt++)
#pragma unroll
        for (int nt = 0; nt < 8; nt++)
#pragma unroll
            for (int j = 0; j < 4; j++) acc[mt][nt][j] = 0.f;

#define LOAD_STAGE(s, k0) do {                                                  \
        __nv_bfloat16* sb_ = dsm + (s) * STAGE_ELEMS;                           \
        slice_load_async(Qhi, sb_,            m0, (k0), ar, ah2);               \
        slice_load_async(Qlo, sb_ + ASL,      m0, (k0), ar, ah2);               \
        if (tid < 256) slice_load_async(Thi, sb_ + 2 * ASL,      n0, (k0), br, bh2); \
        else           slice_load_async(Tlo, sb_ + 2 * ASL + BSL, n0, (k0), br, bh2); \
        asm volatile("cp.async.commit_group;\n" ::: "memory");                  \
    } while (0)

    LOAD_STAGE(0, 0);
    if (nCh > 1) LOAD_STAGE(1, 16);

    for (int c = 0; c < nCh; c++) {
        if (c + 1 < nCh) asm volatile("cp.async.wait_group 1;" ::: "memory");
        else             asm volatile("cp.async.wait_group 0;" ::: "memory");
        __syncthreads();
        if (c + 2 < nCh) LOAD_STAGE((c + 2) % 3, (c + 2) * 16);

        const uint32_t stB = sbase + (uint32_t)((c % 3) * STAGE_ELEMS * 2);
        chunk_mma(stB + aoff,
                  stB + (uint32_t)(ASL * 2) + aoff,
                  stB + (uint32_t)(2 * ASL * 2) + boff,
                  stB + (uint32_t)(2 * ASL * 2 + BSL * 2) + boff,
                  acc);
    }
#undef LOAD_STAGE

    const float FINF = __int_as_float(0x7F800000);
    float rmin[2][2] = {{FINF, FINF}, {FINF, FINF}};
#pragma unroll
    for (int mt = 0; mt < 2; mt++) {
        int mrow = m0 + wm + mt * 16 + fr;
        float q0 = qn[mrow], q1 = qn[mrow + 8];
#pragma unroll
        for (int nt = 0; nt < 8; nt++) {
            int n = n0 + wn + nt * 8 + fc;
            if (n < NT) {
                float t0 = tn[n], t1 = tn[n + 1];
                float2 o;
                o.x = fmaxf(q0 + t0 - 2.f * acc[mt][nt][0], 0.f);
                o.y = fmaxf(q0 + t1 - 2.f * acc[mt][nt][1], 0.f);
                *(float2*)&out[(size_t)mrow * NT + n] = o;
                rmin[mt][0] = fminf(rmin[mt][0], fminf(o.x, o.y));
                o.x = fmaxf(q1 + t0 - 2.f * acc[mt][nt][2], 0.f);
                o.y = fmaxf(q1 + t1 - 2.f * acc[mt][nt][3], 0.f);
                *(float2*)&out[(size_t)(mrow + 8) * NT + n] = o;
                rmin[mt][1] = fminf(rmin[mt][1], fminf(o.x, o.y));
            }
        }
    }
    __syncthreads();
#pragma unroll
    for (int mt = 0; mt < 2; mt++)
#pragma unroll
        for (int rr = 0; rr < 2; rr++) {
            float m = rmin[mt][rr];
            m = fminf(m, __shfl_xor_sync(0xFFFFFFFFu, m, 1));
            m = fminf(m, __shfl_xor_sync(0xFFFFFFFFu, m, 2));
            if ((lane & 3) == 0)
                sMin[wm + mt * 16 + rr * 8 + fr][wn >> 6] = m;
        }
    __syncthreads();
    if (tid < 256)
        gmin[(size_t)(m0 + tid) * NTILES + blockIdx.x] =
            fminf(sMin[tid][0], sMin[tid][1]);
}

// ---------------------------------------------------------------------------
__global__ void __launch_bounds__(256, 2)
mma_linear_kernel(const __nv_bfloat16* __restrict__ Ahi, const __nv_bfloat16* __restrict__ Alo,
                  const __nv_bfloat16* __restrict__ Wth, const __nv_bfloat16* __restrict__ Wtl,
                  const float* __restrict__ bias,
                  __nv_bfloat16* __restrict__ Ohi, __nv_bfloat16* __restrict__ Olo,
                  float* __restrict__ nrm, float* __restrict__ Ofp, int nCh)
{
    __shared__ __align__(16) __nv_bfloat16 smem[8 * SLICE_ELEMS];
    __shared__ float snorm[128];
    __shared__ float sbias[128];
    const int tid = threadIdx.x;
    const int wid = tid >> 5, lane = tid & 31;
    const int m0 = blockIdx.x * 128;
    const int wm = (wid & 3) * 32;
    const int wn = (wid >> 2) * 64;
    const int lr = tid >> 1, lh = tid & 1;
    const int fr = lane >> 2, fc = (lane & 3) * 2;

    if (tid < 128) { sbias[tid] = bias[tid]; snorm[tid] = 0.f; }

    float acc[2][8][4];
#pragma unroll
    for (int mt = 0; mt < 2; mt++)
#pragma unroll
        for (int nt = 0; nt < 8; nt++)
#pragma unroll
            for (int j = 0; j < 4; j++) acc[mt][nt][j] = 0.f;

    gemm3_mainloop(Ahi, Alo, Wth, Wtl, smem, m0, 0, nCh,
                   wm, wn, lane, lr, lh, acc);

#pragma unroll
    for (int mt = 0; mt < 2; mt++) {
        int r0 = wm + mt * 16 + fr;
        int r1 = r0 + 8;
        size_t g0 = (size_t)(m0 + r0) * 128;
        size_t g1 = (size_t)(m0 + r1) * 128;
        float ns0 = 0.f, ns1 = 0.f;
#pragma unroll
        for (int nt = 0; nt < 8; nt++) {
            int n = wn + nt * 8 + fc;
            float b0 = sbias[n], b1 = sbias[n + 1];
            float v00 = fmaxf(acc[mt][nt][0] + b0, 0.f);
            float v01 = fmaxf(acc[mt][nt][1] + b1, 0.f);
            float v10 = fmaxf(acc[mt][nt][2] + b0, 0.f);
            float v11 = fmaxf(acc[mt][nt][3] + b1, 0.f);
            ns0 += v00 * v00 + v01 * v01;
            ns1 += v10 * v10 + v11 * v11;
            __nv_bfloat162 h, l;
            h.x = __float2bfloat16_rn(v00);
            h.y = __float2bfloat16_rn(v01);
            l.x = __float2bfloat16_rn(v00 - __bfloat162float(h.x));
            l.y = __float2bfloat16_rn(v01 - __bfloat162float(h.y));
            *(__nv_bfloat162*)&Ohi[g0 + n] = h;
            *(__nv_bfloat162*)&Olo[g0 + n] = l;
            h.x = __float2bfloat16_rn(v10);
            h.y = __float2bfloat16_rn(v11);
            l.x = __float2bfloat16_rn(v10 - __bfloat162float(h.x));
            l.y = __float2bfloat16_rn(v11 - __bfloat162float(h.y));
            *(__nv_bfloat162*)&Ohi[g1 + n] = h;
            *(__nv_bfloat162*)&Olo[g1 + n] = l;
            if (Ofp) {
                *(float2*)&Ofp[g0 + n] = make_float2(v00, v01);
                *(float2*)&Ofp[g1 + n] = make_float2(v10, v11);
            }
        }
        atomicAdd(&snorm[r0], ns0);
        atomicAdd(&snorm[r1], ns1);
    }
    __syncthreads();
    if (tid < 128 && m0 + tid < NT) nrm[m0 + tid] = snorm[tid];
}

// ---------------------------------------------------------------------------
__global__ void __launch_bounds__(256)
linear_relu_kernel(const float* __restrict__ A, const float* __restrict__ W,
                   const float* __restrict__ bias, float* __restrict__ out,
                   int M, int K)
{
    __shared__ __align__(16) float As[16 * 68];
    __shared__ __align__(16) float Bs[16 * 136];
    const int tx = threadIdx.x, ty = threadIdx.y;
    const int tid = ty * 16 + tx;
    const int m0 = blockIdx.x * 64;

    float acc[4][8];
#pragma unroll
    for (int r = 0; r < 4; r++)
#pragma unroll
        for (int c = 0; c < 8; c++) acc[r][c] = 0.f;

    const int nChunks = (K + 15) / 16;
    for (int ch = 0; ch < nChunks; ch++) {
        const int k0 = ch * 16;
#pragma unroll
        for (int i = 0; i < 4; i++) {
            int e = tid + i * 256;
            int k = e & 15, m = e >> 4;
            float v = 0.f;
            if (k0 + k < K && m0 + m < M) v = A[(size_t)(m0 + m) * K + k0 + k];
            As[k * 68 + m] = v;
        }
#pragma unroll
        for (int i = 0; i < 8; i++) {
            int e = tid + i * 256;
            int h = e & 127, k = e >> 7;
            float v = 0.f;
            if (k0 + k < K) v = W[(size_t)(k0 + k) * HD + h];
            Bs[k * 136 + h] = v;
        }
        __syncthreads();
#pragma unroll
        for (int k = 0; k < 16; k++) {
            float4 a  = *(const float4*)&As[k * 68 + ty * 4];
            float4 b0 = *(const float4*)&Bs[k * 136 + tx * 4];
            float4 b1 = *(const float4*)&Bs[k * 136 + 64 + tx * 4];
            float av[4] = {a.x, a.y, a.z, a.w};
            float bv[8] = {b0.x, b0.y, b0.z, b0.w, b1.x, b1.y, b1.z, b1.w};
#pragma unroll
            for (int r = 0; r < 4; r++)
#pragma unroll
                for (int c = 0; c < 8; c++) acc[r][c] += av[r] * bv[c];
        }
        __syncthreads();
    }
#pragma unroll
    for (int r = 0; r < 4; r++) {
        int m = m0 + ty * 4 + r;
        if (m >= M) continue;
#pragma unroll
        for (int half = 0; half < 2; half++) {
#pragma unroll
            for (int c = 0; c < 4; c++) {
                int h = half * 64 + tx * 4 + c;
                float v = acc[r][half * 4 + c] + bias[h];
                out[(size_t)m * HD + h] = fmaxf(v, 0.f);
            }
        }
    }
}

// ---------------------------------------------------------------------------
__global__ void __launch_bounds__(256)
linear_softmax_kernel(const float* __restrict__ A, const float* __restrict__ W,
                      const float* __restrict__ bias, float* __restrict__ out, int M)
{
    __shared__ float Ws[HD * NL];
    __shared__ float bs[NL];
    int tid = threadIdx.x;
    for (int i = tid; i < HD * NL; i += 256) Ws[i] = W[i];
    if (tid < NL) bs[tid] = bias[tid];
    __syncthreads();

    int warp = tid >> 5, lane = tid & 31;
    int m = blockIdx.x * 8 + warp;
    if (m >= M) return;

    float acc[NL];
#pragma unroll
    for (int h = 0; h < NL; h++) acc[h] = 0.f;
    for (int k = lane; k < HD; k += 32) {
        float x = A[(size_t)m * HD + k];
#pragma unroll
        for (int h = 0; h < NL; h++) acc[h] += x * Ws[k * NL + h];
    }
#pragma unroll
    for (int h = 0; h < NL; h++)
#pragma unroll
        for (int off = 16; off > 0; off >>= 1)
            acc[h] += __shfl_down_sync(0xFFFFFFFFu, acc[h], off);

    if (lane == 0) {
        float v[NL], mx = -1e30f;
#pragma unroll
        for (int h = 0; h < NL; h++) { v[h] = acc[h] + bs[h]; mx = fmaxf(mx, v[h]); }
        float s = 0.f;
#pragma unroll
        for (int h = 0; h < NL; h++) { v[h] = expf(v[h] - mx); s += v[h]; }
        float inv = 1.0f / s;
#pragma unroll
        for (int h = 0; h < NL; h++) out[(size_t)m * NL + h] = v[h] * inv;
    }
}

// ---------------------------------------------------------------------------
__global__ void __launch_bounds__(256)
rownorm_kernel(const float* __restrict__ A, float* __restrict__ out, int M, int D)
{
    int warp = threadIdx.x >> 5, lane = threadIdx.x & 31;
    int m = blockIdx.x * 8 + warp;
    if (m >= M) return;
    float s = 0.f;
    for (int k = lane; k < D; k += 32) { float v = A[(size_t)m * D + k]; s += v * v; }
#pragma unroll
    for (int off = 16; off > 0; off >>= 1) s += __shfl_down_sync(0xFFFFFFFFu, s, off);
    if (lane == 0) out[m] = s;
}

// ---------------------------------------------------------------------------
// SIMT fp32 distance GEMM (layer 4, D=8) + tile min.
// ---------------------------------------------------------------------------
__global__ void __launch_bounds__(256)
dist_kernel(const float* __restrict__ Q, const float* __restrict__ T,
            const float* __restrict__ qn, const float* __restrict__ tn,
            float* __restrict__ out, float* __restrict__ gmin, int D, int Ncols)
{
    __shared__ __align__(16) float As[16 * 68];
    __shared__ __align__(16) float Bs[16 * 136];
    __shared__ unsigned sMinU[64];
    const int tx = threadIdx.x, ty = threadIdx.y;
    const int tid = ty * 16 + tx;
    const int n0 = blockIdx.x * 128;
    const int m0 = blockIdx.y * 64;

    if (tid < 64) sMinU[tid] = 0x7F800000u;

    float acc[4][8];
#pragma unroll
    for (int r = 0; r < 4; r++)
#pragma unroll
        for (int c = 0; c < 8; c++) acc[r][c] = 0.f;

    const int nChunks = (D + 15) / 16;
    for (int ch = 0; ch < nChunks; ch++) {
        const int k0 = ch * 16;
#pragma unroll
        for (int i = 0; i < 4; i++) {
            int e = tid + i * 256;
            int k = e & 15, m = e >> 4;
            float v = (k0 + k < D) ? Q[(size_t)(m0 + m) * D + k0 + k] : 0.f;
            As[k * 68 + m] = v;
        }
#pragma unroll
        for (int i = 0; i < 8; i++) {
            int e = tid + i * 256;
            int k = e & 15, n = e >> 4;
            int gn = n0 + n;
            float v = 0.f;
            if (k0 + k < D && gn < Ncols) v = T[(size_t)gn * D + k0 + k];
            Bs[k * 136 + n] = v;
        }
        __syncthreads();
#pragma unroll
        for (int k = 0; k < 16; k++) {
            float4 a  = *(const float4*)&As[k * 68 + ty * 4];
            float4 b0 = *(const float4*)&Bs[k * 136 + tx * 4];
            float4 b1 = *(const float4*)&Bs[k * 136 + 64 + tx * 4];
            float av[4] = {a.x, a.y, a.z, a.w};
            float bv[8] = {b0.x, b0.y, b0.z, b0.w, b1.x, b1.y, b1.z, b1.w};
#pragma unroll
            for (int r = 0; r < 4; r++)
#pragma unroll
                for (int c = 0; c < 8; c++) acc[r][c] += av[r] * bv[c];
        }
        __syncthreads();
    }
    const float FINF = __int_as_float(0x7F800000);
#pragma unroll
    for (int r = 0; r < 4; r++) {
        int m = m0 + ty * 4 + r;
        float qv = qn[m];
        float lm = FINF;
#pragma unroll
        for (int half = 0; half < 2; half++) {
#pragma unroll
            for (int c = 0; c < 4; c++) {
                int n = n0 + half * 64 + tx * 4 + c;
                if (n < Ncols) {
                    float d = fmaxf(qv + tn[n] - 2.f * acc[r][half * 4 + c], 0.f);
                    out[(size_t)m * Ncols + n] = d;
                    lm = fminf(lm, d);
                }
            }
        }
        if (lm < FINF) atomicMin(&sMinU[ty * 4 + r], __float_as_uint(lm));
    }
    __syncthreads();
    if (tid < 64)
        gmin[(size_t)(m0 + tid) * NTILES + blockIdx.x] = __uint_as_float(sMinU[tid]);
}

// ---------------------------------------------------------------------------
__device__ __forceinline__ void find_kth(const unsigned* hist, int NB, unsigned kth,
                                         int tid, unsigned* s_bin, unsigned* s_kthr)
{
    if (tid < 32) {
        unsigned running = 0;
        for (int base = 0; base < NB; base += 32) {
            unsigned v = hist[base + tid];
            unsigned sc = v;
#pragma unroll
            for (int off = 1; off < 32; off <<= 1) {
                unsigned t = __shfl_up_sync(0xFFFFFFFFu, sc, off);
                if (tid >= off) sc += t;
            }
            unsigned tot = __shfl_sync(0xFFFFFFFFu, sc, 31);
            if (running + tot >= kth) {
                unsigned mask = __ballot_sync(0xFFFFFFFFu, running + sc >= kth);
                int l = __ffs(mask) - 1;
                if (tid == l) { *s_bin = (unsigned)(base + l); *s_kthr = kth - running - (sc - v); }
                break;
            }
            running += tot;
        }
    }
}

// ---------------------------------------------------------------------------
// Exact top-K select: tile-min threshold + tile-subset scan.
// ---------------------------------------------------------------------------
#define SEL_THREADS 512
#define SEL_CAP 2048
#define OFF_CAND  16384
#define OFF_SEL   (OFF_CAND + SEL_CAP * 8)
#define OFF_TIES  (OFF_SEL + 1024)
#define OFF_TLAB  (OFF_TIES + 1024)
#define OFF_MINS  (OFF_TLAB + 512)
#define OFF_TLIST (OFF_MINS + 392 * 4)
#define SEL_SMEM  (OFF_TLIST + 392 * 4)

__global__ void __launch_bounds__(SEL_THREADS)
select_kernel(const float* __restrict__ d2mat, const float* __restrict__ gmin,
              const int* __restrict__ labels, float* __restrict__ total, int init)
{
    extern __shared__ __align__(16) char sms[];
    unsigned* hist = (unsigned*)sms;
    u64* cand  = (u64*)(sms + OFF_CAND);
    u64* sel   = (u64*)(sms + OFF_SEL);
    u64* ties  = (u64*)(sms + OFF_TIES);
    int* tlab  = (int*)(sms + OFF_TLAB);
    float* mins = (float*)(sms + OFF_MINS);
    int* tlist = (int*)(sms + OFF_TLIST);

    __shared__ unsigned s_M75, s_bin, s_kthr, s_candcnt, s_selcnt, s_tiecnt, s_ntiles;
    __shared__ float s_w[80];
    __shared__ int s_lab[80];

    const int b = blockIdx.x, tid = threadIdx.x, lane = tid & 31;
    const uint4* usrc = (const uint4*)(d2mat + (size_t)b * NT);
    const int NH = NT / 4;

    for (int i = tid; i < NTILES; i += SEL_THREADS)
        mins[i] = gmin[(size_t)b * NTILES + i];
    if (tid == 0) { s_candcnt = 0; s_selcnt = 0; s_tiecnt = 0; s_ntiles = 0; }
    __syncthreads();

    if (tid < NTILES) {
        unsigned key = __float_as_uint(mins[tid]);
        int c = 0;
        for (int j = 0; j < NTILES; j++) {
            unsigned kj = __float_as_uint(mins[j]);
            c += (kj < key) || (kj == key && j < tid);
        }
        if (c == KNN - 1) s_M75 = key;
    }
    __syncthreads();
    const unsigned Mkey = s_M75;

    if (tid < NTILES) {
        if (__float_as_uint(mins[tid]) <= Mkey) {
            unsigned s = atomicAdd(&s_ntiles, 1u);
            tlist[s] = tid;
        }
    }
    __syncthreads();
    const int ntl = (int)s_ntiles;

    for (int w = tid; w < ntl * 32; w += SEL_THREADS) {
        int t = tlist[w >> 5];
        int i4 = t * 32 + (w & 31);
        if (i4 < NH) {
            uint4 a = usrc[i4];
            unsigned k[4] = {a.x, a.y, a.z, a.w};
#pragma unroll
            for (int j = 0; j < 4; j++) {
                if (k[j] <= Mkey) {
                    unsigned s = atomicAdd(&s_candcnt, 1u);
                    if (s < SEL_CAP) cand[s] = ((u64)k[j] << 32) | (unsigned)(i4 * 4 + j);
                }
            }
        }
    }
    __syncthreads();

    unsigned Tkey;
    const unsigned candTotal = s_candcnt;

    if (candTotal <= SEL_CAP) {
        const int cc = (int)candTotal;
        for (int i = tid; i < 4096; i += SEL_THREADS) hist[i] = 0;
        __syncthreads();
        for (int i = tid; i < cc; i += SEL_THREADS)
            atomicAdd(&hist[(unsigned)(cand[i] >> 52)], 1u);
        __syncthreads();
        find_kth(hist, 4096, KNN, tid, &s_bin, &s_kthr);
        __syncthreads();
        const unsigned pfx = s_bin;
        const unsigned k1v = s_kthr;
        for (int i = tid; i < 4096; i += SEL_THREADS) hist[i] = 0;
        __syncthreads();
        for (int i = tid; i < cc; i += SEL_THREADS) {
            unsigned key = (unsigned)(cand[i] >> 32);
            if ((key >> 20) == pfx) atomicAdd(&hist[(key >> 8) & 0xFFFu], 1u);
        }
        __syncthreads();
        find_kth(hist, 4096, k1v, tid, &s_bin, &s_kthr);
        __syncthreads();
        const unsigned pfx20 = (pfx << 12) | s_bin;
        const unsigned k2v = s_kthr;
        for (int i = tid; i < 256; i += SEL_THREADS) hist[i] = 0;
        __syncthreads();
        for (int i = tid; i < cc; i += SEL_THREADS) {
            unsigned key = (unsigned)(cand[i] >> 32);
            if ((key >> 8) == pfx20) atomicAdd(&hist[key & 0xFFu], 1u);
        }
        __syncthreads();
        find_kth(hist, 256, k2v, tid, &s_bin, &s_kthr);
        __syncthreads();
        Tkey = (pfx20 << 8) | s_bin;
        for (int i = tid; i < cc; i += SEL_THREADS) {
            u64 cv = cand[i];
            unsigned key = (unsigned)(cv >> 32);
            if (key < Tkey) {
                unsigned s = atomicAdd(&s_selcnt, 1u);
                if (s < 128) sel[s] = cv;
            } else if (key == Tkey) {
                unsigned s = atomicAdd(&s_tiecnt, 1u);
                if (s < 128) ties[s] = cv;
            }
        }
        __syncthreads();
    } else {
        // fallback (degenerate ties): radix over the tile subset.
        for (int i = tid; i < 4096; i += SEL_THREADS) hist[i] = 0;
        __syncthreads();
        for (int w = tid; w < ntl * 32; w += SEL_THREADS) {
            int t = tlist[w >> 5];
            int i4 = t * 32 + (w & 31);
            uint4 a = (i4 < NH) ? usrc[i4] : make_uint4(~0u, ~0u, ~0u, ~0u);
            unsigned k[4] = {a.x, a.y, a.z, a.w};
#pragma unroll
            for (int j = 0; j < 4; j++) {
                unsigned bin = (k[j] <= Mkey) ? (k[j] >> 20) : 0xFFFFFFFFu;
                unsigned grp = __match_any_sync(0xFFFFFFFFu, bin);
                if (bin != 0xFFFFFFFFu && lane == __ffs(grp) - 1)
                    atomicAdd(&hist[bin], (unsigned)__popc(grp));
            }
        }
        __syncthreads();
        find_kth(hist, 4096, KNN, tid, &s_bin, &s_kthr);
        __syncthreads();
        const unsigned pfx = s_bin;
        const unsigned k1v = s_kthr;

        for (int i = tid; i < 4096; i += SEL_THREADS) hist[i] = 0;
        __syncthreads();
        for (int w = tid; w < ntl * 32; w += SEL_THREADS) {
            int t = tlist[w >> 5];
            int i4 = t * 32 + (w & 31);
            uint4 a = (i4 < NH) ? usrc[i4] : make_uint4(~0u, ~0u, ~0u, ~0u);
            unsigned k[4] = {a.x, a.y, a.z, a.w};
#pragma unroll
            for (int j = 0; j < 4; j++) {
                unsigned bin = (k[j] <= Mkey && (k[j] >> 20) == pfx)
                               ? ((k[j] >> 8) & 0xFFFu) : 0xFFFFFFFFu;
                unsigned grp = __match_any_sync(0xFFFFFFFFu, bin);
                if (bin != 0xFFFFFFFFu && lane == __ffs(grp) - 1)
                    atomicAdd(&hist[bin], (unsigned)__popc(grp));
            }
        }
        __syncthreads();
        find_kth(hist, 4096, k1v, tid, &s_bin, &s_kthr);
        __syncthreads();
        const unsigned pfx20 = (pfx << 12) | s_bin;
        const unsigned k2v = s_kthr;

        for (int i = tid; i < 256; i += SEL_THREADS) hist[i] = 0;
        __syncthreads();
        for (int w = tid; w < ntl * 32; w += SEL_THREADS) {
            int t = tlist[w >> 5];
            int i4 = t * 32 + (w & 31);
            uint4 a = (i4 < NH) ? usrc[i4] : make_uint4(~0u, ~0u, ~0u, ~0u);
            unsigned k[4] = {a.x, a.y, a.z, a.w};
#pragma unroll
            for (int j = 0; j < 4; j++) {
                unsigned bin = (k[j] <= Mkey && (k[j] >> 8) == pfx20)
                               ? (k[j] & 0xFFu) : 0xFFFFFFFFu;
                unsigned grp = __match_any_sync(0xFFFFFFFFu, bin);
                if (bin != 0xFFFFFFFFu && lane == __ffs(grp) - 1)
                    atomicAdd(&hist[bin], (unsigned)__popc(grp));
            }
        }
        __syncthreads();
        find_kth(hist, 256, k2v, tid, &s_bin, &s_kthr);
        __syncthreads();
        Tkey = (pfx20 << 8) | s_bin;

        for (int w = tid; w < ntl * 32; w += SEL_THREADS) {
            int t = tlist[w >> 5];
            int i4 = t * 32 + (w & 31);
            if (i4 < NH) {
                uint4 a = usrc[i4];
                unsigned k[4] = {a.x, a.y, a.z, a.w};
#pragma unroll
                for (int j = 0; j < 4; j++) {
                    if (k[j] < Tkey) {
                        unsigned s = atomicAdd(&s_selcnt, 1u);
                        if (s < 128) sel[s] = ((u64)k[j] << 32) | (unsigned)(i4 * 4 + j);
                    } else if (k[j] == Tkey) {
                        unsigned s = atomicAdd(&s_tiecnt, 1u);
                        if (s < 128) ties[s] = ((u64)k[j] << 32) | (unsigned)(i4 * 4 + j);
                    }
                }
            }
        }
        __syncthreads();
    }

    const int ns = min((int)s_selcnt, 128);
    const int ne = min((int)s_tiecnt, 128);

    if (tid < ns) {
        u64 mine = sel[tid];
        unsigned my_idx = (unsigned)(mine & 0xFFFFFFFFu);
        int rank = 0;
        for (int j = 0; j < ns; j++) rank += ((unsigned)(sel[j] & 0xFFFFFFFFu) < my_idx);
        float d2 = __uint_as_float((unsigned)(mine >> 32));
        s_w[rank] = (d2 > 0.f) ? __fdiv_rn(1.0f, __fsqrt_rn(d2)) : 0.f;
        s_lab[rank] = labels[my_idx];
    }
    if (tid >= 128 && tid - 128 < ne) {
        int t = tid - 128;
        unsigned my_idx = (unsigned)(ties[t] & 0xFFFFFFFFu);
        int rank = 0;
        for (int j = 0; j < ne; j++) rank += ((unsigned)(ties[j] & 0xFFFFFFFFu) < my_idx);
        tlab[rank] = labels[my_idx];
    }
    __syncthreads();

    if (tid == 0) {
        float cls[NL];
#pragma unroll
        for (int l = 0; l < NL; l++) cls[l] = 0.f;
        float stot = 0.f;
        for (int j = 0; j < ns; j++) { stot += s_w[j]; cls[s_lab[j]] += s_w[j]; }
        int need = KNN - ns;
        float d2T = __uint_as_float(Tkey);
        float wT = (d2T > 0.f) ? __fdiv_rn(1.0f, __fsqrt_rn(d2T)) : 0.f;
        int m = (need < ne) ? need : ne;
        for (int j = 0; j < m; j++) { stot += wT; cls[tlab[j]] += wT; }
#pragma unroll
        for (int l = 0; l < NL; l++) {
            float val = stot - cls[l];
            size_t o = (size_t)b * NL + l;
            if (init) total[o] = val; else total[o] += val;
        }
    }
}

// ---------------------------------------------------------------------------
__global__ void __launch_bounds__(256)
pvalue_kernel(const float* __restrict__ total, const float* __restrict__ cali,
              float* __restrict__ out)
{
    const int b = blockIdx.x, tid = threadIdx.x;
    float t[NL];
#pragma unroll
    for (int l = 0; l < NL; l++) t[l] = total[(size_t)b * NL + l];
    int cnt[NL];
#pragma unroll
    for (int l = 0; l < NL; l++) cnt[l] = 0;
    for (int i = tid; i < NC; i += 256) {
        float c = cali[i];
#pragma unroll
        for (int l = 0; l < NL; l++) cnt[l] += (c >= t[l]) ? 1 : 0;
    }
    __shared__ int sc[NL];
    if (tid < NL) sc[tid] = 0;
    __syncthreads();
#pragma unroll
    for (int l = 0; l < NL; l++) atomicAdd(&sc[l], cnt[l]);
    __syncthreads();
    if (tid < NL) out[(size_t)b * NL + tid] = (float)sc[tid] * (1.0f / NC);
}

// ---------------------------------------------------------------------------
extern "C" void kernel_launch(void* const* d_in, const int* in_sizes, int n_in,
                              void* d_out, int out_size)
{
    const float* x        = (const float*)d_in[0];
    const float* train_x  = (const float*)d_in[1];
    const int*   lab      = (const int*)  d_in[2];
    const float* cali     = (const float*)d_in[3];
    const float* W1 = (const float*)d_in[4];  const float* b1 = (const float*)d_in[5];
    const float* W2 = (const float*)d_in[6];  const float* b2 = (const float*)d_in[7];
    const float* W3 = (const float*)d_in[8];  const float* b3 = (const float*)d_in[9];
    const float* W4 = (const float*)d_in[10]; const float* b4 = (const float*)d_in[11];
    float* out = (float*)d_out;

    float *h1p, *h2p, *h3p, *q4p, *t3p, *t4p, *d2p, *qnp, *tnp, *totp, *minp;
    __nv_bfloat16 *qhip, *qlop, *thip, *tlop, *thi2p, *tlo2p;
    __nv_bfloat16 *w1th, *w1tl, *w2th, *w2tl, *w3th, *w3tl;
    cudaGetSymbolAddress((void**)&h1p, g_h1);
    cudaGetSymbolAddress((void**)&h2p, g_h2);
    cudaGetSymbolAddress((void**)&h3p, g_h3);
    cudaGetSymbolAddress((void**)&q4p, g_q4);
    cudaGetSymbolAddress((void**)&t3p, g_t3);
    cudaGetSymbolAddress((void**)&t4p, g_t4);
    cudaGetSymbolAddress((void**)&d2p, g_d2);
    cudaGetSymbolAddress((void**)&minp, g_min);
    cudaGetSymbolAddress((void**)&qnp, g_qn);
    cudaGetSymbolAddress((void**)&tnp, g_tn);
    cudaGetSymbolAddress((void**)&totp, g_tot);
    cudaGetSymbolAddress((void**)&qhip, g_qhi);
    cudaGetSymbolAddress((void**)&qlop, g_qlo);
    cudaGetSymbolAddress((void**)&thip, g_thi);
    cudaGetSymbolAddress((void**)&tlop, g_tlo);
    cudaGetSymbolAddress((void**)&thi2p, g_thi2);
    cudaGetSymbolAddress((void**)&tlo2p, g_tlo2);
    cudaGetSymbolAddress((void**)&w1th, g_w1th);
    cudaGetSymbolAddress((void**)&w1tl, g_w1tl);
    cudaGetSymbolAddress((void**)&w2th, g_w2th);
    cudaGetSymbolAddress((void**)&w2tl, g_w2tl);
    cudaGetSymbolAddress((void**)&w3th, g_w3th);
    cudaGetSymbolAddress((void**)&w3tl, g_w3tl);

    cudaFuncSetAttribute(select_kernel,
                         cudaFuncAttributeMaxDynamicSharedMemorySize, SEL_SMEM);
    cudaFuncSetAttribute(mma_dist_kernel,
                         cudaFuncAttributeMaxDynamicSharedMemorySize, MD_SMEM);

    dim3 tb(16, 16);
    const int D0 = 83;
    const dim3 mgrid(NTILES, BQ / 256);

    conv_norm_kernel<<<BQ / 8, 256>>>(x, qhip, qlop, qnp, BQ, D0);
    conv_norm_kernel<<<NTP / 8, 256>>>(train_x, thip, tlop, tnp, NT, D0);
    wt_convert_kernel<<<(3 * 128 * 128 + 255) / 256, 256>>>(W1, W2, W3);

    // layer 0 (mma_dist = launch #4 -> profiled)
    mma_dist_kernel<<<mgrid, 512, MD_SMEM>>>(qhip, qlop, thip, tlop, qnp, tnp, d2p, minp, 6);
    select_kernel<<<BQ, SEL_THREADS, SEL_SMEM>>>(d2p, minp, lab, totp, 1);

    // query-side MLP (tiny SIMT)
    linear_relu_kernel<<<BQ / 64, tb>>>(x,   W1, b1, h1p, BQ, D0);
    linear_relu_kernel<<<BQ / 64, tb>>>(h1p, W2, b2, h2p, BQ, HD);
    linear_relu_kernel<<<BQ / 64, tb>>>(h2p, W3, b3, h3p, BQ, HD);
    linear_softmax_kernel<<<(BQ + 7) / 8, 256>>>(h3p, W4, b4, q4p, BQ);

    // layer 1
    mma_linear_kernel<<<NTILES, 256>>>(thip, tlop, w1th, w1tl, b1,
                                       thi2p, tlo2p, tnp, (float*)0, 6);
    conv_norm_kernel<<<BQ / 8, 256>>>(h1p, qhip, qlop, qnp, BQ, HD);
    mma_dist_kernel<<<mgrid, 512, MD_SMEM>>>(qhip, qlop, thi2p, tlo2p, qnp, tnp, d2p, minp, 8);
    select_kernel<<<BQ, SEL_THREADS, SEL_SMEM>>>(d2p, minp, lab, totp, 0);

    // layer 2
    mma_linear_kernel<<<NTILES, 256>>>(thi2p, tlo2p, w2th, w2tl, b2,
                                       thip, tlop, tnp, (float*)0, 8);
    conv_norm_kernel<<<BQ / 8, 256>>>(h2p, qhip, qlop, qnp, BQ, HD);
    mma_dist_kernel<<<mgrid, 512, MD_SMEM>>>(qhip, qlop, thip, tlop, qnp, tnp, d2p, minp, 8);
    select_kernel<<<BQ, SEL_THREADS, SEL_SMEM>>>(d2p, minp, lab, totp, 0);

    // layer 3 (+ fp32 t3 for softmax)
    mma_linear_kernel<<<NTILES, 256>>>(thip, tlop, w3th, w3tl, b3,
                                       thi2p, tlo2p, tnp, t3p, 8);
    conv_norm_kernel<<<BQ / 8, 256>>>(h3p, qhip, qlop, qnp, BQ, HD);
    mma_dist_kernel<<<mgrid, 512, MD_SMEM>>>(qhip, qlop, thi2p, tlo2p, qnp, tnp, d2p, minp, 8);
    select_kernel<<<BQ, SEL_THREADS, SEL_SMEM>>>(d2p, minp, lab, totp, 0);

    // layer 4 (softmax features, D=8): exact fp32 path
    linear_softmax_kernel<<<(NT + 7) / 8, 256>>>(t3p, W4, b4, t4p, NT);
    rownorm_kernel<<<(BQ + 7) / 8, 256>>>(q4p, qnp, BQ, NL);
    rownorm_kernel<<<(NT + 7) / 8, 256>>>(t4p, tnp, NT, NL);
    dist_kernel<<<dim3(NTILES, BQ / 64), tb>>>(q4p, t4p, qnp, tnp, d2p, minp, NL, NT);
    select_kernel<<<BQ, SEL_THREADS, SEL_SMEM>>>(d2p, minp, lab, totp, 0);

    pvalue_kernel<<<BQ, 256>>>(totp, cali, out);
}